// round 7
// baseline (speedup 1.0000x reference)
#include <cuda_runtime.h>
#include <cuda_bf16.h>
#include <math.h>
#include <cstdint>

#define BSZ 4
#define SQ  1024
#define EMB 1024
#define NH  16
#define HD  64

typedef unsigned long long u64;
typedef unsigned short ushortx;

// ---------------------------------------------------------------------------
// Scratch (__device__ globals; allocation-free)
// ---------------------------------------------------------------------------
__device__ float g_Q[BSZ*NH*SQ*HD];
__device__ float g_K[BSZ*NH*SQ*HD];
__device__ float g_V[BSZ*NH*SQ*HD];

// bf16 hi/lo split operands
__device__ uint4 g_Xhi4[4096*1024*2/16];
__device__ uint4 g_Xlo4[4096*1024*2/16];
__device__ uint4 g_Ohi4[4096*1024*2/16];
__device__ uint4 g_Olo4[4096*1024*2/16];
__device__ uint4 g_WaThi4[3072*1024*2/16];   // W_attn^T [3072][1024]
__device__ uint4 g_WaTlo4[3072*1024*2/16];
__device__ uint4 g_WpThi4[1024*1024*2/16];   // W_proj^T [1024][1024]
__device__ uint4 g_WpTlo4[1024*1024*2/16];

// ---------------------------------------------------------------------------
// helpers
// ---------------------------------------------------------------------------
__device__ __forceinline__ uint32_t smem_u32(const void* p) {
    uint32_t a;
    asm("{ .reg .u64 t; cvta.to.shared.u64 t, %1; cvt.u32.u64 %0, t; }" : "=r"(a) : "l"(p));
    return a;
}
__device__ __forceinline__ void cpa16(uint32_t dst, const void* src) {
    asm volatile("cp.async.cg.shared.global [%0], [%1], 16;"
                 :: "r"(dst), "l"(__cvta_generic_to_global(src)) : "memory");
}
#define CPA_COMMIT() asm volatile("cp.async.commit_group;" ::: "memory")
#define CPA_WAIT(n)  asm volatile("cp.async.wait_group %0;" :: "n"(n) : "memory")

// m16n8k16 bf16 MMA, fp32 accumulate
__device__ __forceinline__ void mma16816(float* c, const uint32_t* a, const uint32_t* b) {
    asm volatile("mma.sync.aligned.m16n8k16.row.col.f32.bf16.bf16.f32 "
        "{%0,%1,%2,%3}, {%4,%5,%6,%7}, {%8,%9}, {%0,%1,%2,%3};"
        : "+f"(c[0]), "+f"(c[1]), "+f"(c[2]), "+f"(c[3])
        : "r"(a[0]), "r"(a[1]), "r"(a[2]), "r"(a[3]), "r"(b[0]), "r"(b[1]));
}
__device__ __forceinline__ void mma16816_b2(float* c, const uint32_t* a, uint32_t b0, uint32_t b1) {
    asm volatile("mma.sync.aligned.m16n8k16.row.col.f32.bf16.bf16.f32 "
        "{%0,%1,%2,%3}, {%4,%5,%6,%7}, {%8,%9}, {%0,%1,%2,%3};"
        : "+f"(c[0]), "+f"(c[1]), "+f"(c[2]), "+f"(c[3])
        : "r"(a[0]), "r"(a[1]), "r"(a[2]), "r"(a[3]), "r"(b0), "r"(b1));
}
__device__ __forceinline__ void ldm_x4(uint32_t* r, uint32_t addr) {
    asm volatile("ldmatrix.sync.aligned.m8n8.x4.shared.b16 {%0,%1,%2,%3}, [%4];"
        : "=r"(r[0]), "=r"(r[1]), "=r"(r[2]), "=r"(r[3]) : "r"(addr));
}
__device__ __forceinline__ void ldm_x2(uint32_t* r, uint32_t addr) {
    asm volatile("ldmatrix.sync.aligned.m8n8.x2.shared.b16 {%0,%1}, [%2];"
        : "=r"(r[0]), "=r"(r[1]) : "r"(addr));
}
__device__ __forceinline__ void ldm_x2t(uint32_t* r, uint32_t addr) {
    asm volatile("ldmatrix.sync.aligned.m8n8.x2.trans.shared.b16 {%0,%1}, [%2];"
        : "=r"(r[0]), "=r"(r[1]) : "r"(addr));
}
// two f32 -> packed bf16x2 hi + residual lo
__device__ __forceinline__ void split2(float x, float y, uint32_t& h, uint32_t& l) {
    __nv_bfloat16 hx = __float2bfloat16_rn(x);
    __nv_bfloat16 hy = __float2bfloat16_rn(y);
    float rx = x - __bfloat162float(hx);
    float ry = y - __bfloat162float(hy);
    __nv_bfloat16 lx = __float2bfloat16_rn(rx);
    __nv_bfloat16 ly = __float2bfloat16_rn(ry);
    h = (uint32_t)__bfloat16_as_ushort(hx) | ((uint32_t)__bfloat16_as_ushort(hy) << 16);
    l = (uint32_t)__bfloat16_as_ushort(lx) | ((uint32_t)__bfloat16_as_ushort(ly) << 16);
}

// ---------------------------------------------------------------------------
// GEMM geometry: 128x128 block, BK=32, 8 warps (2m x 4n), warp tile 64x32.
// smem stage: 4 arrays (Ahi, Alo, Bhi, Blo), each 128 rows x 80 bytes
// (64B data + 16B pad -> 20-bank row stride, conflict-free ldmatrix phases).
// Double-buffered: 2 stages x 40960B = 81920B -> 2 CTAs/SM.
// ---------------------------------------------------------------------------
#define ROWB   80
#define ARRB   (128*ROWB)     // 10240
#define STAGEB (4*ARRB)       // 40960
#define NCHUNK 32             // 1024 / 32

__device__ __forceinline__ void load_chunk(
    uint32_t st, const ushortx* A0, const ushortx* A1,
    const ushortx* B0, const ushortx* B1, int k0, int tid)
{
    const ushortx* srcs[4] = {A0, A1, B0, B1};
    #pragma unroll
    for (int arr = 0; arr < 4; arr++) {
        const ushortx* s = srcs[arr];
        #pragma unroll
        for (int i = 0; i < 2; i++) {
            const int u = i * 256 + tid;      // 0..511
            const int r = u >> 2, c16 = u & 3;
            cpa16(st + arr * ARRB + r * ROWB + c16 * 16,
                  (const char*)(s + r * 1024 + k0) + c16 * 16);
        }
    }
}

__device__ __forceinline__ void compute_chunk(
    uint32_t st, int wm, int wn, int lane, float acc[4][4][4])
{
    #pragma unroll
    for (int ks = 0; ks < 2; ks++) {
        const uint32_t acol = ks * 32 + ((lane >> 4) << 4);
        uint32_t Ahi[4][4], Alo[4][4], Bh[2][4], Bl[2][4];
        #pragma unroll
        for (int mf = 0; mf < 4; mf++) {
            const uint32_t ra = st + (wm * 64 + mf * 16 + (lane & 15)) * ROWB + acol;
            ldm_x4(Ahi[mf], ra);
            ldm_x4(Alo[mf], ra + ARRB);
        }
        #pragma unroll
        for (int nh = 0; nh < 2; nh++) {
            const uint32_t rb = st + 2 * ARRB + (wn * 32 + nh * 16 + (lane & 15)) * ROWB + acol;
            ldm_x4(Bh[nh], rb);
            ldm_x4(Bl[nh], rb + ARRB);
        }
        #pragma unroll
        for (int mf = 0; mf < 4; mf++)
            #pragma unroll
            for (int nh = 0; nh < 2; nh++)
                #pragma unroll
                for (int s = 0; s < 2; s++) {
                    float* c = acc[mf][nh * 2 + s];
                    mma16816_b2(c, Ahi[mf], Bh[nh][s], Bh[nh][s + 2]);
                    mma16816_b2(c, Ahi[mf], Bl[nh][s], Bl[nh][s + 2]);
                    mma16816_b2(c, Alo[mf], Bh[nh][s], Bh[nh][s + 2]);
                }
    }
}

__device__ __forceinline__ void gemm_mainloop(
    uint32_t sm, const ushortx* A0, const ushortx* A1,
    const ushortx* B0, const ushortx* B1,
    int wm, int wn, int lane, int tid, float acc[4][4][4])
{
    #pragma unroll
    for (int mf = 0; mf < 4; mf++)
        #pragma unroll
        for (int nf = 0; nf < 4; nf++)
            #pragma unroll
            for (int j = 0; j < 4; j++) acc[mf][nf][j] = 0.f;

    load_chunk(sm, A0, A1, B0, B1, 0, tid);
    CPA_COMMIT();
    for (int c = 0; c < NCHUNK; c++) {
        if (c + 1 < NCHUNK) {
            load_chunk(sm + ((c + 1) & 1) * STAGEB, A0, A1, B0, B1, (c + 1) * 32, tid);
            CPA_COMMIT();
            CPA_WAIT(1);
        } else {
            CPA_WAIT(0);
        }
        __syncthreads();
        compute_chunk(sm + (c & 1) * STAGEB, wm, wn, lane, acc);
        __syncthreads();
    }
}

// ---------------------------------------------------------------------------
// QKV GEMM: X @ W_attn + b_attn -> scatter to g_Q (x0.125) / g_K / g_V
// ---------------------------------------------------------------------------
__global__ __launch_bounds__(256, 2) void k_gemm_qkv(const float* __restrict__ bias)
{
    extern __shared__ __align__(16) char dsm[];
    const int tid = threadIdx.x, wid = tid >> 5, lane = tid & 31;
    const int t4 = lane >> 2, tm4 = lane & 3;
    const int wm = wid >> 2, wn = wid & 3;
    const int bn = blockIdx.x * 128, bm = blockIdx.y * 128;
    const uint32_t sm = smem_u32(dsm);

    float acc[4][4][4];
    gemm_mainloop(sm,
        (const ushortx*)g_Xhi4 + (long)bm * 1024, (const ushortx*)g_Xlo4 + (long)bm * 1024,
        (const ushortx*)g_WaThi4 + (long)bn * 1024, (const ushortx*)g_WaTlo4 + (long)bn * 1024,
        wm, wn, lane, tid, acc);

    const int which = bn >> 10;
    float* dst = (which == 0) ? g_Q : (which == 1) ? g_K : g_V;
    const float scale = (which == 0) ? 0.125f : 1.f;

    #pragma unroll
    for (int mf = 0; mf < 4; mf++) {
        #pragma unroll
        for (int nf = 0; nf < 4; nf++) {
            const int n_g = bn + wn * 32 + nf * 8 + tm4 * 2;
            const int e = n_g & 1023, h = e >> 6, d = e & 63;
            const float b0 = __ldg(&bias[n_g]), b1 = __ldg(&bias[n_g + 1]);
            #pragma unroll
            for (int rr = 0; rr < 2; rr++) {
                const int row = bm + wm * 64 + mf * 16 + t4 + rr * 8;
                const int b = row >> 10, s = row & 1023;
                const long off = (((long)(b * NH + h) * SQ) + s) * HD + d;
                float2 v = make_float2((acc[mf][nf][rr * 2 + 0] + b0) * scale,
                                       (acc[mf][nf][rr * 2 + 1] + b1) * scale);
                *(float2*)&dst[off] = v;
            }
        }
    }
}

// ---------------------------------------------------------------------------
// Proj GEMM: Obf16 @ W_proj + b_proj -> out
// ---------------------------------------------------------------------------
__global__ __launch_bounds__(256, 2) void k_gemm_proj(const float* __restrict__ bias,
                                                      float* __restrict__ out)
{
    extern __shared__ __align__(16) char dsm[];
    const int tid = threadIdx.x, wid = tid >> 5, lane = tid & 31;
    const int t4 = lane >> 2, tm4 = lane & 3;
    const int wm = wid >> 2, wn = wid & 3;
    const int bn = blockIdx.x * 128, bm = blockIdx.y * 128;
    const uint32_t sm = smem_u32(dsm);

    float acc[4][4][4];
    gemm_mainloop(sm,
        (const ushortx*)g_Ohi4 + (long)bm * 1024, (const ushortx*)g_Olo4 + (long)bm * 1024,
        (const ushortx*)g_WpThi4 + (long)bn * 1024, (const ushortx*)g_WpTlo4 + (long)bn * 1024,
        wm, wn, lane, tid, acc);

    #pragma unroll
    for (int mf = 0; mf < 4; mf++) {
        #pragma unroll
        for (int nf = 0; nf < 4; nf++) {
            const int n_g = bn + wn * 32 + nf * 8 + tm4 * 2;
            const float b0 = __ldg(&bias[n_g]), b1 = __ldg(&bias[n_g + 1]);
            #pragma unroll
            for (int rr = 0; rr < 2; rr++) {
                const int row = bm + wm * 64 + mf * 16 + t4 + rr * 8;
                float2 v = make_float2(acc[mf][nf][rr * 2 + 0] + b0,
                                       acc[mf][nf][rr * 2 + 1] + b1);
                *(float2*)&out[(long)row * EMB + n_g] = v;
            }
        }
    }
}

// ---------------------------------------------------------------------------
// Elementwise f32 -> bf16 hi/lo split
// ---------------------------------------------------------------------------
__global__ __launch_bounds__(256) void k_cvt(const float4* __restrict__ src,
                                             uint2* __restrict__ hi, uint2* __restrict__ lo, int n4)
{
    int i = blockIdx.x * 256 + threadIdx.x;
    if (i >= n4) return;
    float4 v = src[i];
    uint32_t h0, h1, l0, l1;
    split2(v.x, v.y, h0, l0);
    split2(v.z, v.w, h1, l1);
    hi[i] = make_uint2(h0, h1);
    lo[i] = make_uint2(l0, l1);
}

// ---------------------------------------------------------------------------
// Transpose-convert: W [1024, ncols] f32 -> W^T hi/lo [ncols, 1024] bf16
// ---------------------------------------------------------------------------
__global__ __launch_bounds__(256) void k_wT(const float* __restrict__ W, int ncols,
                                            ushortx* __restrict__ hiT,
                                            ushortx* __restrict__ loT)
{
    __shared__ float t[32][33];
    const int tx = threadIdx.x, ty = threadIdx.y;
    const int n0 = blockIdx.x * 32, k0 = blockIdx.y * 32;
    #pragma unroll
    for (int i = 0; i < 4; i++)
        t[ty + i * 8][tx] = W[(k0 + ty + i * 8) * ncols + n0 + tx];
    __syncthreads();
    #pragma unroll
    for (int i = 0; i < 4; i++) {
        const int r = ty + i * 8;
        float v = t[tx][r];
        __nv_bfloat16 bh = __float2bfloat16_rn(v);
        float rr = v - __bfloat162float(bh);
        __nv_bfloat16 bl = __float2bfloat16_rn(rr);
        const int off = (n0 + r) * 1024 + k0 + tx;
        hiT[off] = __bfloat16_as_ushort(bh);
        loT[off] = __bfloat16_as_ushort(bl);
    }
}

// ---------------------------------------------------------------------------
// HMMA causal flash attention (unchanged from R6 pass).
// Block: 128 q-rows x 1 head. 8 warps x 16 q-rows. 64-key tiles.
// ---------------------------------------------------------------------------
#define AROW 144

__global__ __launch_bounds__(256, 1) void k_attn_mma()
{
    extern __shared__ char smb[];
    const uint32_t sb = smem_u32(smb);
    const int tid = threadIdx.x, lane = tid & 31, w = tid >> 5;
    const int t4 = lane >> 2, tm4 = lane & 3;
    const int bh = blockIdx.y;
    const int q0 = ((int)gridDim.x - 1 - (int)blockIdx.x) * 128;  // heavy blocks first

    // ---- stage Q (f32 -> bf16 hi/lo in smem)
    const float* Qg = g_Q + ((long)bh * SQ + q0) * HD;
    #pragma unroll
    for (int i = 0; i < 8; i++) {
        const int idx = i * 256 + tid;
        const int r = idx >> 4, c4 = idx & 15;
        float4 v = ((const float4*)Qg)[idx];
        uint32_t h0, h1, l0, l1;
        split2(v.x, v.y, h0, l0);
        split2(v.z, v.w, h1, l1);
        *(uint2*)(smb + r * AROW + c4 * 8) = make_uint2(h0, h1);
        *(uint2*)(smb + 128 * AROW + r * AROW + c4 * 8) = make_uint2(l0, l1);
    }
    __syncthreads();

    uint32_t qh[4][4], ql[4][4];
    {
        const uint32_t rowq = w * 16 + (lane & 15);
        #pragma unroll
        for (int ks = 0; ks < 4; ks++) {
            const uint32_t col = ks * 32 + ((lane >> 4) << 4);
            ldm_x4(qh[ks], sb + rowq * AROW + col);
            ldm_x4(ql[ks], sb + 128 * AROW + rowq * AROW + col);
        }
    }
    __syncthreads();

    const uint32_t Khi = sb, Klo = sb + 64 * AROW,
                   Vhi = sb + 128 * AROW, Vlo = sb + 192 * AROW;

    float O[8][4];
    #pragma unroll
    for (int i = 0; i < 8; i++)
        #pragma unroll
        for (int j = 0; j < 4; j++) O[i][j] = 0.f;
    float m0 = -INFINITY, m1 = -INFINITY, lsum0 = 0.f, lsum1 = 0.f;
    const int qrow0 = q0 + w * 16 + t4;

    const float* Kg = g_K + (long)bh * SQ * HD;
    const float* Vg = g_V + (long)bh * SQ * HD;
    const int nkt = q0 / 64 + 2;

    for (int kt = 0; kt < nkt; kt++) {
        const int k0 = kt * 64;
        #pragma unroll
        for (int i = 0; i < 4; i++) {
            const int idx = i * 256 + tid;
            const int r = idx >> 4, c4 = idx & 15;
            float4 kv = ((const float4*)(Kg + (long)k0 * HD))[idx];
            float4 vv = ((const float4*)(Vg + (long)k0 * HD))[idx];
            uint32_t h0, h1, l0, l1;
            split2(kv.x, kv.y, h0, l0);
            split2(kv.z, kv.w, h1, l1);
            *(uint2*)(smb + (Khi - sb) + r * AROW + c4 * 8) = make_uint2(h0, h1);
            *(uint2*)(smb + (Klo - sb) + r * AROW + c4 * 8) = make_uint2(l0, l1);
            split2(vv.x, vv.y, h0, l0);
            split2(vv.z, vv.w, h1, l1);
            *(uint2*)(smb + (Vhi - sb) + r * AROW + c4 * 8) = make_uint2(h0, h1);
            *(uint2*)(smb + (Vlo - sb) + r * AROW + c4 * 8) = make_uint2(l0, l1);
        }
        __syncthreads();

        float sc[8][4];
        #pragma unroll
        for (int nf = 0; nf < 8; nf++) {
            sc[nf][0] = sc[nf][1] = sc[nf][2] = sc[nf][3] = 0.f;
            const uint32_t rowk = nf * 8 + (lane & 7);
            const uint32_t colp = ((lane >> 3) & 1) * 16;
            #pragma unroll
            for (int ks = 0; ks < 4; ks++) {
                uint32_t bh_[2], bl_[2];
                ldm_x2(bh_, Khi + rowk * AROW + ks * 32 + colp);
                ldm_x2(bl_, Klo + rowk * AROW + ks * 32 + colp);
                mma16816(sc[nf], qh[ks], bh_);
                mma16816(sc[nf], qh[ks], bl_);
                mma16816(sc[nf], ql[ks], bh_);
            }
        }

        if (kt >= nkt - 2) {
            #pragma unroll
            for (int nf = 0; nf < 8; nf++) {
                const int col = k0 + nf * 8 + tm4 * 2;
                if (col     > qrow0)     sc[nf][0] = -1e30f;
                if (col + 1 > qrow0)     sc[nf][1] = -1e30f;
                if (col     > qrow0 + 8) sc[nf][2] = -1e30f;
                if (col + 1 > qrow0 + 8) sc[nf][3] = -1e30f;
            }
        }

        float mx0 = sc[0][0], mx1 = sc[0][2];
        #pragma unroll
        for (int nf = 0; nf < 8; nf++) {
            mx0 = fmaxf(mx0, fmaxf(sc[nf][0], sc[nf][1]));
            mx1 = fmaxf(mx1, fmaxf(sc[nf][2], sc[nf][3]));
        }
        mx0 = fmaxf(mx0, __shfl_xor_sync(0xFFFFFFFF, mx0, 1));
        mx0 = fmaxf(mx0, __shfl_xor_sync(0xFFFFFFFF, mx0, 2));
        mx1 = fmaxf(mx1, __shfl_xor_sync(0xFFFFFFFF, mx1, 1));
        mx1 = fmaxf(mx1, __shfl_xor_sync(0xFFFFFFFF, mx1, 2));
        const float mn0 = fmaxf(m0, mx0), mn1 = fmaxf(m1, mx1);
        const float c0 = __expf(m0 - mn0), c1 = __expf(m1 - mn1);
        m0 = mn0; m1 = mn1;
        float ps0 = 0.f, ps1 = 0.f;
        #pragma unroll
        for (int nf = 0; nf < 8; nf++) {
            sc[nf][0] = __expf(sc[nf][0] - mn0); ps0 += sc[nf][0];
            sc[nf][1] = __expf(sc[nf][1] - mn0); ps0 += sc[nf][1];
            sc[nf][2] = __expf(sc[nf][2] - mn1); ps1 += sc[nf][2];
            sc[nf][3] = __expf(sc[nf][3] - mn1); ps1 += sc[nf][3];
        }
        ps0 += __shfl_xor_sync(0xFFFFFFFF, ps0, 1);
        ps0 += __shfl_xor_sync(0xFFFFFFFF, ps0, 2);
        ps1 += __shfl_xor_sync(0xFFFFFFFF, ps1, 1);
        ps1 += __shfl_xor_sync(0xFFFFFFFF, ps1, 2);
        lsum0 = lsum0 * c0 + ps0;
        lsum1 = lsum1 * c1 + ps1;
        #pragma unroll
        for (int nf = 0; nf < 8; nf++) {
            O[nf][0] *= c0; O[nf][1] *= c0;
            O[nf][2] *= c1; O[nf][3] *= c1;
        }

        uint32_t ph[4][4], pl[4][4];
        #pragma unroll
        for (int j = 0; j < 4; j++) {
            split2(sc[2*j    ][0], sc[2*j    ][1], ph[j][0], pl[j][0]);
            split2(sc[2*j    ][2], sc[2*j    ][3], ph[j][1], pl[j][1]);
            split2(sc[2*j + 1][0], sc[2*j + 1][1], ph[j][2], pl[j][2]);
            split2(sc[2*j + 1][2], sc[2*j + 1][3], ph[j][3], pl[j][3]);
        }

        #pragma unroll
        for (int nfd = 0; nfd < 8; nfd++) {
            #pragma unroll
            for (int ks = 0; ks < 4; ks++) {
                uint32_t bvh[2], bvl[2];
                const uint32_t rowv = ks * 16 + (lane & 15);
                ldm_x2t(bvh, Vhi + rowv * AROW + nfd * 16);
                ldm_x2t(bvl, Vlo + rowv * AROW + nfd * 16);
                mma16816(O[nfd], ph[ks], bvh);
                mma16816(O[nfd], ph[ks], bvl);
                mma16816(O[nfd], pl[ks], bvh);
            }
        }
        __syncthreads();
    }

    const float i0 = 1.f / lsum0, i1 = 1.f / lsum1;
    const int b = bh >> 4, h = bh & 15;
    uint32_t* Ohi = (uint32_t*)g_Ohi4;
    uint32_t* Olo = (uint32_t*)g_Olo4;
    const long base0 = ((long)(b * SQ + qrow0)) * EMB + h * HD;
    const long base1 = base0 + 8L * EMB;
    #pragma unroll
    for (int nfd = 0; nfd < 8; nfd++) {
        const int col = nfd * 8 + tm4 * 2;
        uint32_t hh, ll;
        split2(O[nfd][0] * i0, O[nfd][1] * i0, hh, ll);
        Ohi[(base0 + col) >> 1] = hh;
        Olo[(base0 + col) >> 1] = ll;
        split2(O[nfd][2] * i1, O[nfd][3] * i1, hh, ll);
        Ohi[(base1 + col) >> 1] = hh;
        Olo[(base1 + col) >> 1] = ll;
    }
}

// ---------------------------------------------------------------------------
extern "C" void kernel_launch(void* const* d_in, const int* in_sizes, int n_in,
                              void* d_out, int out_size)
{
    const float* x      = (const float*)d_in[0];
    const float* W_attn = (const float*)d_in[1];
    const float* b_attn = (const float*)d_in[2];
    const float* W_proj = (const float*)d_in[3];
    const float* b_proj = (const float*)d_in[4];
    float* out = (float*)d_out;

    const int DSM = 2 * STAGEB;          // 81920
    const int ASM_SZ = 256 * AROW;       // 36864
    cudaFuncSetAttribute(k_gemm_qkv,  cudaFuncAttributeMaxDynamicSharedMemorySize, DSM);
    cudaFuncSetAttribute(k_gemm_proj, cudaFuncAttributeMaxDynamicSharedMemorySize, DSM);

    uint4 *xhi, *xlo, *wahi, *walo, *wphi, *wplo;
    cudaGetSymbolAddress((void**)&xhi,  g_Xhi4);
    cudaGetSymbolAddress((void**)&xlo,  g_Xlo4);
    cudaGetSymbolAddress((void**)&wahi, g_WaThi4);
    cudaGetSymbolAddress((void**)&walo, g_WaTlo4);
    cudaGetSymbolAddress((void**)&wphi, g_WpThi4);
    cudaGetSymbolAddress((void**)&wplo, g_WpTlo4);

    k_cvt<<<4096, 256>>>((const float4*)x, (uint2*)xhi, (uint2*)xlo, 4096 * 1024 / 4);
    k_wT<<<dim3(96, 32), dim3(32, 8)>>>(W_attn, 3072, (ushortx*)wahi, (ushortx*)walo);
    k_wT<<<dim3(32, 32), dim3(32, 8)>>>(W_proj, 1024, (ushortx*)wphi, (ushortx*)wplo);
    k_gemm_qkv<<<dim3(24, 32), 256, DSM>>>(b_attn);
    k_attn_mma<<<dim3(8, 64), 256, ASM_SZ>>>();
    k_gemm_proj<<<dim3(8, 32), 256, DSM>>>(b_proj, out);
}

// round 8
// speedup vs baseline: 1.0155x; 1.0155x over previous
#include <cuda_runtime.h>
#include <cuda_bf16.h>
#include <math.h>
#include <cstdint>

#define BSZ 4
#define SQ  1024
#define EMB 1024
#define NH  16
#define HD  64

typedef unsigned long long u64;
typedef unsigned short ushortx;

// ---------------------------------------------------------------------------
// Scratch (__device__ globals; allocation-free)
// ---------------------------------------------------------------------------
__device__ float g_Q[BSZ*NH*SQ*HD];
__device__ float g_K[BSZ*NH*SQ*HD];
__device__ float g_V[BSZ*NH*SQ*HD];

// bf16 hi/lo split operands
__device__ uint4 g_Xhi4[4096*1024*2/16];
__device__ uint4 g_Xlo4[4096*1024*2/16];
__device__ uint4 g_Ohi4[4096*1024*2/16];
__device__ uint4 g_Olo4[4096*1024*2/16];
__device__ uint4 g_WaThi4[3072*1024*2/16];   // W_attn^T [3072][1024]
__device__ uint4 g_WaTlo4[3072*1024*2/16];
__device__ uint4 g_WpThi4[1024*1024*2/16];   // W_proj^T [1024][1024]
__device__ uint4 g_WpTlo4[1024*1024*2/16];

// ---------------------------------------------------------------------------
// helpers
// ---------------------------------------------------------------------------
__device__ __forceinline__ uint32_t smem_u32(const void* p) {
    uint32_t a;
    asm("{ .reg .u64 t; cvta.to.shared.u64 t, %1; cvt.u32.u64 %0, t; }" : "=r"(a) : "l"(p));
    return a;
}
__device__ __forceinline__ void cpa16(uint32_t dst, const void* src) {
    asm volatile("cp.async.cg.shared.global [%0], [%1], 16;"
                 :: "r"(dst), "l"(__cvta_generic_to_global(src)) : "memory");
}
#define CPA_COMMIT() asm volatile("cp.async.commit_group;" ::: "memory")
#define CPA_WAIT(n)  asm volatile("cp.async.wait_group %0;" :: "n"(n) : "memory")

// m16n8k16 bf16 MMA, fp32 accumulate
__device__ __forceinline__ void mma16816(float* c, const uint32_t* a, const uint32_t* b) {
    asm volatile("mma.sync.aligned.m16n8k16.row.col.f32.bf16.bf16.f32 "
        "{%0,%1,%2,%3}, {%4,%5,%6,%7}, {%8,%9}, {%0,%1,%2,%3};"
        : "+f"(c[0]), "+f"(c[1]), "+f"(c[2]), "+f"(c[3])
        : "r"(a[0]), "r"(a[1]), "r"(a[2]), "r"(a[3]), "r"(b[0]), "r"(b[1]));
}
__device__ __forceinline__ void mma16816_b2(float* c, const uint32_t* a, uint32_t b0, uint32_t b1) {
    asm volatile("mma.sync.aligned.m16n8k16.row.col.f32.bf16.bf16.f32 "
        "{%0,%1,%2,%3}, {%4,%5,%6,%7}, {%8,%9}, {%0,%1,%2,%3};"
        : "+f"(c[0]), "+f"(c[1]), "+f"(c[2]), "+f"(c[3])
        : "r"(a[0]), "r"(a[1]), "r"(a[2]), "r"(a[3]), "r"(b0), "r"(b1));
}
__device__ __forceinline__ void ldm_x4(uint32_t* r, uint32_t addr) {
    asm volatile("ldmatrix.sync.aligned.m8n8.x4.shared.b16 {%0,%1,%2,%3}, [%4];"
        : "=r"(r[0]), "=r"(r[1]), "=r"(r[2]), "=r"(r[3]) : "r"(addr));
}
__device__ __forceinline__ void ldm_x2(uint32_t* r, uint32_t addr) {
    asm volatile("ldmatrix.sync.aligned.m8n8.x2.shared.b16 {%0,%1}, [%2];"
        : "=r"(r[0]), "=r"(r[1]) : "r"(addr));
}
__device__ __forceinline__ void ldm_x2t(uint32_t* r, uint32_t addr) {
    asm volatile("ldmatrix.sync.aligned.m8n8.x2.trans.shared.b16 {%0,%1}, [%2];"
        : "=r"(r[0]), "=r"(r[1]) : "r"(addr));
}
// two f32 -> packed bf16x2 hi + residual lo
__device__ __forceinline__ void split2(float x, float y, uint32_t& h, uint32_t& l) {
    __nv_bfloat16 hx = __float2bfloat16_rn(x);
    __nv_bfloat16 hy = __float2bfloat16_rn(y);
    float rx = x - __bfloat162float(hx);
    float ry = y - __bfloat162float(hy);
    __nv_bfloat16 lx = __float2bfloat16_rn(rx);
    __nv_bfloat16 ly = __float2bfloat16_rn(ry);
    h = (uint32_t)__bfloat16_as_ushort(hx) | ((uint32_t)__bfloat16_as_ushort(hy) << 16);
    l = (uint32_t)__bfloat16_as_ushort(lx) | ((uint32_t)__bfloat16_as_ushort(ly) << 16);
}

// ---------------------------------------------------------------------------
// GEMM geometry: 128x128 block, BK=64, 8 warps (2m x 4n), warp tile 64x32.
// smem stage: 4 arrays (Ahi, Alo, Bhi, Blo), each 128 rows x 144 bytes
// (128B data + 16B pad; 36-bank row stride -> conflict-free ldmatrix phases).
// Double-buffered: 2 x 73728B. 1 CTA/SM, no register cap.
// ---------------------------------------------------------------------------
#define ROWB   144
#define ARRB   (128*ROWB)     // 18432
#define STAGEB (4*ARRB)       // 73728
#define NCHUNK 16             // 1024 / 64

__device__ __forceinline__ void load_chunk(
    uint32_t st, const ushortx* A0, const ushortx* A1,
    const ushortx* B0, const ushortx* B1, int k0, int tid)
{
    const ushortx* srcs[4] = {A0, A1, B0, B1};
    #pragma unroll
    for (int arr = 0; arr < 4; arr++) {
        const ushortx* s = srcs[arr];
        #pragma unroll
        for (int i = 0; i < 4; i++) {
            const int u = i * 256 + tid;      // 0..1023
            const int r = u >> 3, c16 = u & 7;
            cpa16(st + arr * ARRB + r * ROWB + c16 * 16,
                  (const char*)(s + r * 1024 + k0) + c16 * 16);
        }
    }
}

__device__ __forceinline__ void compute_chunk(
    uint32_t st, int wm, int wn, int lane, float acc[4][4][4])
{
    #pragma unroll
    for (int ks = 0; ks < 4; ks++) {
        const uint32_t acol = ks * 32 + ((lane >> 4) << 4);
        uint32_t Ahi[4][4], Alo[4][4], Bh[2][4], Bl[2][4];
        #pragma unroll
        for (int mf = 0; mf < 4; mf++) {
            const uint32_t ra = st + (wm * 64 + mf * 16 + (lane & 15)) * ROWB + acol;
            ldm_x4(Ahi[mf], ra);
            ldm_x4(Alo[mf], ra + ARRB);
        }
        #pragma unroll
        for (int nh = 0; nh < 2; nh++) {
            const uint32_t rb = st + 2 * ARRB + (wn * 32 + nh * 16 + (lane & 15)) * ROWB + acol;
            ldm_x4(Bh[nh], rb);
            ldm_x4(Bl[nh], rb + ARRB);
        }
        #pragma unroll
        for (int mf = 0; mf < 4; mf++)
            #pragma unroll
            for (int nh = 0; nh < 2; nh++)
                #pragma unroll
                for (int s = 0; s < 2; s++) {
                    float* c = acc[mf][nh * 2 + s];
                    mma16816_b2(c, Ahi[mf], Bh[nh][s], Bh[nh][s + 2]);
                    mma16816_b2(c, Ahi[mf], Bl[nh][s], Bl[nh][s + 2]);
                    mma16816_b2(c, Alo[mf], Bh[nh][s], Bh[nh][s + 2]);
                }
    }
}

__device__ __forceinline__ void gemm_mainloop(
    uint32_t sm, const ushortx* A0, const ushortx* A1,
    const ushortx* B0, const ushortx* B1,
    int wm, int wn, int lane, int tid, float acc[4][4][4])
{
    #pragma unroll
    for (int mf = 0; mf < 4; mf++)
        #pragma unroll
        for (int nf = 0; nf < 4; nf++)
            #pragma unroll
            for (int j = 0; j < 4; j++) acc[mf][nf][j] = 0.f;

    load_chunk(sm, A0, A1, B0, B1, 0, tid);
    CPA_COMMIT();
    for (int c = 0; c < NCHUNK; c++) {
        CPA_WAIT(0);              // chunk c resident
        __syncthreads();          // publishes chunk c; proves compute c-1 done
        if (c + 1 < NCHUNK) {
            load_chunk(sm + ((c + 1) & 1) * STAGEB, A0, A1, B0, B1, (c + 1) * 64, tid);
            CPA_COMMIT();
        }
        compute_chunk(sm + (c & 1) * STAGEB, wm, wn, lane, acc);
    }
}

// ---------------------------------------------------------------------------
// QKV GEMM: X @ W_attn + b_attn -> scatter to g_Q (x0.125) / g_K / g_V
// ---------------------------------------------------------------------------
__global__ __launch_bounds__(256, 1) void k_gemm_qkv(const float* __restrict__ bias)
{
    extern __shared__ __align__(16) char dsm[];
    const int tid = threadIdx.x, wid = tid >> 5, lane = tid & 31;
    const int t4 = lane >> 2, tm4 = lane & 3;
    const int wm = wid >> 2, wn = wid & 3;
    const int bn = blockIdx.x * 128, bm = blockIdx.y * 128;
    const uint32_t sm = smem_u32(dsm);

    float acc[4][4][4];
    gemm_mainloop(sm,
        (const ushortx*)g_Xhi4 + (long)bm * 1024, (const ushortx*)g_Xlo4 + (long)bm * 1024,
        (const ushortx*)g_WaThi4 + (long)bn * 1024, (const ushortx*)g_WaTlo4 + (long)bn * 1024,
        wm, wn, lane, tid, acc);

    const int which = bn >> 10;
    float* dst = (which == 0) ? g_Q : (which == 1) ? g_K : g_V;
    const float scale = (which == 0) ? 0.125f : 1.f;

    #pragma unroll
    for (int mf = 0; mf < 4; mf++) {
        #pragma unroll
        for (int nf = 0; nf < 4; nf++) {
            const int n_g = bn + wn * 32 + nf * 8 + tm4 * 2;
            const int e = n_g & 1023, h = e >> 6, d = e & 63;
            const float b0 = __ldg(&bias[n_g]), b1 = __ldg(&bias[n_g + 1]);
            #pragma unroll
            for (int rr = 0; rr < 2; rr++) {
                const int row = bm + wm * 64 + mf * 16 + t4 + rr * 8;
                const int b = row >> 10, s = row & 1023;
                const long off = (((long)(b * NH + h) * SQ) + s) * HD + d;
                float2 v = make_float2((acc[mf][nf][rr * 2 + 0] + b0) * scale,
                                       (acc[mf][nf][rr * 2 + 1] + b1) * scale);
                *(float2*)&dst[off] = v;
            }
        }
    }
}

// ---------------------------------------------------------------------------
// Proj GEMM: Obf16 @ W_proj + b_proj -> out
// ---------------------------------------------------------------------------
__global__ __launch_bounds__(256, 1) void k_gemm_proj(const float* __restrict__ bias,
                                                      float* __restrict__ out)
{
    extern __shared__ __align__(16) char dsm[];
    const int tid = threadIdx.x, wid = tid >> 5, lane = tid & 31;
    const int t4 = lane >> 2, tm4 = lane & 3;
    const int wm = wid >> 2, wn = wid & 3;
    const int bn = blockIdx.x * 128, bm = blockIdx.y * 128;
    const uint32_t sm = smem_u32(dsm);

    float acc[4][4][4];
    gemm_mainloop(sm,
        (const ushortx*)g_Ohi4 + (long)bm * 1024, (const ushortx*)g_Olo4 + (long)bm * 1024,
        (const ushortx*)g_WpThi4 + (long)bn * 1024, (const ushortx*)g_WpTlo4 + (long)bn * 1024,
        wm, wn, lane, tid, acc);

    #pragma unroll
    for (int mf = 0; mf < 4; mf++) {
        #pragma unroll
        for (int nf = 0; nf < 4; nf++) {
            const int n_g = bn + wn * 32 + nf * 8 + tm4 * 2;
            const float b0 = __ldg(&bias[n_g]), b1 = __ldg(&bias[n_g + 1]);
            #pragma unroll
            for (int rr = 0; rr < 2; rr++) {
                const int row = bm + wm * 64 + mf * 16 + t4 + rr * 8;
                float2 v = make_float2(acc[mf][nf][rr * 2 + 0] + b0,
                                       acc[mf][nf][rr * 2 + 1] + b1);
                *(float2*)&out[(long)row * EMB + n_g] = v;
            }
        }
    }
}

// ---------------------------------------------------------------------------
// Elementwise f32 -> bf16 hi/lo split
// ---------------------------------------------------------------------------
__global__ __launch_bounds__(256) void k_cvt(const float4* __restrict__ src,
                                             uint2* __restrict__ hi, uint2* __restrict__ lo, int n4)
{
    int i = blockIdx.x * 256 + threadIdx.x;
    if (i >= n4) return;
    float4 v = src[i];
    uint32_t h0, h1, l0, l1;
    split2(v.x, v.y, h0, l0);
    split2(v.z, v.w, h1, l1);
    hi[i] = make_uint2(h0, h1);
    lo[i] = make_uint2(l0, l1);
}

// ---------------------------------------------------------------------------
// Transpose-convert: W [1024, ncols] f32 -> W^T hi/lo [ncols, 1024] bf16
// ---------------------------------------------------------------------------
__global__ __launch_bounds__(256) void k_wT(const float* __restrict__ W, int ncols,
                                            ushortx* __restrict__ hiT,
                                            ushortx* __restrict__ loT)
{
    __shared__ float t[32][33];
    const int tx = threadIdx.x, ty = threadIdx.y;
    const int n0 = blockIdx.x * 32, k0 = blockIdx.y * 32;
    #pragma unroll
    for (int i = 0; i < 4; i++)
        t[ty + i * 8][tx] = W[(k0 + ty + i * 8) * ncols + n0 + tx];
    __syncthreads();
    #pragma unroll
    for (int i = 0; i < 4; i++) {
        const int r = ty + i * 8;
        float v = t[tx][r];
        __nv_bfloat16 bh = __float2bfloat16_rn(v);
        float rr = v - __bfloat162float(bh);
        __nv_bfloat16 bl = __float2bfloat16_rn(rr);
        const int off = (n0 + r) * 1024 + k0 + tx;
        hiT[off] = __bfloat16_as_ushort(bh);
        loT[off] = __bfloat16_as_ushort(bl);
    }
}

// ---------------------------------------------------------------------------
// HMMA causal flash attention (unchanged from R6 pass).
// Block: 128 q-rows x 1 head. 8 warps x 16 q-rows. 64-key tiles.
// ---------------------------------------------------------------------------
#define AROW 144

__global__ __launch_bounds__(256, 1) void k_attn_mma()
{
    extern __shared__ char smb[];
    const uint32_t sb = smem_u32(smb);
    const int tid = threadIdx.x, lane = tid & 31, w = tid >> 5;
    const int t4 = lane >> 2, tm4 = lane & 3;
    const int bh = blockIdx.y;
    const int q0 = ((int)gridDim.x - 1 - (int)blockIdx.x) * 128;  // heavy blocks first

    // ---- stage Q (f32 -> bf16 hi/lo in smem)
    const float* Qg = g_Q + ((long)bh * SQ + q0) * HD;
    #pragma unroll
    for (int i = 0; i < 8; i++) {
        const int idx = i * 256 + tid;
        const int r = idx >> 4, c4 = idx & 15;
        float4 v = ((const float4*)Qg)[idx];
        uint32_t h0, h1, l0, l1;
        split2(v.x, v.y, h0, l0);
        split2(v.z, v.w, h1, l1);
        *(uint2*)(smb + r * AROW + c4 * 8) = make_uint2(h0, h1);
        *(uint2*)(smb + 128 * AROW + r * AROW + c4 * 8) = make_uint2(l0, l1);
    }
    __syncthreads();

    uint32_t qh[4][4], ql[4][4];
    {
        const uint32_t rowq = w * 16 + (lane & 15);
        #pragma unroll
        for (int ks = 0; ks < 4; ks++) {
            const uint32_t col = ks * 32 + ((lane >> 4) << 4);
            ldm_x4(qh[ks], sb + rowq * AROW + col);
            ldm_x4(ql[ks], sb + 128 * AROW + rowq * AROW + col);
        }
    }
    __syncthreads();

    const uint32_t Khi = sb, Klo = sb + 64 * AROW,
                   Vhi = sb + 128 * AROW, Vlo = sb + 192 * AROW;

    float O[8][4];
    #pragma unroll
    for (int i = 0; i < 8; i++)
        #pragma unroll
        for (int j = 0; j < 4; j++) O[i][j] = 0.f;
    float m0 = -INFINITY, m1 = -INFINITY, lsum0 = 0.f, lsum1 = 0.f;
    const int qrow0 = q0 + w * 16 + t4;

    const float* Kg = g_K + (long)bh * SQ * HD;
    const float* Vg = g_V + (long)bh * SQ * HD;
    const int nkt = q0 / 64 + 2;

    for (int kt = 0; kt < nkt; kt++) {
        const int k0 = kt * 64;
        #pragma unroll
        for (int i = 0; i < 4; i++) {
            const int idx = i * 256 + tid;
            const int r = idx >> 4, c4 = idx & 15;
            float4 kv = ((const float4*)(Kg + (long)k0 * HD))[idx];
            float4 vv = ((const float4*)(Vg + (long)k0 * HD))[idx];
            uint32_t h0, h1, l0, l1;
            split2(kv.x, kv.y, h0, l0);
            split2(kv.z, kv.w, h1, l1);
            *(uint2*)(smb + (Khi - sb) + r * AROW + c4 * 8) = make_uint2(h0, h1);
            *(uint2*)(smb + (Klo - sb) + r * AROW + c4 * 8) = make_uint2(l0, l1);
            split2(vv.x, vv.y, h0, l0);
            split2(vv.z, vv.w, h1, l1);
            *(uint2*)(smb + (Vhi - sb) + r * AROW + c4 * 8) = make_uint2(h0, h1);
            *(uint2*)(smb + (Vlo - sb) + r * AROW + c4 * 8) = make_uint2(l0, l1);
        }
        __syncthreads();

        float sc[8][4];
        #pragma unroll
        for (int nf = 0; nf < 8; nf++) {
            sc[nf][0] = sc[nf][1] = sc[nf][2] = sc[nf][3] = 0.f;
            const uint32_t rowk = nf * 8 + (lane & 7);
            const uint32_t colp = ((lane >> 3) & 1) * 16;
            #pragma unroll
            for (int ks = 0; ks < 4; ks++) {
                uint32_t bh_[2], bl_[2];
                ldm_x2(bh_, Khi + rowk * AROW + ks * 32 + colp);
                ldm_x2(bl_, Klo + rowk * AROW + ks * 32 + colp);
                mma16816(sc[nf], qh[ks], bh_);
                mma16816(sc[nf], qh[ks], bl_);
                mma16816(sc[nf], ql[ks], bh_);
            }
        }

        if (kt >= nkt - 2) {
            #pragma unroll
            for (int nf = 0; nf < 8; nf++) {
                const int col = k0 + nf * 8 + tm4 * 2;
                if (col     > qrow0)     sc[nf][0] = -1e30f;
                if (col + 1 > qrow0)     sc[nf][1] = -1e30f;
                if (col     > qrow0 + 8) sc[nf][2] = -1e30f;
                if (col + 1 > qrow0 + 8) sc[nf][3] = -1e30f;
            }
        }

        float mx0 = sc[0][0], mx1 = sc[0][2];
        #pragma unroll
        for (int nf = 0; nf < 8; nf++) {
            mx0 = fmaxf(mx0, fmaxf(sc[nf][0], sc[nf][1]));
            mx1 = fmaxf(mx1, fmaxf(sc[nf][2], sc[nf][3]));
        }
        mx0 = fmaxf(mx0, __shfl_xor_sync(0xFFFFFFFF, mx0, 1));
        mx0 = fmaxf(mx0, __shfl_xor_sync(0xFFFFFFFF, mx0, 2));
        mx1 = fmaxf(mx1, __shfl_xor_sync(0xFFFFFFFF, mx1, 1));
        mx1 = fmaxf(mx1, __shfl_xor_sync(0xFFFFFFFF, mx1, 2));
        const float mn0 = fmaxf(m0, mx0), mn1 = fmaxf(m1, mx1);
        const float c0 = __expf(m0 - mn0), c1 = __expf(m1 - mn1);
        m0 = mn0; m1 = mn1;
        float ps0 = 0.f, ps1 = 0.f;
        #pragma unroll
        for (int nf = 0; nf < 8; nf++) {
            sc[nf][0] = __expf(sc[nf][0] - mn0); ps0 += sc[nf][0];
            sc[nf][1] = __expf(sc[nf][1] - mn0); ps0 += sc[nf][1];
            sc[nf][2] = __expf(sc[nf][2] - mn1); ps1 += sc[nf][2];
            sc[nf][3] = __expf(sc[nf][3] - mn1); ps1 += sc[nf][3];
        }
        ps0 += __shfl_xor_sync(0xFFFFFFFF, ps0, 1);
        ps0 += __shfl_xor_sync(0xFFFFFFFF, ps0, 2);
        ps1 += __shfl_xor_sync(0xFFFFFFFF, ps1, 1);
        ps1 += __shfl_xor_sync(0xFFFFFFFF, ps1, 2);
        lsum0 = lsum0 * c0 + ps0;
        lsum1 = lsum1 * c1 + ps1;
        #pragma unroll
        for (int nf = 0; nf < 8; nf++) {
            O[nf][0] *= c0; O[nf][1] *= c0;
            O[nf][2] *= c1; O[nf][3] *= c1;
        }

        uint32_t ph[4][4], pl[4][4];
        #pragma unroll
        for (int j = 0; j < 4; j++) {
            split2(sc[2*j    ][0], sc[2*j    ][1], ph[j][0], pl[j][0]);
            split2(sc[2*j    ][2], sc[2*j    ][3], ph[j][1], pl[j][1]);
            split2(sc[2*j + 1][0], sc[2*j + 1][1], ph[j][2], pl[j][2]);
            split2(sc[2*j + 1][2], sc[2*j + 1][3], ph[j][3], pl[j][3]);
        }

        #pragma unroll
        for (int nfd = 0; nfd < 8; nfd++) {
            #pragma unroll
            for (int ks = 0; ks < 4; ks++) {
                uint32_t bvh[2], bvl[2];
                const uint32_t rowv = ks * 16 + (lane & 15);
                ldm_x2t(bvh, Vhi + rowv * AROW + nfd * 16);
                ldm_x2t(bvl, Vlo + rowv * AROW + nfd * 16);
                mma16816(O[nfd], ph[ks], bvh);
                mma16816(O[nfd], ph[ks], bvl);
                mma16816(O[nfd], pl[ks], bvh);
            }
        }
        __syncthreads();
    }

    const float i0 = 1.f / lsum0, i1 = 1.f / lsum1;
    const int b = bh >> 4, h = bh & 15;
    uint32_t* Ohi = (uint32_t*)g_Ohi4;
    uint32_t* Olo = (uint32_t*)g_Olo4;
    const long base0 = ((long)(b * SQ + qrow0)) * EMB + h * HD;
    const long base1 = base0 + 8L * EMB;
    #pragma unroll
    for (int nfd = 0; nfd < 8; nfd++) {
        const int col = nfd * 8 + tm4 * 2;
        uint32_t hh, ll;
        split2(O[nfd][0] * i0, O[nfd][1] * i0, hh, ll);
        Ohi[(base0 + col) >> 1] = hh;
        Olo[(base0 + col) >> 1] = ll;
        split2(O[nfd][2] * i1, O[nfd][3] * i1, hh, ll);
        Ohi[(base1 + col) >> 1] = hh;
        Olo[(base1 + col) >> 1] = ll;
    }
}

// ---------------------------------------------------------------------------
extern "C" void kernel_launch(void* const* d_in, const int* in_sizes, int n_in,
                              void* d_out, int out_size)
{
    const float* x      = (const float*)d_in[0];
    const float* W_attn = (const float*)d_in[1];
    const float* b_attn = (const float*)d_in[2];
    const float* W_proj = (const float*)d_in[3];
    const float* b_proj = (const float*)d_in[4];
    float* out = (float*)d_out;

    const int DSM = 2 * STAGEB;          // 147456
    const int ASM_SZ = 256 * AROW;       // 36864
    cudaFuncSetAttribute(k_gemm_qkv,  cudaFuncAttributeMaxDynamicSharedMemorySize, DSM);
    cudaFuncSetAttribute(k_gemm_proj, cudaFuncAttributeMaxDynamicSharedMemorySize, DSM);

    uint4 *xhi, *xlo, *wahi, *walo, *wphi, *wplo;
    cudaGetSymbolAddress((void**)&xhi,  g_Xhi4);
    cudaGetSymbolAddress((void**)&xlo,  g_Xlo4);
    cudaGetSymbolAddress((void**)&wahi, g_WaThi4);
    cudaGetSymbolAddress((void**)&walo, g_WaTlo4);
    cudaGetSymbolAddress((void**)&wphi, g_WpThi4);
    cudaGetSymbolAddress((void**)&wplo, g_WpTlo4);

    k_cvt<<<4096, 256>>>((const float4*)x, (uint2*)xhi, (uint2*)xlo, 4096 * 1024 / 4);
    k_wT<<<dim3(96, 32), dim3(32, 8)>>>(W_attn, 3072, (ushortx*)wahi, (ushortx*)walo);
    k_wT<<<dim3(32, 32), dim3(32, 8)>>>(W_proj, 1024, (ushortx*)wphi, (ushortx*)wplo);
    k_gemm_qkv<<<dim3(24, 32), 256, DSM>>>(b_attn);
    k_attn_mma<<<dim3(8, 64), 256, ASM_SZ>>>();
    k_gemm_proj<<<dim3(8, 32), 256, DSM>>>(b_proj, out);
}

// round 10
// speedup vs baseline: 1.1035x; 1.0867x over previous
#include <cuda_runtime.h>
#include <cuda_bf16.h>
#include <math.h>
#include <cstdint>

#define BSZ 4
#define SQ  1024
#define EMB 1024
#define NH  16
#define HD  64

typedef unsigned long long u64;
typedef unsigned short ushortx;

// ---------------------------------------------------------------------------
// Scratch (__device__ globals; allocation-free)
// Q/K/V live ONLY as bf16 hi/lo ([B,H,S,D]); O as bf16 hi/lo ([B,S,E]).
// ---------------------------------------------------------------------------
__device__ uint4 g_Qhi4[BSZ*NH*SQ*HD*2/16];
__device__ uint4 g_Qlo4[BSZ*NH*SQ*HD*2/16];
__device__ uint4 g_Khi4[BSZ*NH*SQ*HD*2/16];
__device__ uint4 g_Klo4[BSZ*NH*SQ*HD*2/16];
__device__ uint4 g_Vhi4[BSZ*NH*SQ*HD*2/16];
__device__ uint4 g_Vlo4[BSZ*NH*SQ*HD*2/16];

__device__ uint4 g_Xhi4[4096*1024*2/16];
__device__ uint4 g_Xlo4[4096*1024*2/16];
__device__ uint4 g_Ohi4[4096*1024*2/16];
__device__ uint4 g_Olo4[4096*1024*2/16];
__device__ uint4 g_WaThi4[3072*1024*2/16];   // W_attn^T [3072][1024]
__device__ uint4 g_WaTlo4[3072*1024*2/16];
__device__ uint4 g_WpThi4[1024*1024*2/16];   // W_proj^T [1024][1024]
__device__ uint4 g_WpTlo4[1024*1024*2/16];

// ---------------------------------------------------------------------------
// helpers
// ---------------------------------------------------------------------------
__device__ __forceinline__ uint32_t smem_u32(const void* p) {
    uint32_t a;
    asm("{ .reg .u64 t; cvta.to.shared.u64 t, %1; cvt.u32.u64 %0, t; }" : "=r"(a) : "l"(p));
    return a;
}
__device__ __forceinline__ void cpa16(uint32_t dst, const void* src) {
    asm volatile("cp.async.cg.shared.global [%0], [%1], 16;"
                 :: "r"(dst), "l"(__cvta_generic_to_global(src)) : "memory");
}
#define CPA_COMMIT() asm volatile("cp.async.commit_group;" ::: "memory")
#define CPA_WAIT(n)  asm volatile("cp.async.wait_group %0;" :: "n"(n) : "memory")

__device__ __forceinline__ uint32_t lds32(uint32_t addr) {
    uint32_t v; asm volatile("ld.shared.b32 %0,[%1];" : "=r"(v) : "r"(addr)); return v;
}
// m16n8k16 bf16 MMA, fp32 accumulate
__device__ __forceinline__ void mma16816(float* c, const uint32_t* a, const uint32_t* b) {
    asm volatile("mma.sync.aligned.m16n8k16.row.col.f32.bf16.bf16.f32 "
        "{%0,%1,%2,%3}, {%4,%5,%6,%7}, {%8,%9}, {%0,%1,%2,%3};"
        : "+f"(c[0]), "+f"(c[1]), "+f"(c[2]), "+f"(c[3])
        : "r"(a[0]), "r"(a[1]), "r"(a[2]), "r"(a[3]), "r"(b[0]), "r"(b[1]));
}
__device__ __forceinline__ void ldm_x4(uint32_t* r, uint32_t addr) {
    asm volatile("ldmatrix.sync.aligned.m8n8.x4.shared.b16 {%0,%1,%2,%3}, [%4];"
        : "=r"(r[0]), "=r"(r[1]), "=r"(r[2]), "=r"(r[3]) : "r"(addr));
}
__device__ __forceinline__ void ldm_x2(uint32_t* r, uint32_t addr) {
    asm volatile("ldmatrix.sync.aligned.m8n8.x2.shared.b16 {%0,%1}, [%2];"
        : "=r"(r[0]), "=r"(r[1]) : "r"(addr));
}
__device__ __forceinline__ void ldm_x2t(uint32_t* r, uint32_t addr) {
    asm volatile("ldmatrix.sync.aligned.m8n8.x2.trans.shared.b16 {%0,%1}, [%2];"
        : "=r"(r[0]), "=r"(r[1]) : "r"(addr));
}
// two f32 -> packed bf16x2 hi + residual lo
__device__ __forceinline__ void split2(float x, float y, uint32_t& h, uint32_t& l) {
    __nv_bfloat16 hx = __float2bfloat16_rn(x);
    __nv_bfloat16 hy = __float2bfloat16_rn(y);
    float rx = x - __bfloat162float(hx);
    float ry = y - __bfloat162float(hy);
    __nv_bfloat16 lx = __float2bfloat16_rn(rx);
    __nv_bfloat16 ly = __float2bfloat16_rn(ry);
    h = (uint32_t)__bfloat16_as_ushort(hx) | ((uint32_t)__bfloat16_as_ushort(hy) << 16);
    l = (uint32_t)__bfloat16_as_ushort(lx) | ((uint32_t)__bfloat16_as_ushort(ly) << 16);
}

// ---------------------------------------------------------------------------
// GEMM geometry — EXACT R6 core (275us / tensor 52.4%): 128x128 block, BK=64,
// 8 warps (2m x 4n), warp tile 64x32, scalar lds32 fragment fill,
// wait -> sync -> compute -> sync, double buffer, 1 CTA/SM, no reg cap.
// ---------------------------------------------------------------------------
#define ROWB   144
#define ARRB   (128*ROWB)     // 18432
#define STAGEB (4*ARRB)       // 73728
#define NCHUNK 16             // 1024 / 64

__device__ __forceinline__ void load_chunk(
    uint32_t st, const ushortx* A0, const ushortx* A1,
    const ushortx* B0, const ushortx* B1, int k0, int tid)
{
    const ushortx* srcs[4] = {A0, A1, B0, B1};
    #pragma unroll
    for (int arr = 0; arr < 4; arr++) {
        const ushortx* s = srcs[arr];
        #pragma unroll
        for (int i = 0; i < 4; i++) {
            const int u = i * 256 + tid;      // 0..1023
            const int r = u >> 3, c16 = u & 7;
            cpa16(st + arr * ARRB + r * ROWB + c16 * 16,
                  (const char*)(s + r * 1024 + k0) + c16 * 16);
        }
    }
}

__device__ __forceinline__ void compute_chunk(
    uint32_t st, int wm, int wn, int t4, int tm4, float acc[4][4][4])
{
    #pragma unroll
    for (int ks = 0; ks < 4; ks++) {
        const int kb = ks * 32 + tm4 * 4;     // byte offset of this thread's k pair
        uint32_t Ahi[4][4], Alo[4][4], Bhi[4][2], Blo[4][2];
        #pragma unroll
        for (int mf = 0; mf < 4; mf++) {
            const uint32_t ra = st + (wm * 64 + mf * 16 + t4) * ROWB + kb;
            Ahi[mf][0] = lds32(ra);
            Ahi[mf][1] = lds32(ra + 8 * ROWB);
            Ahi[mf][2] = lds32(ra + 16);
            Ahi[mf][3] = lds32(ra + 8 * ROWB + 16);
            Alo[mf][0] = lds32(ra + ARRB);
            Alo[mf][1] = lds32(ra + ARRB + 8 * ROWB);
            Alo[mf][2] = lds32(ra + ARRB + 16);
            Alo[mf][3] = lds32(ra + ARRB + 8 * ROWB + 16);
        }
        #pragma unroll
        for (int nf = 0; nf < 4; nf++) {
            const uint32_t rb = st + 2 * ARRB + (wn * 32 + nf * 8 + t4) * ROWB + kb;
            Bhi[nf][0] = lds32(rb);
            Bhi[nf][1] = lds32(rb + 16);
            Blo[nf][0] = lds32(rb + ARRB);
            Blo[nf][1] = lds32(rb + ARRB + 16);
        }
        #pragma unroll
        for (int mf = 0; mf < 4; mf++)
            #pragma unroll
            for (int nf = 0; nf < 4; nf++) {
                mma16816(acc[mf][nf], Ahi[mf], Bhi[nf]);
                mma16816(acc[mf][nf], Ahi[mf], Blo[nf]);
                mma16816(acc[mf][nf], Alo[mf], Bhi[nf]);
            }
    }
}

__device__ __forceinline__ void gemm_mainloop(
    uint32_t sm, const ushortx* A0, const ushortx* A1,
    const ushortx* B0, const ushortx* B1,
    int wm, int wn, int t4, int tm4, int tid, float acc[4][4][4])
{
    #pragma unroll
    for (int mf = 0; mf < 4; mf++)
        #pragma unroll
        for (int nf = 0; nf < 4; nf++)
            #pragma unroll
            for (int j = 0; j < 4; j++) acc[mf][nf][j] = 0.f;

    load_chunk(sm, A0, A1, B0, B1, 0, tid);
    CPA_COMMIT();
    for (int c = 0; c < NCHUNK; c++) {
        if (c + 1 < NCHUNK) {
            load_chunk(sm + ((c + 1) & 1) * STAGEB, A0, A1, B0, B1, (c + 1) * 64, tid);
            CPA_COMMIT();
            CPA_WAIT(1);
        } else {
            CPA_WAIT(0);
        }
        __syncthreads();
        compute_chunk(sm + (c & 1) * STAGEB, wm, wn, t4, tm4, acc);
        __syncthreads();
    }
}

// ---------------------------------------------------------------------------
// QKV GEMM: X @ W_attn + b_attn -> bf16 hi/lo Q (x0.125) / K / V  [B,H,S,D]
// ---------------------------------------------------------------------------
__global__ __launch_bounds__(256, 1) void k_gemm_qkv(const float* __restrict__ bias)
{
    extern __shared__ __align__(16) char dsm[];
    const int tid = threadIdx.x, wid = tid >> 5, lane = tid & 31;
    const int t4 = lane >> 2, tm4 = lane & 3;
    const int wm = wid >> 2, wn = wid & 3;
    const int bn = blockIdx.x * 128, bm = blockIdx.y * 128;
    const uint32_t sm = smem_u32(dsm);

    float acc[4][4][4];
    gemm_mainloop(sm,
        (const ushortx*)g_Xhi4 + (long)bm * 1024, (const ushortx*)g_Xlo4 + (long)bm * 1024,
        (const ushortx*)g_WaThi4 + (long)bn * 1024, (const ushortx*)g_WaTlo4 + (long)bn * 1024,
        wm, wn, t4, tm4, tid, acc);

    const int which = bn >> 10;             // 0=Q 1=K 2=V
    uint32_t* dhi = (which == 0) ? (uint32_t*)g_Qhi4 : (which == 1) ? (uint32_t*)g_Khi4 : (uint32_t*)g_Vhi4;
    uint32_t* dlo = (which == 0) ? (uint32_t*)g_Qlo4 : (which == 1) ? (uint32_t*)g_Klo4 : (uint32_t*)g_Vlo4;
    const float scale = (which == 0) ? 0.125f : 1.f;

    #pragma unroll
    for (int mf = 0; mf < 4; mf++) {
        #pragma unroll
        for (int nf = 0; nf < 4; nf++) {
            const int n_g = bn + wn * 32 + nf * 8 + tm4 * 2;
            const int e = n_g & 1023, h = e >> 6, d = e & 63;
            const float b0 = __ldg(&bias[n_g]), b1 = __ldg(&bias[n_g + 1]);
            #pragma unroll
            for (int rr = 0; rr < 2; rr++) {
                const int row = bm + wm * 64 + mf * 16 + t4 + rr * 8;
                const int b = row >> 10, s = row & 1023;
                const long off = (((long)(b * NH + h) * SQ) + s) * HD + d;
                uint32_t hh, ll;
                split2((acc[mf][nf][rr * 2 + 0] + b0) * scale,
                       (acc[mf][nf][rr * 2 + 1] + b1) * scale, hh, ll);
                dhi[off >> 1] = hh;
                dlo[off >> 1] = ll;
            }
        }
    }
}

// ---------------------------------------------------------------------------
// Proj GEMM: Obf16 @ W_proj + b_proj -> out
// ---------------------------------------------------------------------------
__global__ __launch_bounds__(256, 1) void k_gemm_proj(const float* __restrict__ bias,
                                                      float* __restrict__ out)
{
    extern __shared__ __align__(16) char dsm[];
    const int tid = threadIdx.x, wid = tid >> 5, lane = tid & 31;
    const int t4 = lane >> 2, tm4 = lane & 3;
    const int wm = wid >> 2, wn = wid & 3;
    const int bn = blockIdx.x * 128, bm = blockIdx.y * 128;
    const uint32_t sm = smem_u32(dsm);

    float acc[4][4][4];
    gemm_mainloop(sm,
        (const ushortx*)g_Ohi4 + (long)bm * 1024, (const ushortx*)g_Olo4 + (long)bm * 1024,
        (const ushortx*)g_WpThi4 + (long)bn * 1024, (const ushortx*)g_WpTlo4 + (long)bn * 1024,
        wm, wn, t4, tm4, tid, acc);

    #pragma unroll
    for (int mf = 0; mf < 4; mf++) {
        #pragma unroll
        for (int nf = 0; nf < 4; nf++) {
            const int n_g = bn + wn * 32 + nf * 8 + tm4 * 2;
            const float b0 = __ldg(&bias[n_g]), b1 = __ldg(&bias[n_g + 1]);
            #pragma unroll
            for (int rr = 0; rr < 2; rr++) {
                const int row = bm + wm * 64 + mf * 16 + t4 + rr * 8;
                float2 v = make_float2(acc[mf][nf][rr * 2 + 0] + b0,
                                       acc[mf][nf][rr * 2 + 1] + b1);
                *(float2*)&out[(long)row * EMB + n_g] = v;
            }
        }
    }
}

// ---------------------------------------------------------------------------
// Elementwise f32 -> bf16 hi/lo split
// ---------------------------------------------------------------------------
__global__ __launch_bounds__(256) void k_cvt(const float4* __restrict__ src,
                                             uint2* __restrict__ hi, uint2* __restrict__ lo, int n4)
{
    int i = blockIdx.x * 256 + threadIdx.x;
    if (i >= n4) return;
    float4 v = src[i];
    uint32_t h0, h1, l0, l1;
    split2(v.x, v.y, h0, l0);
    split2(v.z, v.w, h1, l1);
    hi[i] = make_uint2(h0, h1);
    lo[i] = make_uint2(l0, l1);
}

// ---------------------------------------------------------------------------
// Transpose-convert: W [1024, ncols] f32 -> W^T hi/lo [ncols, 1024] bf16
// ---------------------------------------------------------------------------
__global__ __launch_bounds__(256) void k_wT(const float* __restrict__ W, int ncols,
                                            ushortx* __restrict__ hiT,
                                            ushortx* __restrict__ loT)
{
    __shared__ float t[32][33];
    const int tx = threadIdx.x, ty = threadIdx.y;
    const int n0 = blockIdx.x * 32, k0 = blockIdx.y * 32;
    #pragma unroll
    for (int i = 0; i < 4; i++)
        t[ty + i * 8][tx] = W[(k0 + ty + i * 8) * ncols + n0 + tx];
    __syncthreads();
    #pragma unroll
    for (int i = 0; i < 4; i++) {
        const int r = ty + i * 8;
        float v = t[tx][r];
        __nv_bfloat16 bh = __float2bfloat16_rn(v);
        float rr = v - __bfloat162float(bh);
        __nv_bfloat16 bl = __float2bfloat16_rn(rr);
        const int off = (n0 + r) * 1024 + k0 + tx;
        hiT[off] = __bfloat16_as_ushort(bh);
        loT[off] = __bfloat16_as_ushort(bl);
    }
}

// ---------------------------------------------------------------------------
// HMMA causal flash attention — bf16-native I/O.
// Block: 128 q-rows x 1 head. 8 warps x 16 q-rows. 64-key tiles.
// Q/K/V arrive pre-split as bf16 hi/lo; staging is pure cp.async.
// smem 256*AROW: Q stage = Qhi[128]|Qlo[128]; k-loop = Khi|Klo|Vhi|Vlo [64] each.
// ---------------------------------------------------------------------------
#define AROW 144

__global__ __launch_bounds__(256, 1) void k_attn_mma()
{
    extern __shared__ char smb[];
    const uint32_t sb = smem_u32(smb);
    const int tid = threadIdx.x, lane = tid & 31, w = tid >> 5;
    const int t4 = lane >> 2, tm4 = lane & 3;
    const int bh = blockIdx.y;
    const int q0 = ((int)gridDim.x - 1 - (int)blockIdx.x) * 128;  // heavy blocks first

    const long headoff = (long)bh * SQ * HD;

    // ---- stage Q hi/lo via cp.async (128 rows x 128B per array)
    {
        const char* qh_g = (const char*)((const ushortx*)g_Qhi4 + headoff + (long)q0 * HD);
        const char* ql_g = (const char*)((const ushortx*)g_Qlo4 + headoff + (long)q0 * HD);
        #pragma unroll
        for (int i = 0; i < 4; i++) {
            const int u = i * 256 + tid;        // 0..1023
            const int r = u >> 3, seg = u & 7;
            cpa16(sb + r * AROW + seg * 16, qh_g + r * 128 + seg * 16);
            cpa16(sb + 128 * AROW + r * AROW + seg * 16, ql_g + r * 128 + seg * 16);
        }
        CPA_COMMIT();
        CPA_WAIT(0);
        __syncthreads();
    }

    // ---- Q fragments (A, m16k16 x4 k-steps), kept in regs for whole kernel
    uint32_t qh[4][4], ql[4][4];
    {
        const uint32_t rowq = w * 16 + (lane & 15);
        #pragma unroll
        for (int ks = 0; ks < 4; ks++) {
            const uint32_t col = ks * 32 + ((lane >> 4) << 4);
            ldm_x4(qh[ks], sb + rowq * AROW + col);
            ldm_x4(ql[ks], sb + 128 * AROW + rowq * AROW + col);
        }
    }
    __syncthreads();   // Q smem area now reusable for K/V

    const uint32_t Khi = sb, Klo = sb + 64 * AROW,
                   Vhi = sb + 128 * AROW, Vlo = sb + 192 * AROW;

    float O[8][4];
    #pragma unroll
    for (int i = 0; i < 8; i++)
        #pragma unroll
        for (int j = 0; j < 4; j++) O[i][j] = 0.f;
    float m0 = -INFINITY, m1 = -INFINITY, lsum0 = 0.f, lsum1 = 0.f;
    const int qrow0 = q0 + w * 16 + t4;

    const char* kh_g = (const char*)((const ushortx*)g_Khi4 + headoff);
    const char* kl_g = (const char*)((const ushortx*)g_Klo4 + headoff);
    const char* vh_g = (const char*)((const ushortx*)g_Vhi4 + headoff);
    const char* vl_g = (const char*)((const ushortx*)g_Vlo4 + headoff);
    const int nkt = q0 / 64 + 2;

    for (int kt = 0; kt < nkt; kt++) {
        const int k0 = kt * 64;
        // ---- stage K/V hi/lo tiles via cp.async (64 rows x 128B x 4 arrays)
        {
            const long tb = (long)k0 * HD * 2;   // byte offset of tile start
            const char* srcs[4] = {kh_g + tb, kl_g + tb, vh_g + tb, vl_g + tb};
            const uint32_t dsts[4] = {Khi, Klo, Vhi, Vlo};
            #pragma unroll
            for (int arr = 0; arr < 4; arr++) {
                #pragma unroll
                for (int i = 0; i < 2; i++) {
                    const int u = i * 256 + tid;   // 0..511
                    const int r = u >> 3, seg = u & 7;
                    cpa16(dsts[arr] + r * AROW + seg * 16, srcs[arr] + r * 128 + seg * 16);
                }
            }
            CPA_COMMIT();
            CPA_WAIT(0);
            __syncthreads();
        }

        // ---- scores S = Q K^T (3-MMA split), 8 n-frags of 8 keys
        float sc[8][4];
        #pragma unroll
        for (int nf = 0; nf < 8; nf++) {
            sc[nf][0] = sc[nf][1] = sc[nf][2] = sc[nf][3] = 0.f;
            const uint32_t rowk = nf * 8 + (lane & 7);
            const uint32_t colp = ((lane >> 3) & 1) * 16;
            #pragma unroll
            for (int ks = 0; ks < 4; ks++) {
                uint32_t bh_[2], bl_[2];
                ldm_x2(bh_, Khi + rowk * AROW + ks * 32 + colp);
                ldm_x2(bl_, Klo + rowk * AROW + ks * 32 + colp);
                mma16816(sc[nf], qh[ks], bh_);
                mma16816(sc[nf], qh[ks], bl_);
                mma16816(sc[nf], ql[ks], bh_);
            }
        }

        // ---- causal mask (only the last two tiles can clip)
        if (kt >= nkt - 2) {
            #pragma unroll
            for (int nf = 0; nf < 8; nf++) {
                const int col = k0 + nf * 8 + tm4 * 2;
                if (col     > qrow0)     sc[nf][0] = -1e30f;
                if (col + 1 > qrow0)     sc[nf][1] = -1e30f;
                if (col     > qrow0 + 8) sc[nf][2] = -1e30f;
                if (col + 1 > qrow0 + 8) sc[nf][3] = -1e30f;
            }
        }

        // ---- online softmax (rows t4 and t4+8 within warp)
        float mx0 = sc[0][0], mx1 = sc[0][2];
        #pragma unroll
        for (int nf = 0; nf < 8; nf++) {
            mx0 = fmaxf(mx0, fmaxf(sc[nf][0], sc[nf][1]));
            mx1 = fmaxf(mx1, fmaxf(sc[nf][2], sc[nf][3]));
        }
        mx0 = fmaxf(mx0, __shfl_xor_sync(0xFFFFFFFF, mx0, 1));
        mx0 = fmaxf(mx0, __shfl_xor_sync(0xFFFFFFFF, mx0, 2));
        mx1 = fmaxf(mx1, __shfl_xor_sync(0xFFFFFFFF, mx1, 1));
        mx1 = fmaxf(mx1, __shfl_xor_sync(0xFFFFFFFF, mx1, 2));
        const float mn0 = fmaxf(m0, mx0), mn1 = fmaxf(m1, mx1);
        const float c0 = __expf(m0 - mn0), c1 = __expf(m1 - mn1);
        m0 = mn0; m1 = mn1;
        float ps0 = 0.f, ps1 = 0.f;
        #pragma unroll
        for (int nf = 0; nf < 8; nf++) {
            sc[nf][0] = __expf(sc[nf][0] - mn0); ps0 += sc[nf][0];
            sc[nf][1] = __expf(sc[nf][1] - mn0); ps0 += sc[nf][1];
            sc[nf][2] = __expf(sc[nf][2] - mn1); ps1 += sc[nf][2];
            sc[nf][3] = __expf(sc[nf][3] - mn1); ps1 += sc[nf][3];
        }
        ps0 += __shfl_xor_sync(0xFFFFFFFF, ps0, 1);
        ps0 += __shfl_xor_sync(0xFFFFFFFF, ps0, 2);
        ps1 += __shfl_xor_sync(0xFFFFFFFF, ps1, 1);
        ps1 += __shfl_xor_sync(0xFFFFFFFF, ps1, 2);
        lsum0 = lsum0 * c0 + ps0;
        lsum1 = lsum1 * c1 + ps1;
        #pragma unroll
        for (int nf = 0; nf < 8; nf++) {
            O[nf][0] *= c0; O[nf][1] *= c0;
            O[nf][2] *= c1; O[nf][3] *= c1;
        }

        // ---- pack P as A-frags (hi/lo) directly from score c-frags
        uint32_t ph[4][4], pl[4][4];
        #pragma unroll
        for (int j = 0; j < 4; j++) {
            split2(sc[2*j    ][0], sc[2*j    ][1], ph[j][0], pl[j][0]);
            split2(sc[2*j    ][2], sc[2*j    ][3], ph[j][1], pl[j][1]);
            split2(sc[2*j + 1][0], sc[2*j + 1][1], ph[j][2], pl[j][2]);
            split2(sc[2*j + 1][2], sc[2*j + 1][3], ph[j][3], pl[j][3]);
        }

        // ---- O += P V (3-MMA split); V^T B-frags via ldmatrix.trans
        #pragma unroll
        for (int nfd = 0; nfd < 8; nfd++) {
            #pragma unroll
            for (int ks = 0; ks < 4; ks++) {
                uint32_t bvh[2], bvl[2];
                const uint32_t rowv = ks * 16 + (lane & 15);
                ldm_x2t(bvh, Vhi + rowv * AROW + nfd * 16);
                ldm_x2t(bvl, Vlo + rowv * AROW + nfd * 16);
                mma16816(O[nfd], ph[ks], bvh);
                mma16816(O[nfd], ph[ks], bvl);
                mma16816(O[nfd], pl[ks], bvh);
            }
        }
        __syncthreads();
    }

    // ---- finalize: O /= l, write bf16 hi/lo in [B,S,E] merged-head layout
    const float i0 = 1.f / lsum0, i1 = 1.f / lsum1;
    const int b = bh >> 4, h = bh & 15;
    uint32_t* Ohi = (uint32_t*)g_Ohi4;
    uint32_t* Olo = (uint32_t*)g_Olo4;
    const long base0 = ((long)(b * SQ + qrow0)) * EMB + h * HD;
    const long base1 = base0 + 8L * EMB;
    #pragma unroll
    for (int nfd = 0; nfd < 8; nfd++) {
        const int col = nfd * 8 + tm4 * 2;
        uint32_t hh, ll;
        split2(O[nfd][0] * i0, O[nfd][1] * i0, hh, ll);
        Ohi[(base0 + col) >> 1] = hh;
        Olo[(base0 + col) >> 1] = ll;
        split2(O[nfd][2] * i1, O[nfd][3] * i1, hh, ll);
        Ohi[(base1 + col) >> 1] = hh;
        Olo[(base1 + col) >> 1] = ll;
    }
}

// ---------------------------------------------------------------------------
extern "C" void kernel_launch(void* const* d_in, const int* in_sizes, int n_in,
                              void* d_out, int out_size)
{
    const float* x      = (const float*)d_in[0];
    const float* W_attn = (const float*)d_in[1];
    const float* b_attn = (const float*)d_in[2];
    const float* W_proj = (const float*)d_in[3];
    const float* b_proj = (const float*)d_in[4];
    float* out = (float*)d_out;

    const int DSM = 2 * STAGEB;          // 147456
    const int ASM_SZ = 256 * AROW;       // 36864
    cudaFuncSetAttribute(k_gemm_qkv,  cudaFuncAttributeMaxDynamicSharedMemorySize, DSM);
    cudaFuncSetAttribute(k_gemm_proj, cudaFuncAttributeMaxDynamicSharedMemorySize, DSM);

    uint4 *xhi, *xlo, *wahi, *walo, *wphi, *wplo;
    cudaGetSymbolAddress((void**)&xhi,  g_Xhi4);
    cudaGetSymbolAddress((void**)&xlo,  g_Xlo4);
    cudaGetSymbolAddress((void**)&wahi, g_WaThi4);
    cudaGetSymbolAddress((void**)&walo, g_WaTlo4);
    cudaGetSymbolAddress((void**)&wphi, g_WpThi4);
    cudaGetSymbolAddress((void**)&wplo, g_WpTlo4);

    k_cvt<<<4096, 256>>>((const float4*)x, (uint2*)xhi, (uint2*)xlo, 4096 * 1024 / 4);
    k_wT<<<dim3(96, 32), dim3(32, 8)>>>(W_attn, 3072, (ushortx*)wahi, (ushortx*)walo);
    k_wT<<<dim3(32, 32), dim3(32, 8)>>>(W_proj, 1024, (ushortx*)wphi, (ushortx*)wplo);
    k_gemm_qkv<<<dim3(24, 32), 256, DSM>>>(b_attn);
    k_attn_mma<<<dim3(8, 64), 256, ASM_SZ>>>();
    k_gemm_proj<<<dim3(8, 32), 256, DSM>>>(b_proj, out);
}

// round 11
// speedup vs baseline: 1.1425x; 1.0354x over previous
#include <cuda_runtime.h>
#include <cuda_bf16.h>
#include <math.h>
#include <cstdint>

#define BSZ 4
#define SQ  1024
#define EMB 1024
#define NH  16
#define HD  64

typedef unsigned long long u64;
typedef unsigned short ushortx;

// ---------------------------------------------------------------------------
// Scratch (__device__ globals; allocation-free)
// Q/K/V live ONLY as bf16 hi/lo ([B,H,S,D]); O as bf16 hi/lo ([B,S,E]).
// ---------------------------------------------------------------------------
__device__ uint4 g_Qhi4[BSZ*NH*SQ*HD*2/16];
__device__ uint4 g_Qlo4[BSZ*NH*SQ*HD*2/16];
__device__ uint4 g_Khi4[BSZ*NH*SQ*HD*2/16];
__device__ uint4 g_Klo4[BSZ*NH*SQ*HD*2/16];
__device__ uint4 g_Vhi4[BSZ*NH*SQ*HD*2/16];
__device__ uint4 g_Vlo4[BSZ*NH*SQ*HD*2/16];

__device__ uint4 g_Xhi4[4096*1024*2/16];
__device__ uint4 g_Xlo4[4096*1024*2/16];
__device__ uint4 g_Ohi4[4096*1024*2/16];
__device__ uint4 g_Olo4[4096*1024*2/16];
__device__ uint4 g_WaThi4[3072*1024*2/16];   // W_attn^T [3072][1024]
__device__ uint4 g_WaTlo4[3072*1024*2/16];
__device__ uint4 g_WpThi4[1024*1024*2/16];   // W_proj^T [1024][1024]
__device__ uint4 g_WpTlo4[1024*1024*2/16];

// ---------------------------------------------------------------------------
// helpers
// ---------------------------------------------------------------------------
__device__ __forceinline__ uint32_t smem_u32(const void* p) {
    uint32_t a;
    asm("{ .reg .u64 t; cvta.to.shared.u64 t, %1; cvt.u32.u64 %0, t; }" : "=r"(a) : "l"(p));
    return a;
}
__device__ __forceinline__ void cpa16(uint32_t dst, const void* src) {
    asm volatile("cp.async.cg.shared.global [%0], [%1], 16;"
                 :: "r"(dst), "l"(__cvta_generic_to_global(src)) : "memory");
}
#define CPA_COMMIT() asm volatile("cp.async.commit_group;" ::: "memory")
#define CPA_WAIT(n)  asm volatile("cp.async.wait_group %0;" :: "n"(n) : "memory")

__device__ __forceinline__ uint32_t lds32(uint32_t addr) {
    uint32_t v; asm volatile("ld.shared.b32 %0,[%1];" : "=r"(v) : "r"(addr)); return v;
}
// m16n8k16 bf16 MMA, fp32 accumulate
__device__ __forceinline__ void mma16816(float* c, const uint32_t* a, const uint32_t* b) {
    asm volatile("mma.sync.aligned.m16n8k16.row.col.f32.bf16.bf16.f32 "
        "{%0,%1,%2,%3}, {%4,%5,%6,%7}, {%8,%9}, {%0,%1,%2,%3};"
        : "+f"(c[0]), "+f"(c[1]), "+f"(c[2]), "+f"(c[3])
        : "r"(a[0]), "r"(a[1]), "r"(a[2]), "r"(a[3]), "r"(b[0]), "r"(b[1]));
}
__device__ __forceinline__ void ldm_x4(uint32_t* r, uint32_t addr) {
    asm volatile("ldmatrix.sync.aligned.m8n8.x4.shared.b16 {%0,%1,%2,%3}, [%4];"
        : "=r"(r[0]), "=r"(r[1]), "=r"(r[2]), "=r"(r[3]) : "r"(addr));
}
__device__ __forceinline__ void ldm_x2(uint32_t* r, uint32_t addr) {
    asm volatile("ldmatrix.sync.aligned.m8n8.x2.shared.b16 {%0,%1}, [%2];"
        : "=r"(r[0]), "=r"(r[1]) : "r"(addr));
}
__device__ __forceinline__ void ldm_x2t(uint32_t* r, uint32_t addr) {
    asm volatile("ldmatrix.sync.aligned.m8n8.x2.trans.shared.b16 {%0,%1}, [%2];"
        : "=r"(r[0]), "=r"(r[1]) : "r"(addr));
}
// two f32 -> packed bf16x2 hi + residual lo
__device__ __forceinline__ void split2(float x, float y, uint32_t& h, uint32_t& l) {
    __nv_bfloat16 hx = __float2bfloat16_rn(x);
    __nv_bfloat16 hy = __float2bfloat16_rn(y);
    float rx = x - __bfloat162float(hx);
    float ry = y - __bfloat162float(hy);
    __nv_bfloat16 lx = __float2bfloat16_rn(rx);
    __nv_bfloat16 ly = __float2bfloat16_rn(ry);
    h = (uint32_t)__bfloat16_as_ushort(hx) | ((uint32_t)__bfloat16_as_ushort(hy) << 16);
    l = (uint32_t)__bfloat16_as_ushort(lx) | ((uint32_t)__bfloat16_as_ushort(ly) << 16);
}

// ---------------------------------------------------------------------------
// GEMM geometry: 64x128 block, BK=64, 4 warps (2m x 2n), warp tile 32x64.
// Per-warp inner work identical to the proven R6 core (48 LDS + 48 MMA / ks,
// scalar lds32 fill, wait(1) -> sync -> compute -> sync).
// smem stage: Ahi/Alo 64x144, Bhi/Blo 128x144 = 55296B; double buffer 110592B.
// 2 CTAs/SM (128 thr each -> 255 regs legal, no cap): cross-CTA overlap
// covers barrier/wait drains.
// ---------------------------------------------------------------------------
#define ROWB   144
#define AARRB  (64*ROWB)               // 9216
#define BARRB  (128*ROWB)              // 18432
#define STAGEB (2*AARRB + 2*BARRB)     // 55296
#define NCHUNK 16                      // 1024 / 64

__device__ __forceinline__ void load_chunk(
    uint32_t st, const ushortx* A0, const ushortx* A1,
    const ushortx* B0, const ushortx* B1, int k0, int tid)
{
    // A hi/lo: 64 rows x 8 segs
    #pragma unroll
    for (int i = 0; i < 4; i++) {
        const int u = i * 128 + tid;      // 0..511
        const int r = u >> 3, c16 = u & 7;
        cpa16(st + r * ROWB + c16 * 16,
              (const char*)(A0 + r * 1024 + k0) + c16 * 16);
        cpa16(st + AARRB + r * ROWB + c16 * 16,
              (const char*)(A1 + r * 1024 + k0) + c16 * 16);
    }
    // B hi/lo: 128 rows x 8 segs
    #pragma unroll
    for (int i = 0; i < 8; i++) {
        const int u = i * 128 + tid;      // 0..1023
        const int r = u >> 3, c16 = u & 7;
        cpa16(st + 2 * AARRB + r * ROWB + c16 * 16,
              (const char*)(B0 + r * 1024 + k0) + c16 * 16);
        cpa16(st + 2 * AARRB + BARRB + r * ROWB + c16 * 16,
              (const char*)(B1 + r * 1024 + k0) + c16 * 16);
    }
}

__device__ __forceinline__ void compute_chunk(
    uint32_t st, int wm, int wn, int t4, int tm4, float acc[2][8][4])
{
    #pragma unroll
    for (int ks = 0; ks < 4; ks++) {
        const int kb = ks * 32 + tm4 * 4;     // byte offset of this thread's k pair
        uint32_t Ahi[2][4], Alo[2][4], Bhi[8][2], Blo[8][2];
        #pragma unroll
        for (int mf = 0; mf < 2; mf++) {
            const uint32_t ra = st + (wm * 32 + mf * 16 + t4) * ROWB + kb;
            Ahi[mf][0] = lds32(ra);
            Ahi[mf][1] = lds32(ra + 8 * ROWB);
            Ahi[mf][2] = lds32(ra + 16);
            Ahi[mf][3] = lds32(ra + 8 * ROWB + 16);
            Alo[mf][0] = lds32(ra + AARRB);
            Alo[mf][1] = lds32(ra + AARRB + 8 * ROWB);
            Alo[mf][2] = lds32(ra + AARRB + 16);
            Alo[mf][3] = lds32(ra + AARRB + 8 * ROWB + 16);
        }
        #pragma unroll
        for (int nf = 0; nf < 8; nf++) {
            const uint32_t rb = st + 2 * AARRB + (wn * 64 + nf * 8 + t4) * ROWB + kb;
            Bhi[nf][0] = lds32(rb);
            Bhi[nf][1] = lds32(rb + 16);
            Blo[nf][0] = lds32(rb + BARRB);
            Blo[nf][1] = lds32(rb + BARRB + 16);
        }
        #pragma unroll
        for (int mf = 0; mf < 2; mf++)
            #pragma unroll
            for (int nf = 0; nf < 8; nf++) {
                mma16816(acc[mf][nf], Ahi[mf], Bhi[nf]);
                mma16816(acc[mf][nf], Ahi[mf], Blo[nf]);
                mma16816(acc[mf][nf], Alo[mf], Bhi[nf]);
            }
    }
}

__device__ __forceinline__ void gemm_mainloop(
    uint32_t sm, const ushortx* A0, const ushortx* A1,
    const ushortx* B0, const ushortx* B1,
    int wm, int wn, int t4, int tm4, int tid, float acc[2][8][4])
{
    #pragma unroll
    for (int mf = 0; mf < 2; mf++)
        #pragma unroll
        for (int nf = 0; nf < 8; nf++)
            #pragma unroll
            for (int j = 0; j < 4; j++) acc[mf][nf][j] = 0.f;

    load_chunk(sm, A0, A1, B0, B1, 0, tid);
    CPA_COMMIT();
    for (int c = 0; c < NCHUNK; c++) {
        if (c + 1 < NCHUNK) {
            load_chunk(sm + ((c + 1) & 1) * STAGEB, A0, A1, B0, B1, (c + 1) * 64, tid);
            CPA_COMMIT();
            CPA_WAIT(1);
        } else {
            CPA_WAIT(0);
        }
        __syncthreads();
        compute_chunk(sm + (c & 1) * STAGEB, wm, wn, t4, tm4, acc);
        __syncthreads();
    }
}

// ---------------------------------------------------------------------------
// QKV GEMM: X @ W_attn + b_attn -> bf16 hi/lo Q (x0.125) / K / V  [B,H,S,D]
// grid (24, 64): x = N-tile of 128 over 3072, y = M-tile of 64 over 4096
// ---------------------------------------------------------------------------
__global__ __launch_bounds__(128, 2) void k_gemm_qkv(const float* __restrict__ bias)
{
    extern __shared__ __align__(16) char dsm[];
    const int tid = threadIdx.x, wid = tid >> 5, lane = tid & 31;
    const int t4 = lane >> 2, tm4 = lane & 3;
    const int wm = wid >> 1, wn = wid & 1;
    const int bn = blockIdx.x * 128, bm = blockIdx.y * 64;
    const uint32_t sm = smem_u32(dsm);

    float acc[2][8][4];
    gemm_mainloop(sm,
        (const ushortx*)g_Xhi4 + (long)bm * 1024, (const ushortx*)g_Xlo4 + (long)bm * 1024,
        (const ushortx*)g_WaThi4 + (long)bn * 1024, (const ushortx*)g_WaTlo4 + (long)bn * 1024,
        wm, wn, t4, tm4, tid, acc);

    const int which = bn >> 10;             // 0=Q 1=K 2=V
    uint32_t* dhi = (which == 0) ? (uint32_t*)g_Qhi4 : (which == 1) ? (uint32_t*)g_Khi4 : (uint32_t*)g_Vhi4;
    uint32_t* dlo = (which == 0) ? (uint32_t*)g_Qlo4 : (which == 1) ? (uint32_t*)g_Klo4 : (uint32_t*)g_Vlo4;
    const float scale = (which == 0) ? 0.125f : 1.f;

    #pragma unroll
    for (int mf = 0; mf < 2; mf++) {
        #pragma unroll
        for (int nf = 0; nf < 8; nf++) {
            const int n_g = bn + wn * 64 + nf * 8 + tm4 * 2;
            const int e = n_g & 1023, h = e >> 6, d = e & 63;
            const float b0 = __ldg(&bias[n_g]), b1 = __ldg(&bias[n_g + 1]);
            #pragma unroll
            for (int rr = 0; rr < 2; rr++) {
                const int row = bm + wm * 32 + mf * 16 + t4 + rr * 8;
                const int b = row >> 10, s = row & 1023;
                const long off = (((long)(b * NH + h) * SQ) + s) * HD + d;
                uint32_t hh, ll;
                split2((acc[mf][nf][rr * 2 + 0] + b0) * scale,
                       (acc[mf][nf][rr * 2 + 1] + b1) * scale, hh, ll);
                dhi[off >> 1] = hh;
                dlo[off >> 1] = ll;
            }
        }
    }
}

// ---------------------------------------------------------------------------
// Proj GEMM: Obf16 @ W_proj + b_proj -> out.  grid (8, 64)
// ---------------------------------------------------------------------------
__global__ __launch_bounds__(128, 2) void k_gemm_proj(const float* __restrict__ bias,
                                                      float* __restrict__ out)
{
    extern __shared__ __align__(16) char dsm[];
    const int tid = threadIdx.x, wid = tid >> 5, lane = tid & 31;
    const int t4 = lane >> 2, tm4 = lane & 3;
    const int wm = wid >> 1, wn = wid & 1;
    const int bn = blockIdx.x * 128, bm = blockIdx.y * 64;
    const uint32_t sm = smem_u32(dsm);

    float acc[2][8][4];
    gemm_mainloop(sm,
        (const ushortx*)g_Ohi4 + (long)bm * 1024, (const ushortx*)g_Olo4 + (long)bm * 1024,
        (const ushortx*)g_WpThi4 + (long)bn * 1024, (const ushortx*)g_WpTlo4 + (long)bn * 1024,
        wm, wn, t4, tm4, tid, acc);

    #pragma unroll
    for (int mf = 0; mf < 2; mf++) {
        #pragma unroll
        for (int nf = 0; nf < 8; nf++) {
            const int n_g = bn + wn * 64 + nf * 8 + tm4 * 2;
            const float b0 = __ldg(&bias[n_g]), b1 = __ldg(&bias[n_g + 1]);
            #pragma unroll
            for (int rr = 0; rr < 2; rr++) {
                const int row = bm + wm * 32 + mf * 16 + t4 + rr * 8;
                float2 v = make_float2(acc[mf][nf][rr * 2 + 0] + b0,
                                       acc[mf][nf][rr * 2 + 1] + b1);
                *(float2*)&out[(long)row * EMB + n_g] = v;
            }
        }
    }
}

// ---------------------------------------------------------------------------
// Elementwise f32 -> bf16 hi/lo split
// ---------------------------------------------------------------------------
__global__ __launch_bounds__(256) void k_cvt(const float4* __restrict__ src,
                                             uint2* __restrict__ hi, uint2* __restrict__ lo, int n4)
{
    int i = blockIdx.x * 256 + threadIdx.x;
    if (i >= n4) return;
    float4 v = src[i];
    uint32_t h0, h1, l0, l1;
    split2(v.x, v.y, h0, l0);
    split2(v.z, v.w, h1, l1);
    hi[i] = make_uint2(h0, h1);
    lo[i] = make_uint2(l0, l1);
}

// ---------------------------------------------------------------------------
// Transpose-convert: W [1024, ncols] f32 -> W^T hi/lo [ncols, 1024] bf16
// ---------------------------------------------------------------------------
__global__ __launch_bounds__(256) void k_wT(const float* __restrict__ W, int ncols,
                                            ushortx* __restrict__ hiT,
                                            ushortx* __restrict__ loT)
{
    __shared__ float t[32][33];
    const int tx = threadIdx.x, ty = threadIdx.y;
    const int n0 = blockIdx.x * 32, k0 = blockIdx.y * 32;
    #pragma unroll
    for (int i = 0; i < 4; i++)
        t[ty + i * 8][tx] = W[(k0 + ty + i * 8) * ncols + n0 + tx];
    __syncthreads();
    #pragma unroll
    for (int i = 0; i < 4; i++) {
        const int r = ty + i * 8;
        float v = t[tx][r];
        __nv_bfloat16 bh = __float2bfloat16_rn(v);
        float rr = v - __bfloat162float(bh);
        __nv_bfloat16 bl = __float2bfloat16_rn(rr);
        const int off = (n0 + r) * 1024 + k0 + tx;
        hiT[off] = __bfloat16_as_ushort(bh);
        loT[off] = __bfloat16_as_ushort(bl);
    }
}

// ---------------------------------------------------------------------------
// HMMA causal flash attention — bf16-native I/O (unchanged from R10 pass).
// Block: 128 q-rows x 1 head. 8 warps x 16 q-rows. 64-key tiles.
// ---------------------------------------------------------------------------
#define AROW 144

__global__ __launch_bounds__(256, 1) void k_attn_mma()
{
    extern __shared__ char smb[];
    const uint32_t sb = smem_u32(smb);
    const int tid = threadIdx.x, lane = tid & 31, w = tid >> 5;
    const int t4 = lane >> 2, tm4 = lane & 3;
    const int bh = blockIdx.y;
    const int q0 = ((int)gridDim.x - 1 - (int)blockIdx.x) * 128;  // heavy blocks first

    const long headoff = (long)bh * SQ * HD;

    // ---- stage Q hi/lo via cp.async (128 rows x 128B per array)
    {
        const char* qh_g = (const char*)((const ushortx*)g_Qhi4 + headoff + (long)q0 * HD);
        const char* ql_g = (const char*)((const ushortx*)g_Qlo4 + headoff + (long)q0 * HD);
        #pragma unroll
        for (int i = 0; i < 4; i++) {
            const int u = i * 256 + tid;        // 0..1023
            const int r = u >> 3, seg = u & 7;
            cpa16(sb + r * AROW + seg * 16, qh_g + r * 128 + seg * 16);
            cpa16(sb + 128 * AROW + r * AROW + seg * 16, ql_g + r * 128 + seg * 16);
        }
        CPA_COMMIT();
        CPA_WAIT(0);
        __syncthreads();
    }

    // ---- Q fragments (A, m16k16 x4 k-steps), kept in regs for whole kernel
    uint32_t qh[4][4], ql[4][4];
    {
        const uint32_t rowq = w * 16 + (lane & 15);
        #pragma unroll
        for (int ks = 0; ks < 4; ks++) {
            const uint32_t col = ks * 32 + ((lane >> 4) << 4);
            ldm_x4(qh[ks], sb + rowq * AROW + col);
            ldm_x4(ql[ks], sb + 128 * AROW + rowq * AROW + col);
        }
    }
    __syncthreads();   // Q smem area now reusable for K/V

    const uint32_t Khi = sb, Klo = sb + 64 * AROW,
                   Vhi = sb + 128 * AROW, Vlo = sb + 192 * AROW;

    float O[8][4];
    #pragma unroll
    for (int i = 0; i < 8; i++)
        #pragma unroll
        for (int j = 0; j < 4; j++) O[i][j] = 0.f;
    float m0 = -INFINITY, m1 = -INFINITY, lsum0 = 0.f, lsum1 = 0.f;
    const int qrow0 = q0 + w * 16 + t4;

    const char* kh_g = (const char*)((const ushortx*)g_Khi4 + headoff);
    const char* kl_g = (const char*)((const ushortx*)g_Klo4 + headoff);
    const char* vh_g = (const char*)((const ushortx*)g_Vhi4 + headoff);
    const char* vl_g = (const char*)((const ushortx*)g_Vlo4 + headoff);
    const int nkt = q0 / 64 + 2;

    for (int kt = 0; kt < nkt; kt++) {
        const int k0 = kt * 64;
        // ---- stage K/V hi/lo tiles via cp.async (64 rows x 128B x 4 arrays)
        {
            const long tb = (long)k0 * HD * 2;   // byte offset of tile start
            const char* srcs[4] = {kh_g + tb, kl_g + tb, vh_g + tb, vl_g + tb};
            const uint32_t dsts[4] = {Khi, Klo, Vhi, Vlo};
            #pragma unroll
            for (int arr = 0; arr < 4; arr++) {
                #pragma unroll
                for (int i = 0; i < 2; i++) {
                    const int u = i * 256 + tid;   // 0..511
                    const int r = u >> 3, seg = u & 7;
                    cpa16(dsts[arr] + r * AROW + seg * 16, srcs[arr] + r * 128 + seg * 16);
                }
            }
            CPA_COMMIT();
            CPA_WAIT(0);
            __syncthreads();
        }

        // ---- scores S = Q K^T (3-MMA split), 8 n-frags of 8 keys
        float sc[8][4];
        #pragma unroll
        for (int nf = 0; nf < 8; nf++) {
            sc[nf][0] = sc[nf][1] = sc[nf][2] = sc[nf][3] = 0.f;
            const uint32_t rowk = nf * 8 + (lane & 7);
            const uint32_t colp = ((lane >> 3) & 1) * 16;
            #pragma unroll
            for (int ks = 0; ks < 4; ks++) {
                uint32_t bh_[2], bl_[2];
                ldm_x2(bh_, Khi + rowk * AROW + ks * 32 + colp);
                ldm_x2(bl_, Klo + rowk * AROW + ks * 32 + colp);
                mma16816(sc[nf], qh[ks], bh_);
                mma16816(sc[nf], qh[ks], bl_);
                mma16816(sc[nf], ql[ks], bh_);
            }
        }

        // ---- causal mask (only the last two tiles can clip)
        if (kt >= nkt - 2) {
            #pragma unroll
            for (int nf = 0; nf < 8; nf++) {
                const int col = k0 + nf * 8 + tm4 * 2;
                if (col     > qrow0)     sc[nf][0] = -1e30f;
                if (col + 1 > qrow0)     sc[nf][1] = -1e30f;
                if (col     > qrow0 + 8) sc[nf][2] = -1e30f;
                if (col + 1 > qrow0 + 8) sc[nf][3] = -1e30f;
            }
        }

        // ---- online softmax (rows t4 and t4+8 within warp)
        float mx0 = sc[0][0], mx1 = sc[0][2];
        #pragma unroll
        for (int nf = 0; nf < 8; nf++) {
            mx0 = fmaxf(mx0, fmaxf(sc[nf][0], sc[nf][1]));
            mx1 = fmaxf(mx1, fmaxf(sc[nf][2], sc[nf][3]));
        }
        mx0 = fmaxf(mx0, __shfl_xor_sync(0xFFFFFFFF, mx0, 1));
        mx0 = fmaxf(mx0, __shfl_xor_sync(0xFFFFFFFF, mx0, 2));
        mx1 = fmaxf(mx1, __shfl_xor_sync(0xFFFFFFFF, mx1, 1));
        mx1 = fmaxf(mx1, __shfl_xor_sync(0xFFFFFFFF, mx1, 2));
        const float mn0 = fmaxf(m0, mx0), mn1 = fmaxf(m1, mx1);
        const float c0 = __expf(m0 - mn0), c1 = __expf(m1 - mn1);
        m0 = mn0; m1 = mn1;
        float ps0 = 0.f, ps1 = 0.f;
        #pragma unroll
        for (int nf = 0; nf < 8; nf++) {
            sc[nf][0] = __expf(sc[nf][0] - mn0); ps0 += sc[nf][0];
            sc[nf][1] = __expf(sc[nf][1] - mn0); ps0 += sc[nf][1];
            sc[nf][2] = __expf(sc[nf][2] - mn1); ps1 += sc[nf][2];
            sc[nf][3] = __expf(sc[nf][3] - mn1); ps1 += sc[nf][3];
        }
        ps0 += __shfl_xor_sync(0xFFFFFFFF, ps0, 1);
        ps0 += __shfl_xor_sync(0xFFFFFFFF, ps0, 2);
        ps1 += __shfl_xor_sync(0xFFFFFFFF, ps1, 1);
        ps1 += __shfl_xor_sync(0xFFFFFFFF, ps1, 2);
        lsum0 = lsum0 * c0 + ps0;
        lsum1 = lsum1 * c1 + ps1;
        #pragma unroll
        for (int nf = 0; nf < 8; nf++) {
            O[nf][0] *= c0; O[nf][1] *= c0;
            O[nf][2] *= c1; O[nf][3] *= c1;
        }

        // ---- pack P as A-frags (hi/lo) directly from score c-frags
        uint32_t ph[4][4], pl[4][4];
        #pragma unroll
        for (int j = 0; j < 4; j++) {
            split2(sc[2*j    ][0], sc[2*j    ][1], ph[j][0], pl[j][0]);
            split2(sc[2*j    ][2], sc[2*j    ][3], ph[j][1], pl[j][1]);
            split2(sc[2*j + 1][0], sc[2*j + 1][1], ph[j][2], pl[j][2]);
            split2(sc[2*j + 1][2], sc[2*j + 1][3], ph[j][3], pl[j][3]);
        }

        // ---- O += P V (3-MMA split); V^T B-frags via ldmatrix.trans
        #pragma unroll
        for (int nfd = 0; nfd < 8; nfd++) {
            #pragma unroll
            for (int ks = 0; ks < 4; ks++) {
                uint32_t bvh[2], bvl[2];
                const uint32_t rowv = ks * 16 + (lane & 15);
                ldm_x2t(bvh, Vhi + rowv * AROW + nfd * 16);
                ldm_x2t(bvl, Vlo + rowv * AROW + nfd * 16);
                mma16816(O[nfd], ph[ks], bvh);
                mma16816(O[nfd], ph[ks], bvl);
                mma16816(O[nfd], pl[ks], bvh);
            }
        }
        __syncthreads();
    }

    // ---- finalize: O /= l, write bf16 hi/lo in [B,S,E] merged-head layout
    const float i0 = 1.f / lsum0, i1 = 1.f / lsum1;
    const int b = bh >> 4, h = bh & 15;
    uint32_t* Ohi = (uint32_t*)g_Ohi4;
    uint32_t* Olo = (uint32_t*)g_Olo4;
    const long base0 = ((long)(b * SQ + qrow0)) * EMB + h * HD;
    const long base1 = base0 + 8L * EMB;
    #pragma unroll
    for (int nfd = 0; nfd < 8; nfd++) {
        const int col = nfd * 8 + tm4 * 2;
        uint32_t hh, ll;
        split2(O[nfd][0] * i0, O[nfd][1] * i0, hh, ll);
        Ohi[(base0 + col) >> 1] = hh;
        Olo[(base0 + col) >> 1] = ll;
        split2(O[nfd][2] * i1, O[nfd][3] * i1, hh, ll);
        Ohi[(base1 + col) >> 1] = hh;
        Olo[(base1 + col) >> 1] = ll;
    }
}

// ---------------------------------------------------------------------------
extern "C" void kernel_launch(void* const* d_in, const int* in_sizes, int n_in,
                              void* d_out, int out_size)
{
    const float* x      = (const float*)d_in[0];
    const float* W_attn = (const float*)d_in[1];
    const float* b_attn = (const float*)d_in[2];
    const float* W_proj = (const float*)d_in[3];
    const float* b_proj = (const float*)d_in[4];
    float* out = (float*)d_out;

    const int DSM = 2 * STAGEB;          // 110592
    const int ASM_SZ = 256 * AROW;       // 36864
    cudaFuncSetAttribute(k_gemm_qkv,  cudaFuncAttributeMaxDynamicSharedMemorySize, DSM);
    cudaFuncSetAttribute(k_gemm_proj, cudaFuncAttributeMaxDynamicSharedMemorySize, DSM);

    uint4 *xhi, *xlo, *wahi, *walo, *wphi, *wplo;
    cudaGetSymbolAddress((void**)&xhi,  g_Xhi4);
    cudaGetSymbolAddress((void**)&xlo,  g_Xlo4);
    cudaGetSymbolAddress((void**)&wahi, g_WaThi4);
    cudaGetSymbolAddress((void**)&walo, g_WaTlo4);
    cudaGetSymbolAddress((void**)&wphi, g_WpThi4);
    cudaGetSymbolAddress((void**)&wplo, g_WpTlo4);

    k_cvt<<<4096, 256>>>((const float4*)x, (uint2*)xhi, (uint2*)xlo, 4096 * 1024 / 4);
    k_wT<<<dim3(96, 32), dim3(32, 8)>>>(W_attn, 3072, (ushortx*)wahi, (ushortx*)walo);
    k_wT<<<dim3(32, 32), dim3(32, 8)>>>(W_proj, 1024, (ushortx*)wphi, (ushortx*)wplo);
    k_gemm_qkv<<<dim3(24, 64), 128, DSM>>>(b_attn);
    k_attn_mma<<<dim3(8, 64), 256, ASM_SZ>>>();
    k_gemm_proj<<<dim3(8, 64), 128, DSM>>>(b_proj, out);
}

// round 12
// speedup vs baseline: 1.1759x; 1.0292x over previous
#include <cuda_runtime.h>
#include <cuda_bf16.h>
#include <math.h>
#include <cstdint>

#define BSZ 4
#define SQ  1024
#define EMB 1024
#define NH  16
#define HD  64

typedef unsigned long long u64;
typedef unsigned short ushortx;

// ---------------------------------------------------------------------------
// Scratch (__device__ globals; allocation-free)
// Q/K/V live ONLY as bf16 hi/lo ([B,H,S,D]); O as bf16 hi/lo ([B,S,E]).
// ---------------------------------------------------------------------------
__device__ uint4 g_Qhi4[BSZ*NH*SQ*HD*2/16];
__device__ uint4 g_Qlo4[BSZ*NH*SQ*HD*2/16];
__device__ uint4 g_Khi4[BSZ*NH*SQ*HD*2/16];
__device__ uint4 g_Klo4[BSZ*NH*SQ*HD*2/16];
__device__ uint4 g_Vhi4[BSZ*NH*SQ*HD*2/16];
__device__ uint4 g_Vlo4[BSZ*NH*SQ*HD*2/16];

__device__ uint4 g_Xhi4[4096*1024*2/16];
__device__ uint4 g_Xlo4[4096*1024*2/16];
__device__ uint4 g_Ohi4[4096*1024*2/16];
__device__ uint4 g_Olo4[4096*1024*2/16];
__device__ uint4 g_WaThi4[3072*1024*2/16];   // W_attn^T [3072][1024]
__device__ uint4 g_WaTlo4[3072*1024*2/16];
__device__ uint4 g_WpThi4[1024*1024*2/16];   // W_proj^T [1024][1024]
__device__ uint4 g_WpTlo4[1024*1024*2/16];

// ---------------------------------------------------------------------------
// helpers
// ---------------------------------------------------------------------------
__device__ __forceinline__ uint32_t smem_u32(const void* p) {
    uint32_t a;
    asm("{ .reg .u64 t; cvta.to.shared.u64 t, %1; cvt.u32.u64 %0, t; }" : "=r"(a) : "l"(p));
    return a;
}
__device__ __forceinline__ void cpa16(uint32_t dst, const void* src) {
    asm volatile("cp.async.cg.shared.global [%0], [%1], 16;"
                 :: "r"(dst), "l"(__cvta_generic_to_global(src)) : "memory");
}
#define CPA_COMMIT() asm volatile("cp.async.commit_group;" ::: "memory")
#define CPA_WAIT(n)  asm volatile("cp.async.wait_group %0;" :: "n"(n) : "memory")

__device__ __forceinline__ uint32_t lds32(uint32_t addr) {
    uint32_t v; asm volatile("ld.shared.b32 %0,[%1];" : "=r"(v) : "r"(addr)); return v;
}
// m16n8k16 bf16 MMA, fp32 accumulate
__device__ __forceinline__ void mma16816(float* c, const uint32_t* a, const uint32_t* b) {
    asm volatile("mma.sync.aligned.m16n8k16.row.col.f32.bf16.bf16.f32 "
        "{%0,%1,%2,%3}, {%4,%5,%6,%7}, {%8,%9}, {%0,%1,%2,%3};"
        : "+f"(c[0]), "+f"(c[1]), "+f"(c[2]), "+f"(c[3])
        : "r"(a[0]), "r"(a[1]), "r"(a[2]), "r"(a[3]), "r"(b[0]), "r"(b[1]));
}
__device__ __forceinline__ void ldm_x4(uint32_t* r, uint32_t addr) {
    asm volatile("ldmatrix.sync.aligned.m8n8.x4.shared.b16 {%0,%1,%2,%3}, [%4];"
        : "=r"(r[0]), "=r"(r[1]), "=r"(r[2]), "=r"(r[3]) : "r"(addr));
}
__device__ __forceinline__ void ldm_x2(uint32_t* r, uint32_t addr) {
    asm volatile("ldmatrix.sync.aligned.m8n8.x2.shared.b16 {%0,%1}, [%2];"
        : "=r"(r[0]), "=r"(r[1]) : "r"(addr));
}
__device__ __forceinline__ void ldm_x2t(uint32_t* r, uint32_t addr) {
    asm volatile("ldmatrix.sync.aligned.m8n8.x2.trans.shared.b16 {%0,%1}, [%2];"
        : "=r"(r[0]), "=r"(r[1]) : "r"(addr));
}
// two f32 -> packed bf16x2 hi + residual lo
__device__ __forceinline__ void split2(float x, float y, uint32_t& h, uint32_t& l) {
    __nv_bfloat16 hx = __float2bfloat16_rn(x);
    __nv_bfloat16 hy = __float2bfloat16_rn(y);
    float rx = x - __bfloat162float(hx);
    float ry = y - __bfloat162float(hy);
    __nv_bfloat16 lx = __float2bfloat16_rn(rx);
    __nv_bfloat16 ly = __float2bfloat16_rn(ry);
    h = (uint32_t)__bfloat16_as_ushort(hx) | ((uint32_t)__bfloat16_as_ushort(hy) << 16);
    l = (uint32_t)__bfloat16_as_ushort(lx) | ((uint32_t)__bfloat16_as_ushort(ly) << 16);
}

// ---------------------------------------------------------------------------
// GEMM geometry (R11, proven): 64x128 block, BK=64, 4 warps (2m x 2n),
// warp tile 32x64, scalar lds32 fill, wait(1)->sync->compute->sync,
// double buffer, 2 CTAs/SM of 128 threads.
// ---------------------------------------------------------------------------
#define ROWB   144
#define AARRB  (64*ROWB)               // 9216
#define BARRB  (128*ROWB)              // 18432
#define STAGEB (2*AARRB + 2*BARRB)     // 55296
#define NCHUNK 16                      // 1024 / 64

__device__ __forceinline__ void load_chunk(
    uint32_t st, const ushortx* A0, const ushortx* A1,
    const ushortx* B0, const ushortx* B1, int k0, int tid)
{
    // A hi/lo: 64 rows x 8 segs
    #pragma unroll
    for (int i = 0; i < 4; i++) {
        const int u = i * 128 + tid;      // 0..511
        const int r = u >> 3, c16 = u & 7;
        cpa16(st + r * ROWB + c16 * 16,
              (const char*)(A0 + r * 1024 + k0) + c16 * 16);
        cpa16(st + AARRB + r * ROWB + c16 * 16,
              (const char*)(A1 + r * 1024 + k0) + c16 * 16);
    }
    // B hi/lo: 128 rows x 8 segs
    #pragma unroll
    for (int i = 0; i < 8; i++) {
        const int u = i * 128 + tid;      // 0..1023
        const int r = u >> 3, c16 = u & 7;
        cpa16(st + 2 * AARRB + r * ROWB + c16 * 16,
              (const char*)(B0 + r * 1024 + k0) + c16 * 16);
        cpa16(st + 2 * AARRB + BARRB + r * ROWB + c16 * 16,
              (const char*)(B1 + r * 1024 + k0) + c16 * 16);
    }
}

__device__ __forceinline__ void compute_chunk(
    uint32_t st, int wm, int wn, int t4, int tm4, float acc[2][8][4])
{
    #pragma unroll
    for (int ks = 0; ks < 4; ks++) {
        const int kb = ks * 32 + tm4 * 4;     // byte offset of this thread's k pair
        uint32_t Ahi[2][4], Alo[2][4], Bhi[8][2], Blo[8][2];
        #pragma unroll
        for (int mf = 0; mf < 2; mf++) {
            const uint32_t ra = st + (wm * 32 + mf * 16 + t4) * ROWB + kb;
            Ahi[mf][0] = lds32(ra);
            Ahi[mf][1] = lds32(ra + 8 * ROWB);
            Ahi[mf][2] = lds32(ra + 16);
            Ahi[mf][3] = lds32(ra + 8 * ROWB + 16);
            Alo[mf][0] = lds32(ra + AARRB);
            Alo[mf][1] = lds32(ra + AARRB + 8 * ROWB);
            Alo[mf][2] = lds32(ra + AARRB + 16);
            Alo[mf][3] = lds32(ra + AARRB + 8 * ROWB + 16);
        }
        #pragma unroll
        for (int nf = 0; nf < 8; nf++) {
            const uint32_t rb = st + 2 * AARRB + (wn * 64 + nf * 8 + t4) * ROWB + kb;
            Bhi[nf][0] = lds32(rb);
            Bhi[nf][1] = lds32(rb + 16);
            Blo[nf][0] = lds32(rb + BARRB);
            Blo[nf][1] = lds32(rb + BARRB + 16);
        }
        #pragma unroll
        for (int mf = 0; mf < 2; mf++)
            #pragma unroll
            for (int nf = 0; nf < 8; nf++) {
                mma16816(acc[mf][nf], Ahi[mf], Bhi[nf]);
                mma16816(acc[mf][nf], Ahi[mf], Blo[nf]);
                mma16816(acc[mf][nf], Alo[mf], Bhi[nf]);
            }
    }
}

__device__ __forceinline__ void gemm_mainloop(
    uint32_t sm, const ushortx* A0, const ushortx* A1,
    const ushortx* B0, const ushortx* B1,
    int wm, int wn, int t4, int tm4, int tid, float acc[2][8][4])
{
    #pragma unroll
    for (int mf = 0; mf < 2; mf++)
        #pragma unroll
        for (int nf = 0; nf < 8; nf++)
            #pragma unroll
            for (int j = 0; j < 4; j++) acc[mf][nf][j] = 0.f;

    load_chunk(sm, A0, A1, B0, B1, 0, tid);
    CPA_COMMIT();
    for (int c = 0; c < NCHUNK; c++) {
        if (c + 1 < NCHUNK) {
            load_chunk(sm + ((c + 1) & 1) * STAGEB, A0, A1, B0, B1, (c + 1) * 64, tid);
            CPA_COMMIT();
            CPA_WAIT(1);
        } else {
            CPA_WAIT(0);
        }
        __syncthreads();
        compute_chunk(sm + (c & 1) * STAGEB, wm, wn, t4, tm4, acc);
        __syncthreads();
    }
}

// ---------------------------------------------------------------------------
// QKV GEMM: X @ W_attn + b_attn -> bf16 hi/lo Q (x0.125) / K / V  [B,H,S,D]
// grid (24, 64)
// ---------------------------------------------------------------------------
__global__ __launch_bounds__(128, 2) void k_gemm_qkv(const float* __restrict__ bias)
{
    extern __shared__ __align__(16) char dsm[];
    const int tid = threadIdx.x, wid = tid >> 5, lane = tid & 31;
    const int t4 = lane >> 2, tm4 = lane & 3;
    const int wm = wid >> 1, wn = wid & 1;
    const int bn = blockIdx.x * 128, bm = blockIdx.y * 64;
    const uint32_t sm = smem_u32(dsm);

    float acc[2][8][4];
    gemm_mainloop(sm,
        (const ushortx*)g_Xhi4 + (long)bm * 1024, (const ushortx*)g_Xlo4 + (long)bm * 1024,
        (const ushortx*)g_WaThi4 + (long)bn * 1024, (const ushortx*)g_WaTlo4 + (long)bn * 1024,
        wm, wn, t4, tm4, tid, acc);

    const int which = bn >> 10;             // 0=Q 1=K 2=V
    uint32_t* dhi = (which == 0) ? (uint32_t*)g_Qhi4 : (which == 1) ? (uint32_t*)g_Khi4 : (uint32_t*)g_Vhi4;
    uint32_t* dlo = (which == 0) ? (uint32_t*)g_Qlo4 : (which == 1) ? (uint32_t*)g_Klo4 : (uint32_t*)g_Vlo4;
    const float scale = (which == 0) ? 0.125f : 1.f;

    #pragma unroll
    for (int mf = 0; mf < 2; mf++) {
        #pragma unroll
        for (int nf = 0; nf < 8; nf++) {
            const int n_g = bn + wn * 64 + nf * 8 + tm4 * 2;
            const int e = n_g & 1023, h = e >> 6, d = e & 63;
            const float b0 = __ldg(&bias[n_g]), b1 = __ldg(&bias[n_g + 1]);
            #pragma unroll
            for (int rr = 0; rr < 2; rr++) {
                const int row = bm + wm * 32 + mf * 16 + t4 + rr * 8;
                const int b = row >> 10, s = row & 1023;
                const long off = (((long)(b * NH + h) * SQ) + s) * HD + d;
                uint32_t hh, ll;
                split2((acc[mf][nf][rr * 2 + 0] + b0) * scale,
                       (acc[mf][nf][rr * 2 + 1] + b1) * scale, hh, ll);
                dhi[off >> 1] = hh;
                dlo[off >> 1] = ll;
            }
        }
    }
}

// ---------------------------------------------------------------------------
// Proj GEMM: Obf16 @ W_proj + b_proj -> out.  grid (8, 64)
// ---------------------------------------------------------------------------
__global__ __launch_bounds__(128, 2) void k_gemm_proj(const float* __restrict__ bias,
                                                      float* __restrict__ out)
{
    extern __shared__ __align__(16) char dsm[];
    const int tid = threadIdx.x, wid = tid >> 5, lane = tid & 31;
    const int t4 = lane >> 2, tm4 = lane & 3;
    const int wm = wid >> 1, wn = wid & 1;
    const int bn = blockIdx.x * 128, bm = blockIdx.y * 64;
    const uint32_t sm = smem_u32(dsm);

    float acc[2][8][4];
    gemm_mainloop(sm,
        (const ushortx*)g_Ohi4 + (long)bm * 1024, (const ushortx*)g_Olo4 + (long)bm * 1024,
        (const ushortx*)g_WpThi4 + (long)bn * 1024, (const ushortx*)g_WpTlo4 + (long)bn * 1024,
        wm, wn, t4, tm4, tid, acc);

    #pragma unroll
    for (int mf = 0; mf < 2; mf++) {
        #pragma unroll
        for (int nf = 0; nf < 8; nf++) {
            const int n_g = bn + wn * 64 + nf * 8 + tm4 * 2;
            const float b0 = __ldg(&bias[n_g]), b1 = __ldg(&bias[n_g + 1]);
            #pragma unroll
            for (int rr = 0; rr < 2; rr++) {
                const int row = bm + wm * 32 + mf * 16 + t4 + rr * 8;
                float2 v = make_float2(acc[mf][nf][rr * 2 + 0] + b0,
                                       acc[mf][nf][rr * 2 + 1] + b1);
                *(float2*)&out[(long)row * EMB + n_g] = v;
            }
        }
    }
}

// ---------------------------------------------------------------------------
// Elementwise f32 -> bf16 hi/lo split
// ---------------------------------------------------------------------------
__global__ __launch_bounds__(256) void k_cvt(const float4* __restrict__ src,
                                             uint2* __restrict__ hi, uint2* __restrict__ lo, int n4)
{
    int i = blockIdx.x * 256 + threadIdx.x;
    if (i >= n4) return;
    float4 v = src[i];
    uint32_t h0, h1, l0, l1;
    split2(v.x, v.y, h0, l0);
    split2(v.z, v.w, h1, l1);
    hi[i] = make_uint2(h0, h1);
    lo[i] = make_uint2(l0, l1);
}

// ---------------------------------------------------------------------------
// Transpose-convert: W [1024, ncols] f32 -> W^T hi/lo [ncols, 1024] bf16
// ---------------------------------------------------------------------------
__global__ __launch_bounds__(256) void k_wT(const float* __restrict__ W, int ncols,
                                            ushortx* __restrict__ hiT,
                                            ushortx* __restrict__ loT)
{
    __shared__ float t[32][33];
    const int tx = threadIdx.x, ty = threadIdx.y;
    const int n0 = blockIdx.x * 32, k0 = blockIdx.y * 32;
    #pragma unroll
    for (int i = 0; i < 4; i++)
        t[ty + i * 8][tx] = W[(k0 + ty + i * 8) * ncols + n0 + tx];
    __syncthreads();
    #pragma unroll
    for (int i = 0; i < 4; i++) {
        const int r = ty + i * 8;
        float v = t[tx][r];
        __nv_bfloat16 bh = __float2bfloat16_rn(v);
        float rr = v - __bfloat162float(bh);
        __nv_bfloat16 bl = __float2bfloat16_rn(rr);
        const int off = (n0 + r) * 1024 + k0 + tx;
        hiT[off] = __bfloat16_as_ushort(bh);
        loT[off] = __bfloat16_as_ushort(bl);
    }
}

// ---------------------------------------------------------------------------
// HMMA causal flash attention — bf16-native I/O + DOUBLE-BUFFERED K/V staging.
// Block: 128 q-rows x 1 head. 8 warps x 16 q-rows. 64-key tiles.
// smem: 2 KV stages x (Khi|Klo|Vhi|Vlo, 64 rows x AROW) = 73728B.
// Q staged through stage-0 area before the loop (frags then live in regs).
// ---------------------------------------------------------------------------
#define AROW     144
#define KVARR    (64*AROW)      // 9216
#define KVSTAGE  (4*KVARR)      // 36864

__global__ __launch_bounds__(256, 1) void k_attn_mma()
{
    extern __shared__ char smb[];
    const uint32_t sb = smem_u32(smb);
    const int tid = threadIdx.x, lane = tid & 31, w = tid >> 5;
    const int t4 = lane >> 2, tm4 = lane & 3;
    const int bh = blockIdx.y;
    const int q0 = ((int)gridDim.x - 1 - (int)blockIdx.x) * 128;  // heavy blocks first

    const long headoff = (long)bh * SQ * HD;

    // ---- stage Q hi/lo via cp.async (uses stage-0 area; 128 rows x 128B x2)
    {
        const char* qh_g = (const char*)((const ushortx*)g_Qhi4 + headoff + (long)q0 * HD);
        const char* ql_g = (const char*)((const ushortx*)g_Qlo4 + headoff + (long)q0 * HD);
        #pragma unroll
        for (int i = 0; i < 4; i++) {
            const int u = i * 256 + tid;        // 0..1023
            const int r = u >> 3, seg = u & 7;
            cpa16(sb + r * AROW + seg * 16, qh_g + r * 128 + seg * 16);
            cpa16(sb + 128 * AROW + r * AROW + seg * 16, ql_g + r * 128 + seg * 16);
        }
        CPA_COMMIT();
        CPA_WAIT(0);
        __syncthreads();
    }

    // ---- Q fragments (A, m16k16 x4 k-steps), kept in regs for whole kernel
    uint32_t qh[4][4], ql[4][4];
    {
        const uint32_t rowq = w * 16 + (lane & 15);
        #pragma unroll
        for (int ks = 0; ks < 4; ks++) {
            const uint32_t col = ks * 32 + ((lane >> 4) << 4);
            ldm_x4(qh[ks], sb + rowq * AROW + col);
            ldm_x4(ql[ks], sb + 128 * AROW + rowq * AROW + col);
        }
    }
    __syncthreads();   // all warps done reading Q smem; buffers reusable

    float O[8][4];
    #pragma unroll
    for (int i = 0; i < 8; i++)
        #pragma unroll
        for (int j = 0; j < 4; j++) O[i][j] = 0.f;
    float m0 = -INFINITY, m1 = -INFINITY, lsum0 = 0.f, lsum1 = 0.f;
    const int qrow0 = q0 + w * 16 + t4;

    const char* kh_g = (const char*)((const ushortx*)g_Khi4 + headoff);
    const char* kl_g = (const char*)((const ushortx*)g_Klo4 + headoff);
    const char* vh_g = (const char*)((const ushortx*)g_Vhi4 + headoff);
    const char* vl_g = (const char*)((const ushortx*)g_Vlo4 + headoff);
    const int nkt = q0 / 64 + 2;

    // stage K/V tile kt into buffer base (each thread: 8 cp.async)
    auto stage_kv = [&](uint32_t base, int kt) {
        const long tb = (long)kt * 64 * HD * 2;
        const char* srcs[4] = {kh_g + tb, kl_g + tb, vh_g + tb, vl_g + tb};
        #pragma unroll
        for (int arr = 0; arr < 4; arr++) {
            #pragma unroll
            for (int i = 0; i < 2; i++) {
                const int u = i * 256 + tid;   // 0..511
                const int r = u >> 3, seg = u & 7;
                cpa16(base + arr * KVARR + r * AROW + seg * 16,
                      srcs[arr] + r * 128 + seg * 16);
            }
        }
    };

    stage_kv(sb, 0);
    CPA_COMMIT();

    for (int kt = 0; kt < nkt; kt++) {
        const int k0 = kt * 64;
        if (kt + 1 < nkt) {
            stage_kv(sb + ((kt + 1) & 1) * KVSTAGE, kt + 1);
            CPA_COMMIT();
            CPA_WAIT(1);
        } else {
            CPA_WAIT(0);
        }
        __syncthreads();

        const uint32_t Khi = sb + (kt & 1) * KVSTAGE;
        const uint32_t Klo = Khi + KVARR;
        const uint32_t Vhi = Khi + 2 * KVARR;
        const uint32_t Vlo = Khi + 3 * KVARR;

        // ---- scores S = Q K^T (3-MMA split), 8 n-frags of 8 keys
        float sc[8][4];
        #pragma unroll
        for (int nf = 0; nf < 8; nf++) {
            sc[nf][0] = sc[nf][1] = sc[nf][2] = sc[nf][3] = 0.f;
            const uint32_t rowk = nf * 8 + (lane & 7);
            const uint32_t colp = ((lane >> 3) & 1) * 16;
            #pragma unroll
            for (int ks = 0; ks < 4; ks++) {
                uint32_t bh_[2], bl_[2];
                ldm_x2(bh_, Khi + rowk * AROW + ks * 32 + colp);
                ldm_x2(bl_, Klo + rowk * AROW + ks * 32 + colp);
                mma16816(sc[nf], qh[ks], bh_);
                mma16816(sc[nf], qh[ks], bl_);
                mma16816(sc[nf], ql[ks], bh_);
            }
        }

        // ---- causal mask (only the last two tiles can clip)
        if (kt >= nkt - 2) {
            #pragma unroll
            for (int nf = 0; nf < 8; nf++) {
                const int col = k0 + nf * 8 + tm4 * 2;
                if (col     > qrow0)     sc[nf][0] = -1e30f;
                if (col + 1 > qrow0)     sc[nf][1] = -1e30f;
                if (col     > qrow0 + 8) sc[nf][2] = -1e30f;
                if (col + 1 > qrow0 + 8) sc[nf][3] = -1e30f;
            }
        }

        // ---- online softmax (rows t4 and t4+8 within warp)
        float mx0 = sc[0][0], mx1 = sc[0][2];
        #pragma unroll
        for (int nf = 0; nf < 8; nf++) {
            mx0 = fmaxf(mx0, fmaxf(sc[nf][0], sc[nf][1]));
            mx1 = fmaxf(mx1, fmaxf(sc[nf][2], sc[nf][3]));
        }
        mx0 = fmaxf(mx0, __shfl_xor_sync(0xFFFFFFFF, mx0, 1));
        mx0 = fmaxf(mx0, __shfl_xor_sync(0xFFFFFFFF, mx0, 2));
        mx1 = fmaxf(mx1, __shfl_xor_sync(0xFFFFFFFF, mx1, 1));
        mx1 = fmaxf(mx1, __shfl_xor_sync(0xFFFFFFFF, mx1, 2));
        const float mn0 = fmaxf(m0, mx0), mn1 = fmaxf(m1, mx1);
        const float c0 = __expf(m0 - mn0), c1 = __expf(m1 - mn1);
        m0 = mn0; m1 = mn1;
        float ps0 = 0.f, ps1 = 0.f;
        #pragma unroll
        for (int nf = 0; nf < 8; nf++) {
            sc[nf][0] = __expf(sc[nf][0] - mn0); ps0 += sc[nf][0];
            sc[nf][1] = __expf(sc[nf][1] - mn0); ps0 += sc[nf][1];
            sc[nf][2] = __expf(sc[nf][2] - mn1); ps1 += sc[nf][2];
            sc[nf][3] = __expf(sc[nf][3] - mn1); ps1 += sc[nf][3];
        }
        ps0 += __shfl_xor_sync(0xFFFFFFFF, ps0, 1);
        ps0 += __shfl_xor_sync(0xFFFFFFFF, ps0, 2);
        ps1 += __shfl_xor_sync(0xFFFFFFFF, ps1, 1);
        ps1 += __shfl_xor_sync(0xFFFFFFFF, ps1, 2);
        lsum0 = lsum0 * c0 + ps0;
        lsum1 = lsum1 * c1 + ps1;
        #pragma unroll
        for (int nf = 0; nf < 8; nf++) {
            O[nf][0] *= c0; O[nf][1] *= c0;
            O[nf][2] *= c1; O[nf][3] *= c1;
        }

        // ---- pack P as A-frags (hi/lo) directly from score c-frags
        uint32_t ph[4][4], pl[4][4];
        #pragma unroll
        for (int j = 0; j < 4; j++) {
            split2(sc[2*j    ][0], sc[2*j    ][1], ph[j][0], pl[j][0]);
            split2(sc[2*j    ][2], sc[2*j    ][3], ph[j][1], pl[j][1]);
            split2(sc[2*j + 1][0], sc[2*j + 1][1], ph[j][2], pl[j][2]);
            split2(sc[2*j + 1][2], sc[2*j + 1][3], ph[j][3], pl[j][3]);
        }

        // ---- O += P V (3-MMA split); V^T B-frags via ldmatrix.trans
        #pragma unroll
        for (int nfd = 0; nfd < 8; nfd++) {
            #pragma unroll
            for (int ks = 0; ks < 4; ks++) {
                uint32_t bvh[2], bvl[2];
                const uint32_t rowv = ks * 16 + (lane & 15);
                ldm_x2t(bvh, Vhi + rowv * AROW + nfd * 16);
                ldm_x2t(bvl, Vlo + rowv * AROW + nfd * 16);
                mma16816(O[nfd], ph[ks], bvh);
                mma16816(O[nfd], ph[ks], bvl);
                mma16816(O[nfd], pl[ks], bvh);
            }
        }
        __syncthreads();   // all warps done with this buffer before restaging
    }

    // ---- finalize: O /= l, write bf16 hi/lo in [B,S,E] merged-head layout
    const float i0 = 1.f / lsum0, i1 = 1.f / lsum1;
    const int b = bh >> 4, h = bh & 15;
    uint32_t* Ohi = (uint32_t*)g_Ohi4;
    uint32_t* Olo = (uint32_t*)g_Olo4;
    const long base0 = ((long)(b * SQ + qrow0)) * EMB + h * HD;
    const long base1 = base0 + 8L * EMB;
    #pragma unroll
    for (int nfd = 0; nfd < 8; nfd++) {
        const int col = nfd * 8 + tm4 * 2;
        uint32_t hh, ll;
        split2(O[nfd][0] * i0, O[nfd][1] * i0, hh, ll);
        Ohi[(base0 + col) >> 1] = hh;
        Olo[(base0 + col) >> 1] = ll;
        split2(O[nfd][2] * i1, O[nfd][3] * i1, hh, ll);
        Ohi[(base1 + col) >> 1] = hh;
        Olo[(base1 + col) >> 1] = ll;
    }
}

// ---------------------------------------------------------------------------
extern "C" void kernel_launch(void* const* d_in, const int* in_sizes, int n_in,
                              void* d_out, int out_size)
{
    const float* x      = (const float*)d_in[0];
    const float* W_attn = (const float*)d_in[1];
    const float* b_attn = (const float*)d_in[2];
    const float* W_proj = (const float*)d_in[3];
    const float* b_proj = (const float*)d_in[4];
    float* out = (float*)d_out;

    const int DSM = 2 * STAGEB;          // 110592
    const int ASM_SZ = 2 * KVSTAGE;      // 73728
    cudaFuncSetAttribute(k_gemm_qkv,  cudaFuncAttributeMaxDynamicSharedMemorySize, DSM);
    cudaFuncSetAttribute(k_gemm_proj, cudaFuncAttributeMaxDynamicSharedMemorySize, DSM);
    cudaFuncSetAttribute(k_attn_mma,  cudaFuncAttributeMaxDynamicSharedMemorySize, ASM_SZ);

    uint4 *xhi, *xlo, *wahi, *walo, *wphi, *wplo;
    cudaGetSymbolAddress((void**)&xhi,  g_Xhi4);
    cudaGetSymbolAddress((void**)&xlo,  g_Xlo4);
    cudaGetSymbolAddress((void**)&wahi, g_WaThi4);
    cudaGetSymbolAddress((void**)&walo, g_WaTlo4);
    cudaGetSymbolAddress((void**)&wphi, g_WpThi4);
    cudaGetSymbolAddress((void**)&wplo, g_WpTlo4);

    k_cvt<<<4096, 256>>>((const float4*)x, (uint2*)xhi, (uint2*)xlo, 4096 * 1024 / 4);
    k_wT<<<dim3(96, 32), dim3(32, 8)>>>(W_attn, 3072, (ushortx*)wahi, (ushortx*)walo);
    k_wT<<<dim3(32, 32), dim3(32, 8)>>>(W_proj, 1024, (ushortx*)wphi, (ushortx*)wplo);
    k_gemm_qkv<<<dim3(24, 64), 128, DSM>>>(b_attn);
    k_attn_mma<<<dim3(8, 64), 256, ASM_SZ>>>();
    k_gemm_proj<<<dim3(8, 64), 128, DSM>>>(b_proj, out);
}

// round 13
// speedup vs baseline: 1.1763x; 1.0003x over previous
#include <cuda_runtime.h>
#include <cuda_bf16.h>
#include <math.h>
#include <cstdint>

#define BSZ 4
#define SQ  1024
#define EMB 1024
#define NH  16
#define HD  64

typedef unsigned long long u64;
typedef unsigned short ushortx;

// ---------------------------------------------------------------------------
// Scratch (__device__ globals; allocation-free)
// Q/K/V live ONLY as bf16 hi/lo ([B,H,S,D]); O as bf16 hi/lo ([B,S,E]).
// ---------------------------------------------------------------------------
__device__ uint4 g_Qhi4[BSZ*NH*SQ*HD*2/16];
__device__ uint4 g_Qlo4[BSZ*NH*SQ*HD*2/16];
__device__ uint4 g_Khi4[BSZ*NH*SQ*HD*2/16];
__device__ uint4 g_Klo4[BSZ*NH*SQ*HD*2/16];
__device__ uint4 g_Vhi4[BSZ*NH*SQ*HD*2/16];
__device__ uint4 g_Vlo4[BSZ*NH*SQ*HD*2/16];

__device__ uint4 g_Xhi4[4096*1024*2/16];
__device__ uint4 g_Xlo4[4096*1024*2/16];
__device__ uint4 g_Ohi4[4096*1024*2/16];
__device__ uint4 g_Olo4[4096*1024*2/16];
__device__ uint4 g_WaThi4[3072*1024*2/16];   // W_attn^T [3072][1024]
__device__ uint4 g_WaTlo4[3072*1024*2/16];
__device__ uint4 g_WpThi4[1024*1024*2/16];   // W_proj^T [1024][1024]
__device__ uint4 g_WpTlo4[1024*1024*2/16];

// ---------------------------------------------------------------------------
// helpers
// ---------------------------------------------------------------------------
__device__ __forceinline__ uint32_t smem_u32(const void* p) {
    uint32_t a;
    asm("{ .reg .u64 t; cvta.to.shared.u64 t, %1; cvt.u32.u64 %0, t; }" : "=r"(a) : "l"(p));
    return a;
}
__device__ __forceinline__ void cpa16(uint32_t dst, const void* src) {
    asm volatile("cp.async.cg.shared.global [%0], [%1], 16;"
                 :: "r"(dst), "l"(__cvta_generic_to_global(src)) : "memory");
}
#define CPA_COMMIT() asm volatile("cp.async.commit_group;" ::: "memory")
#define CPA_WAIT(n)  asm volatile("cp.async.wait_group %0;" :: "n"(n) : "memory")

__device__ __forceinline__ uint32_t lds32(uint32_t addr) {
    uint32_t v; asm volatile("ld.shared.b32 %0,[%1];" : "=r"(v) : "r"(addr)); return v;
}
// m16n8k16 bf16 MMA, fp32 accumulate
__device__ __forceinline__ void mma16816(float* c, const uint32_t* a, const uint32_t* b) {
    asm volatile("mma.sync.aligned.m16n8k16.row.col.f32.bf16.bf16.f32 "
        "{%0,%1,%2,%3}, {%4,%5,%6,%7}, {%8,%9}, {%0,%1,%2,%3};"
        : "+f"(c[0]), "+f"(c[1]), "+f"(c[2]), "+f"(c[3])
        : "r"(a[0]), "r"(a[1]), "r"(a[2]), "r"(a[3]), "r"(b[0]), "r"(b[1]));
}
__device__ __forceinline__ void ldm_x4(uint32_t* r, uint32_t addr) {
    asm volatile("ldmatrix.sync.aligned.m8n8.x4.shared.b16 {%0,%1,%2,%3}, [%4];"
        : "=r"(r[0]), "=r"(r[1]), "=r"(r[2]), "=r"(r[3]) : "r"(addr));
}
__device__ __forceinline__ void ldm_x2(uint32_t* r, uint32_t addr) {
    asm volatile("ldmatrix.sync.aligned.m8n8.x2.shared.b16 {%0,%1}, [%2];"
        : "=r"(r[0]), "=r"(r[1]) : "r"(addr));
}
__device__ __forceinline__ void ldm_x2t(uint32_t* r, uint32_t addr) {
    asm volatile("ldmatrix.sync.aligned.m8n8.x2.trans.shared.b16 {%0,%1}, [%2];"
        : "=r"(r[0]), "=r"(r[1]) : "r"(addr));
}
// two f32 -> packed bf16x2 hi + residual lo
__device__ __forceinline__ void split2(float x, float y, uint32_t& h, uint32_t& l) {
    __nv_bfloat16 hx = __float2bfloat16_rn(x);
    __nv_bfloat16 hy = __float2bfloat16_rn(y);
    float rx = x - __bfloat162float(hx);
    float ry = y - __bfloat162float(hy);
    __nv_bfloat16 lx = __float2bfloat16_rn(rx);
    __nv_bfloat16 ly = __float2bfloat16_rn(ry);
    h = (uint32_t)__bfloat16_as_ushort(hx) | ((uint32_t)__bfloat16_as_ushort(hy) << 16);
    l = (uint32_t)__bfloat16_as_ushort(lx) | ((uint32_t)__bfloat16_as_ushort(ly) << 16);
}

// ---------------------------------------------------------------------------
// GEMM geometry (R11, proven): 64x128 block, BK=64, 4 warps (2m x 2n),
// warp tile 32x64, scalar lds32 fill, wait(1)->sync->compute->sync,
// double buffer, 2 CTAs/SM of 128 threads.
// R13: split-MMA passes separated across independent accumulators.
// ---------------------------------------------------------------------------
#define ROWB   144
#define AARRB  (64*ROWB)               // 9216
#define BARRB  (128*ROWB)              // 18432
#define STAGEB (2*AARRB + 2*BARRB)     // 55296
#define NCHUNK 16                      // 1024 / 64

__device__ __forceinline__ void load_chunk(
    uint32_t st, const ushortx* A0, const ushortx* A1,
    const ushortx* B0, const ushortx* B1, int k0, int tid)
{
    // A hi/lo: 64 rows x 8 segs
    #pragma unroll
    for (int i = 0; i < 4; i++) {
        const int u = i * 128 + tid;      // 0..511
        const int r = u >> 3, c16 = u & 7;
        cpa16(st + r * ROWB + c16 * 16,
              (const char*)(A0 + r * 1024 + k0) + c16 * 16);
        cpa16(st + AARRB + r * ROWB + c16 * 16,
              (const char*)(A1 + r * 1024 + k0) + c16 * 16);
    }
    // B hi/lo: 128 rows x 8 segs
    #pragma unroll
    for (int i = 0; i < 8; i++) {
        const int u = i * 128 + tid;      // 0..1023
        const int r = u >> 3, c16 = u & 7;
        cpa16(st + 2 * AARRB + r * ROWB + c16 * 16,
              (const char*)(B0 + r * 1024 + k0) + c16 * 16);
        cpa16(st + 2 * AARRB + BARRB + r * ROWB + c16 * 16,
              (const char*)(B1 + r * 1024 + k0) + c16 * 16);
    }
}

__device__ __forceinline__ void compute_chunk(
    uint32_t st, int wm, int wn, int t4, int tm4, float acc[2][8][4])
{
    #pragma unroll
    for (int ks = 0; ks < 4; ks++) {
        const int kb = ks * 32 + tm4 * 4;     // byte offset of this thread's k pair
        uint32_t Ahi[2][4], Alo[2][4], Bhi[8][2], Blo[8][2];
        #pragma unroll
        for (int mf = 0; mf < 2; mf++) {
            const uint32_t ra = st + (wm * 32 + mf * 16 + t4) * ROWB + kb;
            Ahi[mf][0] = lds32(ra);
            Ahi[mf][1] = lds32(ra + 8 * ROWB);
            Ahi[mf][2] = lds32(ra + 16);
            Ahi[mf][3] = lds32(ra + 8 * ROWB + 16);
            Alo[mf][0] = lds32(ra + AARRB);
            Alo[mf][1] = lds32(ra + AARRB + 8 * ROWB);
            Alo[mf][2] = lds32(ra + AARRB + 16);
            Alo[mf][3] = lds32(ra + AARRB + 8 * ROWB + 16);
        }
        #pragma unroll
        for (int nf = 0; nf < 8; nf++) {
            const uint32_t rb = st + 2 * AARRB + (wn * 64 + nf * 8 + t4) * ROWB + kb;
            Bhi[nf][0] = lds32(rb);
            Bhi[nf][1] = lds32(rb + 16);
            Blo[nf][0] = lds32(rb + BARRB);
            Blo[nf][1] = lds32(rb + BARRB + 16);
        }
        // 3 split passes, each sweeping 16 independent accumulators
        #pragma unroll
        for (int mf = 0; mf < 2; mf++)
            #pragma unroll
            for (int nf = 0; nf < 8; nf++)
                mma16816(acc[mf][nf], Ahi[mf], Bhi[nf]);
        #pragma unroll
        for (int mf = 0; mf < 2; mf++)
            #pragma unroll
            for (int nf = 0; nf < 8; nf++)
                mma16816(acc[mf][nf], Ahi[mf], Blo[nf]);
        #pragma unroll
        for (int mf = 0; mf < 2; mf++)
            #pragma unroll
            for (int nf = 0; nf < 8; nf++)
                mma16816(acc[mf][nf], Alo[mf], Bhi[nf]);
    }
}

__device__ __forceinline__ void gemm_mainloop(
    uint32_t sm, const ushortx* A0, const ushortx* A1,
    const ushortx* B0, const ushortx* B1,
    int wm, int wn, int t4, int tm4, int tid, float acc[2][8][4])
{
    #pragma unroll
    for (int mf = 0; mf < 2; mf++)
        #pragma unroll
        for (int nf = 0; nf < 8; nf++)
            #pragma unroll
            for (int j = 0; j < 4; j++) acc[mf][nf][j] = 0.f;

    load_chunk(sm, A0, A1, B0, B1, 0, tid);
    CPA_COMMIT();
    for (int c = 0; c < NCHUNK; c++) {
        if (c + 1 < NCHUNK) {
            load_chunk(sm + ((c + 1) & 1) * STAGEB, A0, A1, B0, B1, (c + 1) * 64, tid);
            CPA_COMMIT();
            CPA_WAIT(1);
        } else {
            CPA_WAIT(0);
        }
        __syncthreads();
        compute_chunk(sm + (c & 1) * STAGEB, wm, wn, t4, tm4, acc);
        __syncthreads();
    }
}

// ---------------------------------------------------------------------------
// QKV GEMM: X @ W_attn + b_attn -> bf16 hi/lo Q (x0.125) / K / V  [B,H,S,D]
// grid (24, 64)
// ---------------------------------------------------------------------------
__global__ __launch_bounds__(128, 2) void k_gemm_qkv(const float* __restrict__ bias)
{
    extern __shared__ __align__(16) char dsm[];
    const int tid = threadIdx.x, wid = tid >> 5, lane = tid & 31;
    const int t4 = lane >> 2, tm4 = lane & 3;
    const int wm = wid >> 1, wn = wid & 1;
    const int bn = blockIdx.x * 128, bm = blockIdx.y * 64;
    const uint32_t sm = smem_u32(dsm);

    float acc[2][8][4];
    gemm_mainloop(sm,
        (const ushortx*)g_Xhi4 + (long)bm * 1024, (const ushortx*)g_Xlo4 + (long)bm * 1024,
        (const ushortx*)g_WaThi4 + (long)bn * 1024, (const ushortx*)g_WaTlo4 + (long)bn * 1024,
        wm, wn, t4, tm4, tid, acc);

    const int which = bn >> 10;             // 0=Q 1=K 2=V
    uint32_t* dhi = (which == 0) ? (uint32_t*)g_Qhi4 : (which == 1) ? (uint32_t*)g_Khi4 : (uint32_t*)g_Vhi4;
    uint32_t* dlo = (which == 0) ? (uint32_t*)g_Qlo4 : (which == 1) ? (uint32_t*)g_Klo4 : (uint32_t*)g_Vlo4;
    const float scale = (which == 0) ? 0.125f : 1.f;

    #pragma unroll
    for (int mf = 0; mf < 2; mf++) {
        #pragma unroll
        for (int nf = 0; nf < 8; nf++) {
            const int n_g = bn + wn * 64 + nf * 8 + tm4 * 2;
            const int e = n_g & 1023, h = e >> 6, d = e & 63;
            const float b0 = __ldg(&bias[n_g]), b1 = __ldg(&bias[n_g + 1]);
            #pragma unroll
            for (int rr = 0; rr < 2; rr++) {
                const int row = bm + wm * 32 + mf * 16 + t4 + rr * 8;
                const int b = row >> 10, s = row & 1023;
                const long off = (((long)(b * NH + h) * SQ) + s) * HD + d;
                uint32_t hh, ll;
                split2((acc[mf][nf][rr * 2 + 0] + b0) * scale,
                       (acc[mf][nf][rr * 2 + 1] + b1) * scale, hh, ll);
                dhi[off >> 1] = hh;
                dlo[off >> 1] = ll;
            }
        }
    }
}

// ---------------------------------------------------------------------------
// Proj GEMM: Obf16 @ W_proj + b_proj -> out.  grid (8, 64)
// ---------------------------------------------------------------------------
__global__ __launch_bounds__(128, 2) void k_gemm_proj(const float* __restrict__ bias,
                                                      float* __restrict__ out)
{
    extern __shared__ __align__(16) char dsm[];
    const int tid = threadIdx.x, wid = tid >> 5, lane = tid & 31;
    const int t4 = lane >> 2, tm4 = lane & 3;
    const int wm = wid >> 1, wn = wid & 1;
    const int bn = blockIdx.x * 128, bm = blockIdx.y * 64;
    const uint32_t sm = smem_u32(dsm);

    float acc[2][8][4];
    gemm_mainloop(sm,
        (const ushortx*)g_Ohi4 + (long)bm * 1024, (const ushortx*)g_Olo4 + (long)bm * 1024,
        (const ushortx*)g_WpThi4 + (long)bn * 1024, (const ushortx*)g_WpTlo4 + (long)bn * 1024,
        wm, wn, t4, tm4, tid, acc);

    #pragma unroll
    for (int mf = 0; mf < 2; mf++) {
        #pragma unroll
        for (int nf = 0; nf < 8; nf++) {
            const int n_g = bn + wn * 64 + nf * 8 + tm4 * 2;
            const float b0 = __ldg(&bias[n_g]), b1 = __ldg(&bias[n_g + 1]);
            #pragma unroll
            for (int rr = 0; rr < 2; rr++) {
                const int row = bm + wm * 32 + mf * 16 + t4 + rr * 8;
                float2 v = make_float2(acc[mf][nf][rr * 2 + 0] + b0,
                                       acc[mf][nf][rr * 2 + 1] + b1);
                *(float2*)&out[(long)row * EMB + n_g] = v;
            }
        }
    }
}

// ---------------------------------------------------------------------------
// Elementwise f32 -> bf16 hi/lo split
// ---------------------------------------------------------------------------
__global__ __launch_bounds__(256) void k_cvt(const float4* __restrict__ src,
                                             uint2* __restrict__ hi, uint2* __restrict__ lo, int n4)
{
    int i = blockIdx.x * 256 + threadIdx.x;
    if (i >= n4) return;
    float4 v = src[i];
    uint32_t h0, h1, l0, l1;
    split2(v.x, v.y, h0, l0);
    split2(v.z, v.w, h1, l1);
    hi[i] = make_uint2(h0, h1);
    lo[i] = make_uint2(l0, l1);
}

// ---------------------------------------------------------------------------
// Transpose-convert: W [1024, ncols] f32 -> W^T hi/lo [ncols, 1024] bf16
// ---------------------------------------------------------------------------
__global__ __launch_bounds__(256) void k_wT(const float* __restrict__ W, int ncols,
                                            ushortx* __restrict__ hiT,
                                            ushortx* __restrict__ loT)
{
    __shared__ float t[32][33];
    const int tx = threadIdx.x, ty = threadIdx.y;
    const int n0 = blockIdx.x * 32, k0 = blockIdx.y * 32;
    #pragma unroll
    for (int i = 0; i < 4; i++)
        t[ty + i * 8][tx] = W[(k0 + ty + i * 8) * ncols + n0 + tx];
    __syncthreads();
    #pragma unroll
    for (int i = 0; i < 4; i++) {
        const int r = ty + i * 8;
        float v = t[tx][r];
        __nv_bfloat16 bh = __float2bfloat16_rn(v);
        float rr = v - __bfloat162float(bh);
        __nv_bfloat16 bl = __float2bfloat16_rn(rr);
        const int off = (n0 + r) * 1024 + k0 + tx;
        hiT[off] = __bfloat16_as_ushort(bh);
        loT[off] = __bfloat16_as_ushort(bl);
    }
}

// ---------------------------------------------------------------------------
// HMMA causal flash attention — bf16-native I/O + double-buffered K/V staging.
// Block: 128 q-rows x 1 head. 8 warps x 16 q-rows. 64-key tiles.
// R13: QK and PV loops restructured as ks-outer with 3 independent-acc passes.
// ---------------------------------------------------------------------------
#define AROW     144
#define KVARR    (64*AROW)      // 9216
#define KVSTAGE  (4*KVARR)      // 36864

__global__ __launch_bounds__(256, 1) void k_attn_mma()
{
    extern __shared__ char smb[];
    const uint32_t sb = smem_u32(smb);
    const int tid = threadIdx.x, lane = tid & 31, w = tid >> 5;
    const int t4 = lane >> 2, tm4 = lane & 3;
    const int bh = blockIdx.y;
    const int q0 = ((int)gridDim.x - 1 - (int)blockIdx.x) * 128;  // heavy blocks first

    const long headoff = (long)bh * SQ * HD;

    // ---- stage Q hi/lo via cp.async (uses stage-0 area; 128 rows x 128B x2)
    {
        const char* qh_g = (const char*)((const ushortx*)g_Qhi4 + headoff + (long)q0 * HD);
        const char* ql_g = (const char*)((const ushortx*)g_Qlo4 + headoff + (long)q0 * HD);
        #pragma unroll
        for (int i = 0; i < 4; i++) {
            const int u = i * 256 + tid;        // 0..1023
            const int r = u >> 3, seg = u & 7;
            cpa16(sb + r * AROW + seg * 16, qh_g + r * 128 + seg * 16);
            cpa16(sb + 128 * AROW + r * AROW + seg * 16, ql_g + r * 128 + seg * 16);
        }
        CPA_COMMIT();
        CPA_WAIT(0);
        __syncthreads();
    }

    // ---- Q fragments (A, m16k16 x4 k-steps), kept in regs for whole kernel
    uint32_t qh[4][4], ql[4][4];
    {
        const uint32_t rowq = w * 16 + (lane & 15);
        #pragma unroll
        for (int ks = 0; ks < 4; ks++) {
            const uint32_t col = ks * 32 + ((lane >> 4) << 4);
            ldm_x4(qh[ks], sb + rowq * AROW + col);
            ldm_x4(ql[ks], sb + 128 * AROW + rowq * AROW + col);
        }
    }
    __syncthreads();   // all warps done reading Q smem; buffers reusable

    float O[8][4];
    #pragma unroll
    for (int i = 0; i < 8; i++)
        #pragma unroll
        for (int j = 0; j < 4; j++) O[i][j] = 0.f;
    float m0 = -INFINITY, m1 = -INFINITY, lsum0 = 0.f, lsum1 = 0.f;
    const int qrow0 = q0 + w * 16 + t4;

    const char* kh_g = (const char*)((const ushortx*)g_Khi4 + headoff);
    const char* kl_g = (const char*)((const ushortx*)g_Klo4 + headoff);
    const char* vh_g = (const char*)((const ushortx*)g_Vhi4 + headoff);
    const char* vl_g = (const char*)((const ushortx*)g_Vlo4 + headoff);
    const int nkt = q0 / 64 + 2;

    // stage K/V tile kt into buffer base (each thread: 8 cp.async)
    auto stage_kv = [&](uint32_t base, int kt) {
        const long tb = (long)kt * 64 * HD * 2;
        const char* srcs[4] = {kh_g + tb, kl_g + tb, vh_g + tb, vl_g + tb};
        #pragma unroll
        for (int arr = 0; arr < 4; arr++) {
            #pragma unroll
            for (int i = 0; i < 2; i++) {
                const int u = i * 256 + tid;   // 0..511
                const int r = u >> 3, seg = u & 7;
                cpa16(base + arr * KVARR + r * AROW + seg * 16,
                      srcs[arr] + r * 128 + seg * 16);
            }
        }
    };

    stage_kv(sb, 0);
    CPA_COMMIT();

    for (int kt = 0; kt < nkt; kt++) {
        const int k0 = kt * 64;
        if (kt + 1 < nkt) {
            stage_kv(sb + ((kt + 1) & 1) * KVSTAGE, kt + 1);
            CPA_COMMIT();
            CPA_WAIT(1);
        } else {
            CPA_WAIT(0);
        }
        __syncthreads();

        const uint32_t Khi = sb + (kt & 1) * KVSTAGE;
        const uint32_t Klo = Khi + KVARR;
        const uint32_t Vhi = Khi + 2 * KVARR;
        const uint32_t Vlo = Khi + 3 * KVARR;

        // ---- scores S = Q K^T: ks-outer, frags hoisted, 3 passes x 8 indep accs
        float sc[8][4];
        #pragma unroll
        for (int nf = 0; nf < 8; nf++)
            sc[nf][0] = sc[nf][1] = sc[nf][2] = sc[nf][3] = 0.f;
        {
            const uint32_t rowkb = (lane & 7);
            const uint32_t colp = ((lane >> 3) & 1) * 16;
            #pragma unroll
            for (int ks = 0; ks < 4; ks++) {
                uint32_t kbh[8][2], kbl[8][2];
                #pragma unroll
                for (int nf = 0; nf < 8; nf++) {
                    ldm_x2(kbh[nf], Khi + (nf * 8 + rowkb) * AROW + ks * 32 + colp);
                    ldm_x2(kbl[nf], Klo + (nf * 8 + rowkb) * AROW + ks * 32 + colp);
                }
                #pragma unroll
                for (int nf = 0; nf < 8; nf++) mma16816(sc[nf], qh[ks], kbh[nf]);
                #pragma unroll
                for (int nf = 0; nf < 8; nf++) mma16816(sc[nf], qh[ks], kbl[nf]);
                #pragma unroll
                for (int nf = 0; nf < 8; nf++) mma16816(sc[nf], ql[ks], kbh[nf]);
            }
        }

        // ---- causal mask (only the last two tiles can clip)
        if (kt >= nkt - 2) {
            #pragma unroll
            for (int nf = 0; nf < 8; nf++) {
                const int col = k0 + nf * 8 + tm4 * 2;
                if (col     > qrow0)     sc[nf][0] = -1e30f;
                if (col + 1 > qrow0)     sc[nf][1] = -1e30f;
                if (col     > qrow0 + 8) sc[nf][2] = -1e30f;
                if (col + 1 > qrow0 + 8) sc[nf][3] = -1e30f;
            }
        }

        // ---- online softmax (rows t4 and t4+8 within warp)
        float mx0 = sc[0][0], mx1 = sc[0][2];
        #pragma unroll
        for (int nf = 0; nf < 8; nf++) {
            mx0 = fmaxf(mx0, fmaxf(sc[nf][0], sc[nf][1]));
            mx1 = fmaxf(mx1, fmaxf(sc[nf][2], sc[nf][3]));
        }
        mx0 = fmaxf(mx0, __shfl_xor_sync(0xFFFFFFFF, mx0, 1));
        mx0 = fmaxf(mx0, __shfl_xor_sync(0xFFFFFFFF, mx0, 2));
        mx1 = fmaxf(mx1, __shfl_xor_sync(0xFFFFFFFF, mx1, 1));
        mx1 = fmaxf(mx1, __shfl_xor_sync(0xFFFFFFFF, mx1, 2));
        const float mn0 = fmaxf(m0, mx0), mn1 = fmaxf(m1, mx1);
        const float c0 = __expf(m0 - mn0), c1 = __expf(m1 - mn1);
        m0 = mn0; m1 = mn1;
        float ps0 = 0.f, ps1 = 0.f;
        #pragma unroll
        for (int nf = 0; nf < 8; nf++) {
            sc[nf][0] = __expf(sc[nf][0] - mn0); ps0 += sc[nf][0];
            sc[nf][1] = __expf(sc[nf][1] - mn0); ps0 += sc[nf][1];
            sc[nf][2] = __expf(sc[nf][2] - mn1); ps1 += sc[nf][2];
            sc[nf][3] = __expf(sc[nf][3] - mn1); ps1 += sc[nf][3];
        }
        ps0 += __shfl_xor_sync(0xFFFFFFFF, ps0, 1);
        ps0 += __shfl_xor_sync(0xFFFFFFFF, ps0, 2);
        ps1 += __shfl_xor_sync(0xFFFFFFFF, ps1, 1);
        ps1 += __shfl_xor_sync(0xFFFFFFFF, ps1, 2);
        lsum0 = lsum0 * c0 + ps0;
        lsum1 = lsum1 * c1 + ps1;
        #pragma unroll
        for (int nf = 0; nf < 8; nf++) {
            O[nf][0] *= c0; O[nf][1] *= c0;
            O[nf][2] *= c1; O[nf][3] *= c1;
        }

        // ---- pack P as A-frags (hi/lo) directly from score c-frags
        uint32_t ph[4][4], pl[4][4];
        #pragma unroll
        for (int j = 0; j < 4; j++) {
            split2(sc[2*j    ][0], sc[2*j    ][1], ph[j][0], pl[j][0]);
            split2(sc[2*j    ][2], sc[2*j    ][3], ph[j][1], pl[j][1]);
            split2(sc[2*j + 1][0], sc[2*j + 1][1], ph[j][2], pl[j][2]);
            split2(sc[2*j + 1][2], sc[2*j + 1][3], ph[j][3], pl[j][3]);
        }

        // ---- O += P V: ks-outer, V^T frags hoisted, 3 passes x 8 indep accs
        {
            const uint32_t rowvb = (lane & 15);
            #pragma unroll
            for (int ks = 0; ks < 4; ks++) {
                uint32_t vbh[8][2], vbl[8][2];
                #pragma unroll
                for (int nfd = 0; nfd < 8; nfd++) {
                    ldm_x2t(vbh[nfd], Vhi + (ks * 16 + rowvb) * AROW + nfd * 16);
                    ldm_x2t(vbl[nfd], Vlo + (ks * 16 + rowvb) * AROW + nfd * 16);
                }
                #pragma unroll
                for (int nfd = 0; nfd < 8; nfd++) mma16816(O[nfd], ph[ks], vbh[nfd]);
                #pragma unroll
                for (int nfd = 0; nfd < 8; nfd++) mma16816(O[nfd], ph[ks], vbl[nfd]);
                #pragma unroll
                for (int nfd = 0; nfd < 8; nfd++) mma16816(O[nfd], pl[ks], vbh[nfd]);
            }
        }
        __syncthreads();   // all warps done with this buffer before restaging
    }

    // ---- finalize: O /= l, write bf16 hi/lo in [B,S,E] merged-head layout
    const float i0 = 1.f / lsum0, i1 = 1.f / lsum1;
    const int b = bh >> 4, h = bh & 15;
    uint32_t* Ohi = (uint32_t*)g_Ohi4;
    uint32_t* Olo = (uint32_t*)g_Olo4;
    const long base0 = ((long)(b * SQ + qrow0)) * EMB + h * HD;
    const long base1 = base0 + 8L * EMB;
    #pragma unroll
    for (int nfd = 0; nfd < 8; nfd++) {
        const int col = nfd * 8 + tm4 * 2;
        uint32_t hh, ll;
        split2(O[nfd][0] * i0, O[nfd][1] * i0, hh, ll);
        Ohi[(base0 + col) >> 1] = hh;
        Olo[(base0 + col) >> 1] = ll;
        split2(O[nfd][2] * i1, O[nfd][3] * i1, hh, ll);
        Ohi[(base1 + col) >> 1] = hh;
        Olo[(base1 + col) >> 1] = ll;
    }
}

// ---------------------------------------------------------------------------
extern "C" void kernel_launch(void* const* d_in, const int* in_sizes, int n_in,
                              void* d_out, int out_size)
{
    const float* x      = (const float*)d_in[0];
    const float* W_attn = (const float*)d_in[1];
    const float* b_attn = (const float*)d_in[2];
    const float* W_proj = (const float*)d_in[3];
    const float* b_proj = (const float*)d_in[4];
    float* out = (float*)d_out;

    const int DSM = 2 * STAGEB;          // 110592
    const int ASM_SZ = 2 * KVSTAGE;      // 73728
    cudaFuncSetAttribute(k_gemm_qkv,  cudaFuncAttributeMaxDynamicSharedMemorySize, DSM);
    cudaFuncSetAttribute(k_gemm_proj, cudaFuncAttributeMaxDynamicSharedMemorySize, DSM);
    cudaFuncSetAttribute(k_attn_mma,  cudaFuncAttributeMaxDynamicSharedMemorySize, ASM_SZ);

    uint4 *xhi, *xlo, *wahi, *walo, *wphi, *wplo;
    cudaGetSymbolAddress((void**)&xhi,  g_Xhi4);
    cudaGetSymbolAddress((void**)&xlo,  g_Xlo4);
    cudaGetSymbolAddress((void**)&wahi, g_WaThi4);
    cudaGetSymbolAddress((void**)&walo, g_WaTlo4);
    cudaGetSymbolAddress((void**)&wphi, g_WpThi4);
    cudaGetSymbolAddress((void**)&wplo, g_WpTlo4);

    k_cvt<<<4096, 256>>>((const float4*)x, (uint2*)xhi, (uint2*)xlo, 4096 * 1024 / 4);
    k_wT<<<dim3(96, 32), dim3(32, 8)>>>(W_attn, 3072, (ushortx*)wahi, (ushortx*)walo);
    k_wT<<<dim3(32, 32), dim3(32, 8)>>>(W_proj, 1024, (ushortx*)wphi, (ushortx*)wplo);
    k_gemm_qkv<<<dim3(24, 64), 128, DSM>>>(b_attn);
    k_attn_mma<<<dim3(8, 64), 256, ASM_SZ>>>();
    k_gemm_proj<<<dim3(8, 64), 128, DSM>>>(b_proj, out);
}

// round 14
// speedup vs baseline: 1.5109x; 1.2844x over previous
#include <cuda_runtime.h>
#include <cuda_fp16.h>
#include <math.h>
#include <cstdint>

#define BSZ 4
#define SQ  1024
#define EMB 1024
#define NH  16
#define HD  64

typedef unsigned long long u64;
typedef unsigned short ushortx;

// ---------------------------------------------------------------------------
// Scratch (__device__ globals; allocation-free)
// A-side operands single fp16: X, Q, O.  B-side split fp16 hi/lo: K, V, W^T.
// ---------------------------------------------------------------------------
__device__ uint4 g_Xh4[4096*1024*2/16];
__device__ uint4 g_Qh4[BSZ*NH*SQ*HD*2/16];
__device__ uint4 g_Kh4[BSZ*NH*SQ*HD*2/16];
__device__ uint4 g_Kl4[BSZ*NH*SQ*HD*2/16];
__device__ uint4 g_Vh4[BSZ*NH*SQ*HD*2/16];
__device__ uint4 g_Vl4[BSZ*NH*SQ*HD*2/16];
__device__ uint4 g_Oh4[4096*1024*2/16];
__device__ uint4 g_WaTh4[3072*1024*2/16];   // W_attn^T [3072][1024]
__device__ uint4 g_WaTl4[3072*1024*2/16];
__device__ uint4 g_WpTh4[1024*1024*2/16];   // W_proj^T [1024][1024]
__device__ uint4 g_WpTl4[1024*1024*2/16];

// ---------------------------------------------------------------------------
// helpers
// ---------------------------------------------------------------------------
__device__ __forceinline__ uint32_t smem_u32(const void* p) {
    uint32_t a;
    asm("{ .reg .u64 t; cvta.to.shared.u64 t, %1; cvt.u32.u64 %0, t; }" : "=r"(a) : "l"(p));
    return a;
}
__device__ __forceinline__ void cpa16(uint32_t dst, const void* src) {
    asm volatile("cp.async.cg.shared.global [%0], [%1], 16;"
                 :: "r"(dst), "l"(__cvta_generic_to_global(src)) : "memory");
}
#define CPA_COMMIT() asm volatile("cp.async.commit_group;" ::: "memory")
#define CPA_WAIT(n)  asm volatile("cp.async.wait_group %0;" :: "n"(n) : "memory")

__device__ __forceinline__ uint32_t lds32(uint32_t addr) {
    uint32_t v; asm volatile("ld.shared.b32 %0,[%1];" : "=r"(v) : "r"(addr)); return v;
}
// m16n8k16 fp16 MMA, fp32 accumulate
__device__ __forceinline__ void mma16816(float* c, const uint32_t* a, const uint32_t* b) {
    asm volatile("mma.sync.aligned.m16n8k16.row.col.f32.f16.f16.f32 "
        "{%0,%1,%2,%3}, {%4,%5,%6,%7}, {%8,%9}, {%0,%1,%2,%3};"
        : "+f"(c[0]), "+f"(c[1]), "+f"(c[2]), "+f"(c[3])
        : "r"(a[0]), "r"(a[1]), "r"(a[2]), "r"(a[3]), "r"(b[0]), "r"(b[1]));
}
__device__ __forceinline__ void ldm_x4(uint32_t* r, uint32_t addr) {
    asm volatile("ldmatrix.sync.aligned.m8n8.x4.shared.b16 {%0,%1,%2,%3}, [%4];"
        : "=r"(r[0]), "=r"(r[1]), "=r"(r[2]), "=r"(r[3]) : "r"(addr));
}
__device__ __forceinline__ void ldm_x2(uint32_t* r, uint32_t addr) {
    asm volatile("ldmatrix.sync.aligned.m8n8.x2.shared.b16 {%0,%1}, [%2];"
        : "=r"(r[0]), "=r"(r[1]) : "r"(addr));
}
__device__ __forceinline__ void ldm_x2t(uint32_t* r, uint32_t addr) {
    asm volatile("ldmatrix.sync.aligned.m8n8.x2.trans.shared.b16 {%0,%1}, [%2];"
        : "=r"(r[0]), "=r"(r[1]) : "r"(addr));
}
// two f32 -> one packed f16x2
__device__ __forceinline__ uint32_t pack2h(float x, float y) {
    uint32_t r;
    asm("{ .reg .f16 a,b; cvt.rn.f16.f32 a,%1; cvt.rn.f16.f32 b,%2; mov.b32 %0,{a,b}; }"
        : "=r"(r) : "f"(x), "f"(y));
    return r;
}
// two f32 -> packed f16x2 hi + residual lo
__device__ __forceinline__ void split2h(float x, float y, uint32_t& h, uint32_t& l) {
    __half hx = __float2half_rn(x);
    __half hy = __float2half_rn(y);
    float rx = x - __half2float(hx);
    float ry = y - __half2float(hy);
    __half lx = __float2half_rn(rx);
    __half ly = __float2half_rn(ry);
    h = (uint32_t)__half_as_ushort(hx) | ((uint32_t)__half_as_ushort(hy) << 16);
    l = (uint32_t)__half_as_ushort(lx) | ((uint32_t)__half_as_ushort(ly) << 16);
}

// ---------------------------------------------------------------------------
// GEMM geometry: 64x128 block, BK=64, 4 warps (2m x 2n), warp tile 32x64.
// A single fp16 (1 array, 64x144B), B split hi/lo (2 arrays, 128x144B each).
// 2 MMA passes per ks (A*Bhi, A*Blo). wait(1)->sync->compute->sync,
// double buffer, 2 CTAs/SM of 128 threads.
// ---------------------------------------------------------------------------
#define ROWB   144
#define AARRB  (64*ROWB)               // 9216
#define BARRB  (128*ROWB)              // 18432
#define STAGEB (AARRB + 2*BARRB)       // 46080
#define NCHUNK 16                      // 1024 / 64

__device__ __forceinline__ void load_chunk(
    uint32_t st, const ushortx* A0,
    const ushortx* B0, const ushortx* B1, int k0, int tid)
{
    // A: 64 rows x 8 segs (single)
    #pragma unroll
    for (int i = 0; i < 4; i++) {
        const int u = i * 128 + tid;      // 0..511
        const int r = u >> 3, c16 = u & 7;
        cpa16(st + r * ROWB + c16 * 16,
              (const char*)(A0 + r * 1024 + k0) + c16 * 16);
    }
    // B hi/lo: 128 rows x 8 segs each
    #pragma unroll
    for (int i = 0; i < 8; i++) {
        const int u = i * 128 + tid;      // 0..1023
        const int r = u >> 3, c16 = u & 7;
        cpa16(st + AARRB + r * ROWB + c16 * 16,
              (const char*)(B0 + r * 1024 + k0) + c16 * 16);
        cpa16(st + AARRB + BARRB + r * ROWB + c16 * 16,
              (const char*)(B1 + r * 1024 + k0) + c16 * 16);
    }
}

__device__ __forceinline__ void compute_chunk(
    uint32_t st, int wm, int wn, int t4, int tm4, float acc[2][8][4])
{
    #pragma unroll
    for (int ks = 0; ks < 4; ks++) {
        const int kb = ks * 32 + tm4 * 4;     // byte offset of this thread's k pair
        uint32_t Ah[2][4], Bh[8][2], Bl[8][2];
        #pragma unroll
        for (int mf = 0; mf < 2; mf++) {
            const uint32_t ra = st + (wm * 32 + mf * 16 + t4) * ROWB + kb;
            Ah[mf][0] = lds32(ra);
            Ah[mf][1] = lds32(ra + 8 * ROWB);
            Ah[mf][2] = lds32(ra + 16);
            Ah[mf][3] = lds32(ra + 8 * ROWB + 16);
        }
        #pragma unroll
        for (int nf = 0; nf < 8; nf++) {
            const uint32_t rb = st + AARRB + (wn * 64 + nf * 8 + t4) * ROWB + kb;
            Bh[nf][0] = lds32(rb);
            Bh[nf][1] = lds32(rb + 16);
            Bl[nf][0] = lds32(rb + BARRB);
            Bl[nf][1] = lds32(rb + BARRB + 16);
        }
        #pragma unroll
        for (int mf = 0; mf < 2; mf++)
            #pragma unroll
            for (int nf = 0; nf < 8; nf++)
                mma16816(acc[mf][nf], Ah[mf], Bh[nf]);
        #pragma unroll
        for (int mf = 0; mf < 2; mf++)
            #pragma unroll
            for (int nf = 0; nf < 8; nf++)
                mma16816(acc[mf][nf], Ah[mf], Bl[nf]);
    }
}

__device__ __forceinline__ void gemm_mainloop(
    uint32_t sm, const ushortx* A0,
    const ushortx* B0, const ushortx* B1,
    int wm, int wn, int t4, int tm4, int tid, float acc[2][8][4])
{
    #pragma unroll
    for (int mf = 0; mf < 2; mf++)
        #pragma unroll
        for (int nf = 0; nf < 8; nf++)
            #pragma unroll
            for (int j = 0; j < 4; j++) acc[mf][nf][j] = 0.f;

    load_chunk(sm, A0, B0, B1, 0, tid);
    CPA_COMMIT();
    for (int c = 0; c < NCHUNK; c++) {
        if (c + 1 < NCHUNK) {
            load_chunk(sm + ((c + 1) & 1) * STAGEB, A0, B0, B1, (c + 1) * 64, tid);
            CPA_COMMIT();
            CPA_WAIT(1);
        } else {
            CPA_WAIT(0);
        }
        __syncthreads();
        compute_chunk(sm + (c & 1) * STAGEB, wm, wn, t4, tm4, acc);
        __syncthreads();
    }
}

// ---------------------------------------------------------------------------
// QKV GEMM: X @ W_attn + b_attn -> Q single fp16 (x0.125) / K,V fp16 hi/lo
// grid (24, 64)
// ---------------------------------------------------------------------------
__global__ __launch_bounds__(128, 2) void k_gemm_qkv(const float* __restrict__ bias)
{
    extern __shared__ __align__(16) char dsm[];
    const int tid = threadIdx.x, wid = tid >> 5, lane = tid & 31;
    const int t4 = lane >> 2, tm4 = lane & 3;
    const int wm = wid >> 1, wn = wid & 1;
    const int bn = blockIdx.x * 128, bm = blockIdx.y * 64;
    const uint32_t sm = smem_u32(dsm);

    float acc[2][8][4];
    gemm_mainloop(sm,
        (const ushortx*)g_Xh4 + (long)bm * 1024,
        (const ushortx*)g_WaTh4 + (long)bn * 1024, (const ushortx*)g_WaTl4 + (long)bn * 1024,
        wm, wn, t4, tm4, tid, acc);

    const int which = bn >> 10;             // 0=Q 1=K 2=V
    uint32_t* qh = (uint32_t*)g_Qh4;
    uint32_t* dhi = (which == 1) ? (uint32_t*)g_Kh4 : (uint32_t*)g_Vh4;
    uint32_t* dlo = (which == 1) ? (uint32_t*)g_Kl4 : (uint32_t*)g_Vl4;

    #pragma unroll
    for (int mf = 0; mf < 2; mf++) {
        #pragma unroll
        for (int nf = 0; nf < 8; nf++) {
            const int n_g = bn + wn * 64 + nf * 8 + tm4 * 2;
            const int e = n_g & 1023, h = e >> 6, d = e & 63;
            const float b0 = __ldg(&bias[n_g]), b1 = __ldg(&bias[n_g + 1]);
            #pragma unroll
            for (int rr = 0; rr < 2; rr++) {
                const int row = bm + wm * 32 + mf * 16 + t4 + rr * 8;
                const int b = row >> 10, s = row & 1023;
                const long off = (((long)(b * NH + h) * SQ) + s) * HD + d;
                const float v0 = acc[mf][nf][rr * 2 + 0] + b0;
                const float v1 = acc[mf][nf][rr * 2 + 1] + b1;
                if (which == 0) {
                    qh[off >> 1] = pack2h(v0 * 0.125f, v1 * 0.125f);
                } else {
                    uint32_t hh, ll;
                    split2h(v0, v1, hh, ll);
                    dhi[off >> 1] = hh;
                    dlo[off >> 1] = ll;
                }
            }
        }
    }
}

// ---------------------------------------------------------------------------
// Proj GEMM: O(fp16) @ W_proj + b_proj -> out.  grid (8, 64)
// ---------------------------------------------------------------------------
__global__ __launch_bounds__(128, 2) void k_gemm_proj(const float* __restrict__ bias,
                                                      float* __restrict__ out)
{
    extern __shared__ __align__(16) char dsm[];
    const int tid = threadIdx.x, wid = tid >> 5, lane = tid & 31;
    const int t4 = lane >> 2, tm4 = lane & 3;
    const int wm = wid >> 1, wn = wid & 1;
    const int bn = blockIdx.x * 128, bm = blockIdx.y * 64;
    const uint32_t sm = smem_u32(dsm);

    float acc[2][8][4];
    gemm_mainloop(sm,
        (const ushortx*)g_Oh4 + (long)bm * 1024,
        (const ushortx*)g_WpTh4 + (long)bn * 1024, (const ushortx*)g_WpTl4 + (long)bn * 1024,
        wm, wn, t4, tm4, tid, acc);

    #pragma unroll
    for (int mf = 0; mf < 2; mf++) {
        #pragma unroll
        for (int nf = 0; nf < 8; nf++) {
            const int n_g = bn + wn * 64 + nf * 8 + tm4 * 2;
            const float b0 = __ldg(&bias[n_g]), b1 = __ldg(&bias[n_g + 1]);
            #pragma unroll
            for (int rr = 0; rr < 2; rr++) {
                const int row = bm + wm * 32 + mf * 16 + t4 + rr * 8;
                float2 v = make_float2(acc[mf][nf][rr * 2 + 0] + b0,
                                       acc[mf][nf][rr * 2 + 1] + b1);
                *(float2*)&out[(long)row * EMB + n_g] = v;
            }
        }
    }
}

// ---------------------------------------------------------------------------
// Elementwise f32 -> single fp16 (A-side operands)
// ---------------------------------------------------------------------------
__global__ __launch_bounds__(256) void k_cvt_h(const float4* __restrict__ src,
                                               uint2* __restrict__ dst, int n4)
{
    int i = blockIdx.x * 256 + threadIdx.x;
    if (i >= n4) return;
    float4 v = src[i];
    dst[i] = make_uint2(pack2h(v.x, v.y), pack2h(v.z, v.w));
}

// ---------------------------------------------------------------------------
// Transpose-convert: W [1024, ncols] f32 -> W^T hi/lo fp16 [ncols, 1024]
// ---------------------------------------------------------------------------
__global__ __launch_bounds__(256) void k_wT(const float* __restrict__ W, int ncols,
                                            ushortx* __restrict__ hiT,
                                            ushortx* __restrict__ loT)
{
    __shared__ float t[32][33];
    const int tx = threadIdx.x, ty = threadIdx.y;
    const int n0 = blockIdx.x * 32, k0 = blockIdx.y * 32;
    #pragma unroll
    for (int i = 0; i < 4; i++)
        t[ty + i * 8][tx] = W[(k0 + ty + i * 8) * ncols + n0 + tx];
    __syncthreads();
    #pragma unroll
    for (int i = 0; i < 4; i++) {
        const int r = ty + i * 8;
        float v = t[tx][r];
        __half bh = __float2half_rn(v);
        float rr = v - __half2float(bh);
        __half bl = __float2half_rn(rr);
        const int off = (n0 + r) * 1024 + k0 + tx;
        hiT[off] = __half_as_ushort(bh);
        loT[off] = __half_as_ushort(bl);
    }
}

// ---------------------------------------------------------------------------
// HMMA causal flash attention — fp16, double-buffered K/V staging.
// Block: 128 q-rows x 1 head. 8 warps x 16 q-rows. 64-key tiles.
// Q single fp16 (A), K/V split hi/lo (B). 2-MMA passes. O written single fp16.
// ---------------------------------------------------------------------------
#define AROW     144
#define KVARR    (64*AROW)      // 9216
#define KVSTAGE  (4*KVARR)      // 36864

__global__ __launch_bounds__(256, 1) void k_attn_mma()
{
    extern __shared__ char smb[];
    const uint32_t sb = smem_u32(smb);
    const int tid = threadIdx.x, lane = tid & 31, w = tid >> 5;
    const int t4 = lane >> 2, tm4 = lane & 3;
    const int bh = blockIdx.y;
    const int q0 = ((int)gridDim.x - 1 - (int)blockIdx.x) * 128;  // heavy blocks first

    const long headoff = (long)bh * SQ * HD;

    // ---- stage Q (single fp16) via cp.async: 128 rows x 128B
    {
        const char* q_g = (const char*)((const ushortx*)g_Qh4 + headoff + (long)q0 * HD);
        #pragma unroll
        for (int i = 0; i < 4; i++) {
            const int u = i * 256 + tid;        // 0..1023
            const int r = u >> 3, seg = u & 7;
            cpa16(sb + r * AROW + seg * 16, q_g + r * 128 + seg * 16);
        }
        CPA_COMMIT();
        CPA_WAIT(0);
        __syncthreads();
    }

    // ---- Q fragments (A, m16k16 x4 k-steps), kept in regs for whole kernel
    uint32_t qh[4][4];
    {
        const uint32_t rowq = w * 16 + (lane & 15);
        #pragma unroll
        for (int ks = 0; ks < 4; ks++) {
            const uint32_t col = ks * 32 + ((lane >> 4) << 4);
            ldm_x4(qh[ks], sb + rowq * AROW + col);
        }
    }
    __syncthreads();   // all warps done reading Q smem; buffers reusable

    float O[8][4];
    #pragma unroll
    for (int i = 0; i < 8; i++)
        #pragma unroll
        for (int j = 0; j < 4; j++) O[i][j] = 0.f;
    float m0 = -INFINITY, m1 = -INFINITY, lsum0 = 0.f, lsum1 = 0.f;
    const int qrow0 = q0 + w * 16 + t4;

    const char* kh_g = (const char*)((const ushortx*)g_Kh4 + headoff);
    const char* kl_g = (const char*)((const ushortx*)g_Kl4 + headoff);
    const char* vh_g = (const char*)((const ushortx*)g_Vh4 + headoff);
    const char* vl_g = (const char*)((const ushortx*)g_Vl4 + headoff);
    const int nkt = q0 / 64 + 2;

    // stage K/V tile kt into buffer base (each thread: 8 cp.async)
    auto stage_kv = [&](uint32_t base, int kt) {
        const long tb = (long)kt * 64 * HD * 2;
        const char* srcs[4] = {kh_g + tb, kl_g + tb, vh_g + tb, vl_g + tb};
        #pragma unroll
        for (int arr = 0; arr < 4; arr++) {
            #pragma unroll
            for (int i = 0; i < 2; i++) {
                const int u = i * 256 + tid;   // 0..511
                const int r = u >> 3, seg = u & 7;
                cpa16(base + arr * KVARR + r * AROW + seg * 16,
                      srcs[arr] + r * 128 + seg * 16);
            }
        }
    };

    stage_kv(sb, 0);
    CPA_COMMIT();

    for (int kt = 0; kt < nkt; kt++) {
        const int k0 = kt * 64;
        if (kt + 1 < nkt) {
            stage_kv(sb + ((kt + 1) & 1) * KVSTAGE, kt + 1);
            CPA_COMMIT();
            CPA_WAIT(1);
        } else {
            CPA_WAIT(0);
        }
        __syncthreads();

        const uint32_t Khi = sb + (kt & 1) * KVSTAGE;
        const uint32_t Klo = Khi + KVARR;
        const uint32_t Vhi = Khi + 2 * KVARR;
        const uint32_t Vlo = Khi + 3 * KVARR;

        // ---- scores S = Q (Khi + Klo)^T: 2 passes x 8 indep accs per ks
        float sc[8][4];
        #pragma unroll
        for (int nf = 0; nf < 8; nf++)
            sc[nf][0] = sc[nf][1] = sc[nf][2] = sc[nf][3] = 0.f;
        {
            const uint32_t rowkb = (lane & 7);
            const uint32_t colp = ((lane >> 3) & 1) * 16;
            #pragma unroll
            for (int ks = 0; ks < 4; ks++) {
                uint32_t kbh[8][2], kbl[8][2];
                #pragma unroll
                for (int nf = 0; nf < 8; nf++) {
                    ldm_x2(kbh[nf], Khi + (nf * 8 + rowkb) * AROW + ks * 32 + colp);
                    ldm_x2(kbl[nf], Klo + (nf * 8 + rowkb) * AROW + ks * 32 + colp);
                }
                #pragma unroll
                for (int nf = 0; nf < 8; nf++) mma16816(sc[nf], qh[ks], kbh[nf]);
                #pragma unroll
                for (int nf = 0; nf < 8; nf++) mma16816(sc[nf], qh[ks], kbl[nf]);
            }
        }

        // ---- causal mask (only the last two tiles can clip)
        if (kt >= nkt - 2) {
            #pragma unroll
            for (int nf = 0; nf < 8; nf++) {
                const int col = k0 + nf * 8 + tm4 * 2;
                if (col     > qrow0)     sc[nf][0] = -1e30f;
                if (col + 1 > qrow0)     sc[nf][1] = -1e30f;
                if (col     > qrow0 + 8) sc[nf][2] = -1e30f;
                if (col + 1 > qrow0 + 8) sc[nf][3] = -1e30f;
            }
        }

        // ---- online softmax (rows t4 and t4+8 within warp)
        float mx0 = sc[0][0], mx1 = sc[0][2];
        #pragma unroll
        for (int nf = 0; nf < 8; nf++) {
            mx0 = fmaxf(mx0, fmaxf(sc[nf][0], sc[nf][1]));
            mx1 = fmaxf(mx1, fmaxf(sc[nf][2], sc[nf][3]));
        }
        mx0 = fmaxf(mx0, __shfl_xor_sync(0xFFFFFFFF, mx0, 1));
        mx0 = fmaxf(mx0, __shfl_xor_sync(0xFFFFFFFF, mx0, 2));
        mx1 = fmaxf(mx1, __shfl_xor_sync(0xFFFFFFFF, mx1, 1));
        mx1 = fmaxf(mx1, __shfl_xor_sync(0xFFFFFFFF, mx1, 2));
        const float mn0 = fmaxf(m0, mx0), mn1 = fmaxf(m1, mx1);
        const float c0 = __expf(m0 - mn0), c1 = __expf(m1 - mn1);
        m0 = mn0; m1 = mn1;
        float ps0 = 0.f, ps1 = 0.f;
        #pragma unroll
        for (int nf = 0; nf < 8; nf++) {
            sc[nf][0] = __expf(sc[nf][0] - mn0); ps0 += sc[nf][0];
            sc[nf][1] = __expf(sc[nf][1] - mn0); ps0 += sc[nf][1];
            sc[nf][2] = __expf(sc[nf][2] - mn1); ps1 += sc[nf][2];
            sc[nf][3] = __expf(sc[nf][3] - mn1); ps1 += sc[nf][3];
        }
        ps0 += __shfl_xor_sync(0xFFFFFFFF, ps0, 1);
        ps0 += __shfl_xor_sync(0xFFFFFFFF, ps0, 2);
        ps1 += __shfl_xor_sync(0xFFFFFFFF, ps1, 1);
        ps1 += __shfl_xor_sync(0xFFFFFFFF, ps1, 2);
        lsum0 = lsum0 * c0 + ps0;
        lsum1 = lsum1 * c1 + ps1;
        #pragma unroll
        for (int nf = 0; nf < 8; nf++) {
            O[nf][0] *= c0; O[nf][1] *= c0;
            O[nf][2] *= c1; O[nf][3] *= c1;
        }

        // ---- pack P as single-fp16 A-frags directly from score c-frags
        uint32_t ph[4][4];
        #pragma unroll
        for (int j = 0; j < 4; j++) {
            ph[j][0] = pack2h(sc[2*j    ][0], sc[2*j    ][1]);
            ph[j][1] = pack2h(sc[2*j    ][2], sc[2*j    ][3]);
            ph[j][2] = pack2h(sc[2*j + 1][0], sc[2*j + 1][1]);
            ph[j][3] = pack2h(sc[2*j + 1][2], sc[2*j + 1][3]);
        }

        // ---- O += P (Vhi + Vlo): 2 passes x 8 indep accs per ks
        {
            const uint32_t rowvb = (lane & 15);
            #pragma unroll
            for (int ks = 0; ks < 4; ks++) {
                uint32_t vbh[8][2], vbl[8][2];
                #pragma unroll
                for (int nfd = 0; nfd < 8; nfd++) {
                    ldm_x2t(vbh[nfd], Vhi + (ks * 16 + rowvb) * AROW + nfd * 16);
                    ldm_x2t(vbl[nfd], Vlo + (ks * 16 + rowvb) * AROW + nfd * 16);
                }
                #pragma unroll
                for (int nfd = 0; nfd < 8; nfd++) mma16816(O[nfd], ph[ks], vbh[nfd]);
                #pragma unroll
                for (int nfd = 0; nfd < 8; nfd++) mma16816(O[nfd], ph[ks], vbl[nfd]);
            }
        }
        __syncthreads();   // all warps done with this buffer before restaging
    }

    // ---- finalize: O /= l, write single fp16 in [B,S,E] merged-head layout
    const float i0 = 1.f / lsum0, i1 = 1.f / lsum1;
    const int b = bh >> 4, h = bh & 15;
    uint32_t* Oh = (uint32_t*)g_Oh4;
    const long base0 = ((long)(b * SQ + qrow0)) * EMB + h * HD;
    const long base1 = base0 + 8L * EMB;
    #pragma unroll
    for (int nfd = 0; nfd < 8; nfd++) {
        const int col = nfd * 8 + tm4 * 2;
        Oh[(base0 + col) >> 1] = pack2h(O[nfd][0] * i0, O[nfd][1] * i0);
        Oh[(base1 + col) >> 1] = pack2h(O[nfd][2] * i1, O[nfd][3] * i1);
    }
}

// ---------------------------------------------------------------------------
extern "C" void kernel_launch(void* const* d_in, const int* in_sizes, int n_in,
                              void* d_out, int out_size)
{
    const float* x      = (const float*)d_in[0];
    const float* W_attn = (const float*)d_in[1];
    const float* b_attn = (const float*)d_in[2];
    const float* W_proj = (const float*)d_in[3];
    const float* b_proj = (const float*)d_in[4];
    float* out = (float*)d_out;

    const int DSM = 2 * STAGEB;          // 92160
    const int ASM_SZ = 2 * KVSTAGE;      // 73728
    cudaFuncSetAttribute(k_gemm_qkv,  cudaFuncAttributeMaxDynamicSharedMemorySize, DSM);
    cudaFuncSetAttribute(k_gemm_proj, cudaFuncAttributeMaxDynamicSharedMemorySize, DSM);
    cudaFuncSetAttribute(k_attn_mma,  cudaFuncAttributeMaxDynamicSharedMemorySize, ASM_SZ);

    uint4 *xh, *wah, *wal, *wph, *wpl;
    cudaGetSymbolAddress((void**)&xh,  g_Xh4);
    cudaGetSymbolAddress((void**)&wah, g_WaTh4);
    cudaGetSymbolAddress((void**)&wal, g_WaTl4);
    cudaGetSymbolAddress((void**)&wph, g_WpTh4);
    cudaGetSymbolAddress((void**)&wpl, g_WpTl4);

    k_cvt_h<<<4096, 256>>>((const float4*)x, (uint2*)xh, 4096 * 1024 / 4);
    k_wT<<<dim3(96, 32), dim3(32, 8)>>>(W_attn, 3072, (ushortx*)wah, (ushortx*)wal);
    k_wT<<<dim3(32, 32), dim3(32, 8)>>>(W_proj, 1024, (ushortx*)wph, (ushortx*)wpl);
    k_gemm_qkv<<<dim3(24, 64), 128, DSM>>>(b_attn);
    k_attn_mma<<<dim3(8, 64), 256, ASM_SZ>>>();
    k_gemm_proj<<<dim3(8, 64), 128, DSM>>>(b_proj, out);
}

// round 16
// speedup vs baseline: 2.5880x; 1.7129x over previous
#include <cuda_runtime.h>
#include <cuda_fp16.h>
#include <math.h>
#include <cstdint>

#define BSZ 4
#define SQ  1024
#define EMB 1024
#define NH  16
#define HD  64

typedef unsigned long long u64;
typedef unsigned short ushortx;

// ---------------------------------------------------------------------------
// Scratch (__device__ globals; allocation-free) — ALL operands single fp16.
// ---------------------------------------------------------------------------
__device__ uint4 g_Xh4[4096*1024*2/16];
__device__ uint4 g_Qh4[BSZ*NH*SQ*HD*2/16];
__device__ uint4 g_Kh4[BSZ*NH*SQ*HD*2/16];
__device__ uint4 g_Vh4[BSZ*NH*SQ*HD*2/16];
__device__ uint4 g_Oh4[4096*1024*2/16];
__device__ uint4 g_WaTh4[3072*1024*2/16];   // W_attn^T [3072][1024]
__device__ uint4 g_WpTh4[1024*1024*2/16];   // W_proj^T [1024][1024]

// ---------------------------------------------------------------------------
// helpers
// ---------------------------------------------------------------------------
__device__ __forceinline__ uint32_t smem_u32(const void* p) {
    uint32_t a;
    asm("{ .reg .u64 t; cvta.to.shared.u64 t, %1; cvt.u32.u64 %0, t; }" : "=r"(a) : "l"(p));
    return a;
}
__device__ __forceinline__ void cpa16(uint32_t dst, const void* src) {
    asm volatile("cp.async.cg.shared.global [%0], [%1], 16;"
                 :: "r"(dst), "l"(__cvta_generic_to_global(src)) : "memory");
}
#define CPA_COMMIT() asm volatile("cp.async.commit_group;" ::: "memory")
#define CPA_WAIT(n)  asm volatile("cp.async.wait_group %0;" :: "n"(n) : "memory")

__device__ __forceinline__ uint32_t lds32(uint32_t addr) {
    uint32_t v; asm volatile("ld.shared.b32 %0,[%1];" : "=r"(v) : "r"(addr)); return v;
}
// m16n8k16 fp16 MMA, fp32 accumulate
__device__ __forceinline__ void mma16816(float* c, const uint32_t* a, const uint32_t* b) {
    asm volatile("mma.sync.aligned.m16n8k16.row.col.f32.f16.f16.f32 "
        "{%0,%1,%2,%3}, {%4,%5,%6,%7}, {%8,%9}, {%0,%1,%2,%3};"
        : "+f"(c[0]), "+f"(c[1]), "+f"(c[2]), "+f"(c[3])
        : "r"(a[0]), "r"(a[1]), "r"(a[2]), "r"(a[3]), "r"(b[0]), "r"(b[1]));
}
__device__ __forceinline__ void ldm_x4(uint32_t* r, uint32_t addr) {
    asm volatile("ldmatrix.sync.aligned.m8n8.x4.shared.b16 {%0,%1,%2,%3}, [%4];"
        : "=r"(r[0]), "=r"(r[1]), "=r"(r[2]), "=r"(r[3]) : "r"(addr));
}
__device__ __forceinline__ void ldm_x2(uint32_t* r, uint32_t addr) {
    asm volatile("ldmatrix.sync.aligned.m8n8.x2.shared.b16 {%0,%1}, [%2];"
        : "=r"(r[0]), "=r"(r[1]) : "r"(addr));
}
__device__ __forceinline__ void ldm_x2t(uint32_t* r, uint32_t addr) {
    asm volatile("ldmatrix.sync.aligned.m8n8.x2.trans.shared.b16 {%0,%1}, [%2];"
        : "=r"(r[0]), "=r"(r[1]) : "r"(addr));
}
// two f32 -> one packed f16x2
__device__ __forceinline__ uint32_t pack2h(float x, float y) {
    uint32_t r;
    asm("{ .reg .f16 a,b; cvt.rn.f16.f32 a,%1; cvt.rn.f16.f32 b,%2; mov.b32 %0,{a,b}; }"
        : "=r"(r) : "f"(x), "f"(y));
    return r;
}

// ---------------------------------------------------------------------------
// GEMM geometry: 64x128 block, BK=64, 4 warps (2m x 2n), warp tile 32x64.
// A single fp16 (64x144B), B single fp16 (128x144B). 1 MMA per output frag.
// wait(1)->sync->compute->sync, double buffer, 2 CTAs/SM of 128 threads.
// ---------------------------------------------------------------------------
#define ROWB   144
#define AARRB  (64*ROWB)               // 9216
#define BARRB  (128*ROWB)              // 18432
#define STAGEB (AARRB + BARRB)         // 27648
#define NCHUNK 16                      // 1024 / 64

__device__ __forceinline__ void load_chunk(
    uint32_t st, const ushortx* A0, const ushortx* B0, int k0, int tid)
{
    // A: 64 rows x 8 segs
    #pragma unroll
    for (int i = 0; i < 4; i++) {
        const int u = i * 128 + tid;      // 0..511
        const int r = u >> 3, c16 = u & 7;
        cpa16(st + r * ROWB + c16 * 16,
              (const char*)(A0 + r * 1024 + k0) + c16 * 16);
    }
    // B: 128 rows x 8 segs
    #pragma unroll
    for (int i = 0; i < 8; i++) {
        const int u = i * 128 + tid;      // 0..1023
        const int r = u >> 3, c16 = u & 7;
        cpa16(st + AARRB + r * ROWB + c16 * 16,
              (const char*)(B0 + r * 1024 + k0) + c16 * 16);
    }
}

__device__ __forceinline__ void compute_chunk(
    uint32_t st, int wm, int wn, int t4, int tm4, float acc[2][8][4])
{
    #pragma unroll
    for (int ks = 0; ks < 4; ks++) {
        const int kb = ks * 32 + tm4 * 4;     // byte offset of this thread's k pair
        uint32_t Ah[2][4], Bh[8][2];
        #pragma unroll
        for (int mf = 0; mf < 2; mf++) {
            const uint32_t ra = st + (wm * 32 + mf * 16 + t4) * ROWB + kb;
            Ah[mf][0] = lds32(ra);
            Ah[mf][1] = lds32(ra + 8 * ROWB);
            Ah[mf][2] = lds32(ra + 16);
            Ah[mf][3] = lds32(ra + 8 * ROWB + 16);
        }
        #pragma unroll
        for (int nf = 0; nf < 8; nf++) {
            const uint32_t rb = st + AARRB + (wn * 64 + nf * 8 + t4) * ROWB + kb;
            Bh[nf][0] = lds32(rb);
            Bh[nf][1] = lds32(rb + 16);
        }
        #pragma unroll
        for (int mf = 0; mf < 2; mf++)
            #pragma unroll
            for (int nf = 0; nf < 8; nf++)
                mma16816(acc[mf][nf], Ah[mf], Bh[nf]);
    }
}

__device__ __forceinline__ void gemm_mainloop(
    uint32_t sm, const ushortx* A0, const ushortx* B0,
    int wm, int wn, int t4, int tm4, int tid, float acc[2][8][4])
{
    #pragma unroll
    for (int mf = 0; mf < 2; mf++)
        #pragma unroll
        for (int nf = 0; nf < 8; nf++)
            #pragma unroll
            for (int j = 0; j < 4; j++) acc[mf][nf][j] = 0.f;

    load_chunk(sm, A0, B0, 0, tid);
    CPA_COMMIT();
    for (int c = 0; c < NCHUNK; c++) {
        if (c + 1 < NCHUNK) {
            load_chunk(sm + ((c + 1) & 1) * STAGEB, A0, B0, (c + 1) * 64, tid);
            CPA_COMMIT();
            CPA_WAIT(1);
        } else {
            CPA_WAIT(0);
        }
        __syncthreads();
        compute_chunk(sm + (c & 1) * STAGEB, wm, wn, t4, tm4, acc);
        __syncthreads();
    }
}

// ---------------------------------------------------------------------------
// QKV GEMM: X @ W_attn + b_attn -> Q (x0.125) / K / V single fp16 [B,H,S,D]
// grid (24, 64)
// ---------------------------------------------------------------------------
__global__ __launch_bounds__(128, 2) void k_gemm_qkv(const float* __restrict__ bias)
{
    extern __shared__ __align__(16) char dsm[];
    const int tid = threadIdx.x, wid = tid >> 5, lane = tid & 31;
    const int t4 = lane >> 2, tm4 = lane & 3;
    const int wm = wid >> 1, wn = wid & 1;
    const int bn = blockIdx.x * 128, bm = blockIdx.y * 64;
    const uint32_t sm = smem_u32(dsm);

    float acc[2][8][4];
    gemm_mainloop(sm,
        (const ushortx*)g_Xh4 + (long)bm * 1024,
        (const ushortx*)g_WaTh4 + (long)bn * 1024,
        wm, wn, t4, tm4, tid, acc);

    const int which = bn >> 10;             // 0=Q 1=K 2=V
    uint32_t* dst = (which == 0) ? (uint32_t*)g_Qh4 : (which == 1) ? (uint32_t*)g_Kh4 : (uint32_t*)g_Vh4;
    const float scale = (which == 0) ? 0.125f : 1.f;

    #pragma unroll
    for (int mf = 0; mf < 2; mf++) {
        #pragma unroll
        for (int nf = 0; nf < 8; nf++) {
            const int n_g = bn + wn * 64 + nf * 8 + tm4 * 2;
            const int e = n_g & 1023, h = e >> 6, d = e & 63;
            const float b0 = __ldg(&bias[n_g]), b1 = __ldg(&bias[n_g + 1]);
            #pragma unroll
            for (int rr = 0; rr < 2; rr++) {
                const int row = bm + wm * 32 + mf * 16 + t4 + rr * 8;
                const int b = row >> 10, s = row & 1023;
                const long off = (((long)(b * NH + h) * SQ) + s) * HD + d;
                dst[off >> 1] = pack2h((acc[mf][nf][rr * 2 + 0] + b0) * scale,
                                       (acc[mf][nf][rr * 2 + 1] + b1) * scale);
            }
        }
    }
}

// ---------------------------------------------------------------------------
// Proj GEMM: O(fp16) @ W_proj + b_proj -> out.  grid (8, 64)
// ---------------------------------------------------------------------------
__global__ __launch_bounds__(128, 2) void k_gemm_proj(const float* __restrict__ bias,
                                                      float* __restrict__ out)
{
    extern __shared__ __align__(16) char dsm[];
    const int tid = threadIdx.x, wid = tid >> 5, lane = tid & 31;
    const int t4 = lane >> 2, tm4 = lane & 3;
    const int wm = wid >> 1, wn = wid & 1;
    const int bn = blockIdx.x * 128, bm = blockIdx.y * 64;
    const uint32_t sm = smem_u32(dsm);

    float acc[2][8][4];
    gemm_mainloop(sm,
        (const ushortx*)g_Oh4 + (long)bm * 1024,
        (const ushortx*)g_WpTh4 + (long)bn * 1024,
        wm, wn, t4, tm4, tid, acc);

    #pragma unroll
    for (int mf = 0; mf < 2; mf++) {
        #pragma unroll
        for (int nf = 0; nf < 8; nf++) {
            const int n_g = bn + wn * 64 + nf * 8 + tm4 * 2;
            const float b0 = __ldg(&bias[n_g]), b1 = __ldg(&bias[n_g + 1]);
            #pragma unroll
            for (int rr = 0; rr < 2; rr++) {
                const int row = bm + wm * 32 + mf * 16 + t4 + rr * 8;
                float2 v = make_float2(acc[mf][nf][rr * 2 + 0] + b0,
                                       acc[mf][nf][rr * 2 + 1] + b1);
                *(float2*)&out[(long)row * EMB + n_g] = v;
            }
        }
    }
}

// ---------------------------------------------------------------------------
// Elementwise f32 -> single fp16
// ---------------------------------------------------------------------------
__global__ __launch_bounds__(256) void k_cvt_h(const float4* __restrict__ src,
                                               uint2* __restrict__ dst, int n4)
{
    int i = blockIdx.x * 256 + threadIdx.x;
    if (i >= n4) return;
    float4 v = src[i];
    dst[i] = make_uint2(pack2h(v.x, v.y), pack2h(v.z, v.w));
}

// ---------------------------------------------------------------------------
// Transpose-convert: W [1024, ncols] f32 -> W^T single fp16 [ncols, 1024]
// ---------------------------------------------------------------------------
__global__ __launch_bounds__(256) void k_wT(const float* __restrict__ W, int ncols,
                                            ushortx* __restrict__ hT)
{
    __shared__ float t[32][33];
    const int tx = threadIdx.x, ty = threadIdx.y;
    const int n0 = blockIdx.x * 32, k0 = blockIdx.y * 32;
    #pragma unroll
    for (int i = 0; i < 4; i++)
        t[ty + i * 8][tx] = W[(k0 + ty + i * 8) * ncols + n0 + tx];
    __syncthreads();
    #pragma unroll
    for (int i = 0; i < 4; i++) {
        const int r = ty + i * 8;
        hT[(n0 + r) * 1024 + k0 + tx] = __half_as_ushort(__float2half_rn(t[tx][r]));
    }
}

// ---------------------------------------------------------------------------
// HMMA causal flash attention — single fp16, double-buffered K/V staging.
// Block: 128 q-rows x 1 head. 8 warps x 16 q-rows. 64-key tiles. 1-MMA passes.
// ---------------------------------------------------------------------------
#define AROW     144
#define KVARR    (64*AROW)      // 9216
#define KVSTAGE  (2*KVARR)      // 18432 (Kh | Vh)

__global__ __launch_bounds__(256, 1) void k_attn_mma()
{
    extern __shared__ char smb[];
    const uint32_t sb = smem_u32(smb);
    const int tid = threadIdx.x, lane = tid & 31, w = tid >> 5;
    const int t4 = lane >> 2, tm4 = lane & 3;
    const int bh = blockIdx.y;
    const int q0 = ((int)gridDim.x - 1 - (int)blockIdx.x) * 128;  // heavy blocks first

    const long headoff = (long)bh * SQ * HD;

    // ---- stage Q (single fp16) via cp.async: 128 rows x 128B
    {
        const char* q_g = (const char*)((const ushortx*)g_Qh4 + headoff + (long)q0 * HD);
        #pragma unroll
        for (int i = 0; i < 4; i++) {
            const int u = i * 256 + tid;        // 0..1023
            const int r = u >> 3, seg = u & 7;
            cpa16(sb + r * AROW + seg * 16, q_g + r * 128 + seg * 16);
        }
        CPA_COMMIT();
        CPA_WAIT(0);
        __syncthreads();
    }

    // ---- Q fragments (A, m16k16 x4 k-steps), kept in regs for whole kernel
    uint32_t qh[4][4];
    {
        const uint32_t rowq = w * 16 + (lane & 15);
        #pragma unroll
        for (int ks = 0; ks < 4; ks++) {
            const uint32_t col = ks * 32 + ((lane >> 4) << 4);
            ldm_x4(qh[ks], sb + rowq * AROW + col);
        }
    }
    __syncthreads();   // all warps done reading Q smem; buffers reusable

    float O[8][4];
    #pragma unroll
    for (int i = 0; i < 8; i++)
        #pragma unroll
        for (int j = 0; j < 4; j++) O[i][j] = 0.f;
    float m0 = -INFINITY, m1 = -INFINITY, lsum0 = 0.f, lsum1 = 0.f;
    const int qrow0 = q0 + w * 16 + t4;

    const char* kh_g = (const char*)((const ushortx*)g_Kh4 + headoff);
    const char* vh_g = (const char*)((const ushortx*)g_Vh4 + headoff);
    const int nkt = q0 / 64 + 2;

    // stage K/V tile kt into buffer base (each thread: 4 cp.async)
    auto stage_kv = [&](uint32_t base, int kt) {
        const long tb = (long)kt * 64 * HD * 2;
        #pragma unroll
        for (int i = 0; i < 2; i++) {
            const int u = i * 256 + tid;   // 0..511
            const int r = u >> 3, seg = u & 7;
            cpa16(base + r * AROW + seg * 16, kh_g + tb + r * 128 + seg * 16);
            cpa16(base + KVARR + r * AROW + seg * 16, vh_g + tb + r * 128 + seg * 16);
        }
    };

    stage_kv(sb, 0);
    CPA_COMMIT();

    for (int kt = 0; kt < nkt; kt++) {
        const int k0 = kt * 64;
        if (kt + 1 < nkt) {
            stage_kv(sb + ((kt + 1) & 1) * KVSTAGE, kt + 1);
            CPA_COMMIT();
            CPA_WAIT(1);
        } else {
            CPA_WAIT(0);
        }
        __syncthreads();

        const uint32_t Khi = sb + (kt & 1) * KVSTAGE;
        const uint32_t Vhi = Khi + KVARR;

        // ---- scores S = Q K^T: 1 pass x 8 indep accs per ks
        float sc[8][4];
        #pragma unroll
        for (int nf = 0; nf < 8; nf++)
            sc[nf][0] = sc[nf][1] = sc[nf][2] = sc[nf][3] = 0.f;
        {
            const uint32_t rowkb = (lane & 7);
            const uint32_t colp = ((lane >> 3) & 1) * 16;
            #pragma unroll
            for (int ks = 0; ks < 4; ks++) {
                uint32_t kbh[8][2];
                #pragma unroll
                for (int nf = 0; nf < 8; nf++)
                    ldm_x2(kbh[nf], Khi + (nf * 8 + rowkb) * AROW + ks * 32 + colp);
                #pragma unroll
                for (int nf = 0; nf < 8; nf++) mma16816(sc[nf], qh[ks], kbh[nf]);
            }
        }

        // ---- causal mask (only the last two tiles can clip)
        if (kt >= nkt - 2) {
            #pragma unroll
            for (int nf = 0; nf < 8; nf++) {
                const int col = k0 + nf * 8 + tm4 * 2;
                if (col     > qrow0)     sc[nf][0] = -1e30f;
                if (col + 1 > qrow0)     sc[nf][1] = -1e30f;
                if (col     > qrow0 + 8) sc[nf][2] = -1e30f;
                if (col + 1 > qrow0 + 8) sc[nf][3] = -1e30f;
            }
        }

        // ---- online softmax (rows t4 and t4+8 within warp)
        float mx0 = sc[0][0], mx1 = sc[0][2];
        #pragma unroll
        for (int nf = 0; nf < 8; nf++) {
            mx0 = fmaxf(mx0, fmaxf(sc[nf][0], sc[nf][1]));
            mx1 = fmaxf(mx1, fmaxf(sc[nf][2], sc[nf][3]));
        }
        mx0 = fmaxf(mx0, __shfl_xor_sync(0xFFFFFFFF, mx0, 1));
        mx0 = fmaxf(mx0, __shfl_xor_sync(0xFFFFFFFF, mx0, 2));
        mx1 = fmaxf(mx1, __shfl_xor_sync(0xFFFFFFFF, mx1, 1));
        mx1 = fmaxf(mx1, __shfl_xor_sync(0xFFFFFFFF, mx1, 2));
        const float mn0 = fmaxf(m0, mx0), mn1 = fmaxf(m1, mx1);
        const float c0 = __expf(m0 - mn0), c1 = __expf(m1 - mn1);
        m0 = mn0; m1 = mn1;
        float ps0 = 0.f, ps1 = 0.f;
        #pragma unroll
        for (int nf = 0; nf < 8; nf++) {
            sc[nf][0] = __expf(sc[nf][0] - mn0); ps0 += sc[nf][0];
            sc[nf][1] = __expf(sc[nf][1] - mn0); ps0 += sc[nf][1];
            sc[nf][2] = __expf(sc[nf][2] - mn1); ps1 += sc[nf][2];
            sc[nf][3] = __expf(sc[nf][3] - mn1); ps1 += sc[nf][3];
        }
        ps0 += __shfl_xor_sync(0xFFFFFFFF, ps0, 1);
        ps0 += __shfl_xor_sync(0xFFFFFFFF, ps0, 2);
        ps1 += __shfl_xor_sync(0xFFFFFFFF, ps1, 1);
        ps1 += __shfl_xor_sync(0xFFFFFFFF, ps1, 2);
        lsum0 = lsum0 * c0 + ps0;
        lsum1 = lsum1 * c1 + ps1;
        #pragma unroll
        for (int nf = 0; nf < 8; nf++) {
            O[nf][0] *= c0; O[nf][1] *= c0;
            O[nf][2] *= c1; O[nf][3] *= c1;
        }

        // ---- pack P as single-fp16 A-frags directly from score c-frags
        uint32_t ph[4][4];
        #pragma unroll
        for (int j = 0; j < 4; j++) {
            ph[j][0] = pack2h(sc[2*j    ][0], sc[2*j    ][1]);
            ph[j][1] = pack2h(sc[2*j    ][2], sc[2*j    ][3]);
            ph[j][2] = pack2h(sc[2*j + 1][0], sc[2*j + 1][1]);
            ph[j][3] = pack2h(sc[2*j + 1][2], sc[2*j + 1][3]);
        }

        // ---- O += P V: 1 pass x 8 indep accs per ks
        {
            const uint32_t rowvb = (lane & 15);
            #pragma unroll
            for (int ks = 0; ks < 4; ks++) {
                uint32_t vbh[8][2];
                #pragma unroll
                for (int nfd = 0; nfd < 8; nfd++)
                    ldm_x2t(vbh[nfd], Vhi + (ks * 16 + rowvb) * AROW + nfd * 16);
                #pragma unroll
                for (int nfd = 0; nfd < 8; nfd++) mma16816(O[nfd], ph[ks], vbh[nfd]);
            }
        }
        __syncthreads();   // all warps done with this buffer before restaging
    }

    // ---- finalize: O /= l, write single fp16 in [B,S,E] merged-head layout
    const float i0 = 1.f / lsum0, i1 = 1.f / lsum1;
    const int b = bh >> 4, h = bh & 15;
    uint32_t* Oh = (uint32_t*)g_Oh4;
    const long base0 = ((long)(b * SQ + qrow0)) * EMB + h * HD;
    const long base1 = base0 + 8L * EMB;
    #pragma unroll
    for (int nfd = 0; nfd < 8; nfd++) {
        const int col = nfd * 8 + tm4 * 2;
        Oh[(base0 + col) >> 1] = pack2h(O[nfd][0] * i0, O[nfd][1] * i0);
        Oh[(base1 + col) >> 1] = pack2h(O[nfd][2] * i1, O[nfd][3] * i1);
    }
}

// ---------------------------------------------------------------------------
extern "C" void kernel_launch(void* const* d_in, const int* in_sizes, int n_in,
                              void* d_out, int out_size)
{
    const float* x      = (const float*)d_in[0];
    const float* W_attn = (const float*)d_in[1];
    const float* b_attn = (const float*)d_in[2];
    const float* W_proj = (const float*)d_in[3];
    const float* b_proj = (const float*)d_in[4];
    float* out = (float*)d_out;

    const int DSM = 2 * STAGEB;          // 55296
    const int ASM_SZ = 2 * KVSTAGE;      // 36864
    cudaFuncSetAttribute(k_gemm_qkv,  cudaFuncAttributeMaxDynamicSharedMemorySize, DSM);
    cudaFuncSetAttribute(k_gemm_proj, cudaFuncAttributeMaxDynamicSharedMemorySize, DSM);
    cudaFuncSetAttribute(k_attn_mma,  cudaFuncAttributeMaxDynamicSharedMemorySize, ASM_SZ);

    uint4 *xh, *wah, *wph;
    cudaGetSymbolAddress((void**)&xh,  g_Xh4);
    cudaGetSymbolAddress((void**)&wah, g_WaTh4);
    cudaGetSymbolAddress((void**)&wph, g_WpTh4);

    k_cvt_h<<<4096, 256>>>((const float4*)x, (uint2*)xh, 4096 * 1024 / 4);
    k_wT<<<dim3(96, 32), dim3(32, 8)>>>(W_attn, 3072, (ushortx*)wah);
    k_wT<<<dim3(32, 32), dim3(32, 8)>>>(W_proj, 1024, (ushortx*)wph);
    k_gemm_qkv<<<dim3(24, 64), 128, DSM>>>(b_attn);
    k_attn_mma<<<dim3(8, 64), 256, ASM_SZ>>>();
    k_gemm_proj<<<dim3(8, 64), 128, DSM>>>(b_proj, out);
}

// round 17
// speedup vs baseline: 2.6536x; 1.0254x over previous
#include <cuda_runtime.h>
#include <cuda_fp16.h>
#include <math.h>
#include <cstdint>

#define BSZ 4
#define SQ  1024
#define EMB 1024
#define NH  16
#define HD  64

typedef unsigned long long u64;
typedef unsigned short ushortx;

// ---------------------------------------------------------------------------
// Scratch (__device__ globals; allocation-free) — ALL operands single fp16.
// ---------------------------------------------------------------------------
__device__ uint4 g_Xh4[4096*1024*2/16];
__device__ uint4 g_Qh4[BSZ*NH*SQ*HD*2/16];
__device__ uint4 g_Kh4[BSZ*NH*SQ*HD*2/16];
__device__ uint4 g_Vh4[BSZ*NH*SQ*HD*2/16];
__device__ uint4 g_Oh4[4096*1024*2/16];
__device__ uint4 g_WaTh4[3072*1024*2/16];   // W_attn^T [3072][1024]
__device__ uint4 g_WpTh4[1024*1024*2/16];   // W_proj^T [1024][1024]

// ---------------------------------------------------------------------------
// helpers
// ---------------------------------------------------------------------------
__device__ __forceinline__ uint32_t smem_u32(const void* p) {
    uint32_t a;
    asm("{ .reg .u64 t; cvta.to.shared.u64 t, %1; cvt.u32.u64 %0, t; }" : "=r"(a) : "l"(p));
    return a;
}
__device__ __forceinline__ void cpa16(uint32_t dst, const void* src) {
    asm volatile("cp.async.cg.shared.global [%0], [%1], 16;"
                 :: "r"(dst), "l"(__cvta_generic_to_global(src)) : "memory");
}
#define CPA_COMMIT() asm volatile("cp.async.commit_group;" ::: "memory")
#define CPA_WAIT(n)  asm volatile("cp.async.wait_group %0;" :: "n"(n) : "memory")

__device__ __forceinline__ uint32_t lds32(uint32_t addr) {
    uint32_t v; asm volatile("ld.shared.b32 %0,[%1];" : "=r"(v) : "r"(addr)); return v;
}
// m16n8k16 fp16 MMA, fp32 accumulate
__device__ __forceinline__ void mma16816(float* c, const uint32_t* a, const uint32_t* b) {
    asm volatile("mma.sync.aligned.m16n8k16.row.col.f32.f16.f16.f32 "
        "{%0,%1,%2,%3}, {%4,%5,%6,%7}, {%8,%9}, {%0,%1,%2,%3};"
        : "+f"(c[0]), "+f"(c[1]), "+f"(c[2]), "+f"(c[3])
        : "r"(a[0]), "r"(a[1]), "r"(a[2]), "r"(a[3]), "r"(b[0]), "r"(b[1]));
}
__device__ __forceinline__ void ldm_x4(uint32_t* r, uint32_t addr) {
    asm volatile("ldmatrix.sync.aligned.m8n8.x4.shared.b16 {%0,%1,%2,%3}, [%4];"
        : "=r"(r[0]), "=r"(r[1]), "=r"(r[2]), "=r"(r[3]) : "r"(addr));
}
__device__ __forceinline__ void ldm_x2(uint32_t* r, uint32_t addr) {
    asm volatile("ldmatrix.sync.aligned.m8n8.x2.shared.b16 {%0,%1}, [%2];"
        : "=r"(r[0]), "=r"(r[1]) : "r"(addr));
}
__device__ __forceinline__ void ldm_x2t(uint32_t* r, uint32_t addr) {
    asm volatile("ldmatrix.sync.aligned.m8n8.x2.trans.shared.b16 {%0,%1}, [%2];"
        : "=r"(r[0]), "=r"(r[1]) : "r"(addr));
}
// two f32 -> one packed f16x2
__device__ __forceinline__ uint32_t pack2h(float x, float y) {
    uint32_t r;
    asm("{ .reg .f16 a,b; cvt.rn.f16.f32 a,%1; cvt.rn.f16.f32 b,%2; mov.b32 %0,{a,b}; }"
        : "=r"(r) : "f"(x), "f"(y));
    return r;
}

// ---------------------------------------------------------------------------
// GEMM geometry: 128x128 block, BK=64, 4 warps (2m x 2n), warp tile 64x64.
// A single fp16 (128x144B), B single fp16 (128x144B). Per ks per warp:
// 32 lds32 + 32 MMA (ratio 1.0 vs prior 0.67); cp.async traffic -33%.
// wait(1)->sync->compute->sync, double buffer, 2 CTAs/SM of 128 threads.
// ---------------------------------------------------------------------------
#define ROWB   144
#define AARRB  (128*ROWB)              // 18432
#define BARRB  (128*ROWB)              // 18432
#define STAGEB (AARRB + BARRB)         // 36864
#define NCHUNK 16                      // 1024 / 64

__device__ __forceinline__ void load_chunk(
    uint32_t st, const ushortx* A0, const ushortx* B0, int k0, int tid)
{
    // A: 128 rows x 8 segs
    #pragma unroll
    for (int i = 0; i < 8; i++) {
        const int u = i * 128 + tid;      // 0..1023
        const int r = u >> 3, c16 = u & 7;
        cpa16(st + r * ROWB + c16 * 16,
              (const char*)(A0 + r * 1024 + k0) + c16 * 16);
    }
    // B: 128 rows x 8 segs
    #pragma unroll
    for (int i = 0; i < 8; i++) {
        const int u = i * 128 + tid;      // 0..1023
        const int r = u >> 3, c16 = u & 7;
        cpa16(st + AARRB + r * ROWB + c16 * 16,
              (const char*)(B0 + r * 1024 + k0) + c16 * 16);
    }
}

__device__ __forceinline__ void compute_chunk(
    uint32_t st, int wm, int wn, int t4, int tm4, float acc[4][8][4])
{
    #pragma unroll
    for (int ks = 0; ks < 4; ks++) {
        const int kb = ks * 32 + tm4 * 4;     // byte offset of this thread's k pair
        uint32_t Ah[4][4], Bh[8][2];
        #pragma unroll
        for (int mf = 0; mf < 4; mf++) {
            const uint32_t ra = st + (wm * 64 + mf * 16 + t4) * ROWB + kb;
            Ah[mf][0] = lds32(ra);
            Ah[mf][1] = lds32(ra + 8 * ROWB);
            Ah[mf][2] = lds32(ra + 16);
            Ah[mf][3] = lds32(ra + 8 * ROWB + 16);
        }
        #pragma unroll
        for (int nf = 0; nf < 8; nf++) {
            const uint32_t rb = st + AARRB + (wn * 64 + nf * 8 + t4) * ROWB + kb;
            Bh[nf][0] = lds32(rb);
            Bh[nf][1] = lds32(rb + 16);
        }
        #pragma unroll
        for (int mf = 0; mf < 4; mf++)
            #pragma unroll
            for (int nf = 0; nf < 8; nf++)
                mma16816(acc[mf][nf], Ah[mf], Bh[nf]);
    }
}

__device__ __forceinline__ void gemm_mainloop(
    uint32_t sm, const ushortx* A0, const ushortx* B0,
    int wm, int wn, int t4, int tm4, int tid, float acc[4][8][4])
{
    #pragma unroll
    for (int mf = 0; mf < 4; mf++)
        #pragma unroll
        for (int nf = 0; nf < 8; nf++)
            #pragma unroll
            for (int j = 0; j < 4; j++) acc[mf][nf][j] = 0.f;

    load_chunk(sm, A0, B0, 0, tid);
    CPA_COMMIT();
    for (int c = 0; c < NCHUNK; c++) {
        if (c + 1 < NCHUNK) {
            load_chunk(sm + ((c + 1) & 1) * STAGEB, A0, B0, (c + 1) * 64, tid);
            CPA_COMMIT();
            CPA_WAIT(1);
        } else {
            CPA_WAIT(0);
        }
        __syncthreads();
        compute_chunk(sm + (c & 1) * STAGEB, wm, wn, t4, tm4, acc);
        __syncthreads();
    }
}

// ---------------------------------------------------------------------------
// QKV GEMM: X @ W_attn + b_attn -> Q (x0.125) / K / V single fp16 [B,H,S,D]
// grid (24, 32): 128x128 tiles
// ---------------------------------------------------------------------------
__global__ __launch_bounds__(128, 2) void k_gemm_qkv(const float* __restrict__ bias)
{
    extern __shared__ __align__(16) char dsm[];
    const int tid = threadIdx.x, wid = tid >> 5, lane = tid & 31;
    const int t4 = lane >> 2, tm4 = lane & 3;
    const int wm = wid >> 1, wn = wid & 1;
    const int bn = blockIdx.x * 128, bm = blockIdx.y * 128;
    const uint32_t sm = smem_u32(dsm);

    float acc[4][8][4];
    gemm_mainloop(sm,
        (const ushortx*)g_Xh4 + (long)bm * 1024,
        (const ushortx*)g_WaTh4 + (long)bn * 1024,
        wm, wn, t4, tm4, tid, acc);

    const int which = bn >> 10;             // 0=Q 1=K 2=V
    uint32_t* dst = (which == 0) ? (uint32_t*)g_Qh4 : (which == 1) ? (uint32_t*)g_Kh4 : (uint32_t*)g_Vh4;
    const float scale = (which == 0) ? 0.125f : 1.f;

    #pragma unroll
    for (int mf = 0; mf < 4; mf++) {
        #pragma unroll
        for (int nf = 0; nf < 8; nf++) {
            const int n_g = bn + wn * 64 + nf * 8 + tm4 * 2;
            const int e = n_g & 1023, h = e >> 6, d = e & 63;
            const float b0 = __ldg(&bias[n_g]), b1 = __ldg(&bias[n_g + 1]);
            #pragma unroll
            for (int rr = 0; rr < 2; rr++) {
                const int row = bm + wm * 64 + mf * 16 + t4 + rr * 8;
                const int b = row >> 10, s = row & 1023;
                const long off = (((long)(b * NH + h) * SQ) + s) * HD + d;
                dst[off >> 1] = pack2h((acc[mf][nf][rr * 2 + 0] + b0) * scale,
                                       (acc[mf][nf][rr * 2 + 1] + b1) * scale);
            }
        }
    }
}

// ---------------------------------------------------------------------------
// Proj GEMM: O(fp16) @ W_proj + b_proj -> out.  grid (8, 32)
// ---------------------------------------------------------------------------
__global__ __launch_bounds__(128, 2) void k_gemm_proj(const float* __restrict__ bias,
                                                      float* __restrict__ out)
{
    extern __shared__ __align__(16) char dsm[];
    const int tid = threadIdx.x, wid = tid >> 5, lane = tid & 31;
    const int t4 = lane >> 2, tm4 = lane & 3;
    const int wm = wid >> 1, wn = wid & 1;
    const int bn = blockIdx.x * 128, bm = blockIdx.y * 128;
    const uint32_t sm = smem_u32(dsm);

    float acc[4][8][4];
    gemm_mainloop(sm,
        (const ushortx*)g_Oh4 + (long)bm * 1024,
        (const ushortx*)g_WpTh4 + (long)bn * 1024,
        wm, wn, t4, tm4, tid, acc);

    #pragma unroll
    for (int mf = 0; mf < 4; mf++) {
        #pragma unroll
        for (int nf = 0; nf < 8; nf++) {
            const int n_g = bn + wn * 64 + nf * 8 + tm4 * 2;
            const float b0 = __ldg(&bias[n_g]), b1 = __ldg(&bias[n_g + 1]);
            #pragma unroll
            for (int rr = 0; rr < 2; rr++) {
                const int row = bm + wm * 64 + mf * 16 + t4 + rr * 8;
                float2 v = make_float2(acc[mf][nf][rr * 2 + 0] + b0,
                                       acc[mf][nf][rr * 2 + 1] + b1);
                *(float2*)&out[(long)row * EMB + n_g] = v;
            }
        }
    }
}

// ---------------------------------------------------------------------------
// Elementwise f32 -> single fp16
// ---------------------------------------------------------------------------
__global__ __launch_bounds__(256) void k_cvt_h(const float4* __restrict__ src,
                                               uint2* __restrict__ dst, int n4)
{
    int i = blockIdx.x * 256 + threadIdx.x;
    if (i >= n4) return;
    float4 v = src[i];
    dst[i] = make_uint2(pack2h(v.x, v.y), pack2h(v.z, v.w));
}

// ---------------------------------------------------------------------------
// Transpose-convert: W [1024, ncols] f32 -> W^T single fp16 [ncols, 1024]
// ---------------------------------------------------------------------------
__global__ __launch_bounds__(256) void k_wT(const float* __restrict__ W, int ncols,
                                            ushortx* __restrict__ hT)
{
    __shared__ float t[32][33];
    const int tx = threadIdx.x, ty = threadIdx.y;
    const int n0 = blockIdx.x * 32, k0 = blockIdx.y * 32;
    #pragma unroll
    for (int i = 0; i < 4; i++)
        t[ty + i * 8][tx] = W[(k0 + ty + i * 8) * ncols + n0 + tx];
    __syncthreads();
    #pragma unroll
    for (int i = 0; i < 4; i++) {
        const int r = ty + i * 8;
        hT[(n0 + r) * 1024 + k0 + tx] = __half_as_ushort(__float2half_rn(t[tx][r]));
    }
}

// ---------------------------------------------------------------------------
// HMMA causal flash attention — single fp16, double-buffered K/V staging.
// (unchanged from R16 pass)
// ---------------------------------------------------------------------------
#define AROW     144
#define KVARR    (64*AROW)      // 9216
#define KVSTAGE  (2*KVARR)      // 18432 (Kh | Vh)

__global__ __launch_bounds__(256, 1) void k_attn_mma()
{
    extern __shared__ char smb[];
    const uint32_t sb = smem_u32(smb);
    const int tid = threadIdx.x, lane = tid & 31, w = tid >> 5;
    const int t4 = lane >> 2, tm4 = lane & 3;
    const int bh = blockIdx.y;
    const int q0 = ((int)gridDim.x - 1 - (int)blockIdx.x) * 128;  // heavy blocks first

    const long headoff = (long)bh * SQ * HD;

    // ---- stage Q (single fp16) via cp.async: 128 rows x 128B
    {
        const char* q_g = (const char*)((const ushortx*)g_Qh4 + headoff + (long)q0 * HD);
        #pragma unroll
        for (int i = 0; i < 4; i++) {
            const int u = i * 256 + tid;        // 0..1023
            const int r = u >> 3, seg = u & 7;
            cpa16(sb + r * AROW + seg * 16, q_g + r * 128 + seg * 16);
        }
        CPA_COMMIT();
        CPA_WAIT(0);
        __syncthreads();
    }

    // ---- Q fragments (A, m16k16 x4 k-steps), kept in regs for whole kernel
    uint32_t qh[4][4];
    {
        const uint32_t rowq = w * 16 + (lane & 15);
        #pragma unroll
        for (int ks = 0; ks < 4; ks++) {
            const uint32_t col = ks * 32 + ((lane >> 4) << 4);
            ldm_x4(qh[ks], sb + rowq * AROW + col);
        }
    }
    __syncthreads();   // all warps done reading Q smem; buffers reusable

    float O[8][4];
    #pragma unroll
    for (int i = 0; i < 8; i++)
        #pragma unroll
        for (int j = 0; j < 4; j++) O[i][j] = 0.f;
    float m0 = -INFINITY, m1 = -INFINITY, lsum0 = 0.f, lsum1 = 0.f;
    const int qrow0 = q0 + w * 16 + t4;

    const char* kh_g = (const char*)((const ushortx*)g_Kh4 + headoff);
    const char* vh_g = (const char*)((const ushortx*)g_Vh4 + headoff);
    const int nkt = q0 / 64 + 2;

    // stage K/V tile kt into buffer base (each thread: 4 cp.async)
    auto stage_kv = [&](uint32_t base, int kt) {
        const long tb = (long)kt * 64 * HD * 2;
        #pragma unroll
        for (int i = 0; i < 2; i++) {
            const int u = i * 256 + tid;   // 0..511
            const int r = u >> 3, seg = u & 7;
            cpa16(base + r * AROW + seg * 16, kh_g + tb + r * 128 + seg * 16);
            cpa16(base + KVARR + r * AROW + seg * 16, vh_g + tb + r * 128 + seg * 16);
        }
    };

    stage_kv(sb, 0);
    CPA_COMMIT();

    for (int kt = 0; kt < nkt; kt++) {
        const int k0 = kt * 64;
        if (kt + 1 < nkt) {
            stage_kv(sb + ((kt + 1) & 1) * KVSTAGE, kt + 1);
            CPA_COMMIT();
            CPA_WAIT(1);
        } else {
            CPA_WAIT(0);
        }
        __syncthreads();

        const uint32_t Khi = sb + (kt & 1) * KVSTAGE;
        const uint32_t Vhi = Khi + KVARR;

        // ---- scores S = Q K^T: 1 pass x 8 indep accs per ks
        float sc[8][4];
        #pragma unroll
        for (int nf = 0; nf < 8; nf++)
            sc[nf][0] = sc[nf][1] = sc[nf][2] = sc[nf][3] = 0.f;
        {
            const uint32_t rowkb = (lane & 7);
            const uint32_t colp = ((lane >> 3) & 1) * 16;
            #pragma unroll
            for (int ks = 0; ks < 4; ks++) {
                uint32_t kbh[8][2];
                #pragma unroll
                for (int nf = 0; nf < 8; nf++)
                    ldm_x2(kbh[nf], Khi + (nf * 8 + rowkb) * AROW + ks * 32 + colp);
                #pragma unroll
                for (int nf = 0; nf < 8; nf++) mma16816(sc[nf], qh[ks], kbh[nf]);
            }
        }

        // ---- causal mask (only the last two tiles can clip)
        if (kt >= nkt - 2) {
            #pragma unroll
            for (int nf = 0; nf < 8; nf++) {
                const int col = k0 + nf * 8 + tm4 * 2;
                if (col     > qrow0)     sc[nf][0] = -1e30f;
                if (col + 1 > qrow0)     sc[nf][1] = -1e30f;
                if (col     > qrow0 + 8) sc[nf][2] = -1e30f;
                if (col + 1 > qrow0 + 8) sc[nf][3] = -1e30f;
            }
        }

        // ---- online softmax (rows t4 and t4+8 within warp)
        float mx0 = sc[0][0], mx1 = sc[0][2];
        #pragma unroll
        for (int nf = 0; nf < 8; nf++) {
            mx0 = fmaxf(mx0, fmaxf(sc[nf][0], sc[nf][1]));
            mx1 = fmaxf(mx1, fmaxf(sc[nf][2], sc[nf][3]));
        }
        mx0 = fmaxf(mx0, __shfl_xor_sync(0xFFFFFFFF, mx0, 1));
        mx0 = fmaxf(mx0, __shfl_xor_sync(0xFFFFFFFF, mx0, 2));
        mx1 = fmaxf(mx1, __shfl_xor_sync(0xFFFFFFFF, mx1, 1));
        mx1 = fmaxf(mx1, __shfl_xor_sync(0xFFFFFFFF, mx1, 2));
        const float mn0 = fmaxf(m0, mx0), mn1 = fmaxf(m1, mx1);
        const float c0 = __expf(m0 - mn0), c1 = __expf(m1 - mn1);
        m0 = mn0; m1 = mn1;
        float ps0 = 0.f, ps1 = 0.f;
        #pragma unroll
        for (int nf = 0; nf < 8; nf++) {
            sc[nf][0] = __expf(sc[nf][0] - mn0); ps0 += sc[nf][0];
            sc[nf][1] = __expf(sc[nf][1] - mn0); ps0 += sc[nf][1];
            sc[nf][2] = __expf(sc[nf][2] - mn1); ps1 += sc[nf][2];
            sc[nf][3] = __expf(sc[nf][3] - mn1); ps1 += sc[nf][3];
        }
        ps0 += __shfl_xor_sync(0xFFFFFFFF, ps0, 1);
        ps0 += __shfl_xor_sync(0xFFFFFFFF, ps0, 2);
        ps1 += __shfl_xor_sync(0xFFFFFFFF, ps1, 1);
        ps1 += __shfl_xor_sync(0xFFFFFFFF, ps1, 2);
        lsum0 = lsum0 * c0 + ps0;
        lsum1 = lsum1 * c1 + ps1;
        #pragma unroll
        for (int nf = 0; nf < 8; nf++) {
            O[nf][0] *= c0; O[nf][1] *= c0;
            O[nf][2] *= c1; O[nf][3] *= c1;
        }

        // ---- pack P as single-fp16 A-frags directly from score c-frags
        uint32_t ph[4][4];
        #pragma unroll
        for (int j = 0; j < 4; j++) {
            ph[j][0] = pack2h(sc[2*j    ][0], sc[2*j    ][1]);
            ph[j][1] = pack2h(sc[2*j    ][2], sc[2*j    ][3]);
            ph[j][2] = pack2h(sc[2*j + 1][0], sc[2*j + 1][1]);
            ph[j][3] = pack2h(sc[2*j + 1][2], sc[2*j + 1][3]);
        }

        // ---- O += P V: 1 pass x 8 indep accs per ks
        {
            const uint32_t rowvb = (lane & 15);
            #pragma unroll
            for (int ks = 0; ks < 4; ks++) {
                uint32_t vbh[8][2];
                #pragma unroll
                for (int nfd = 0; nfd < 8; nfd++)
                    ldm_x2t(vbh[nfd], Vhi + (ks * 16 + rowvb) * AROW + nfd * 16);
                #pragma unroll
                for (int nfd = 0; nfd < 8; nfd++) mma16816(O[nfd], ph[ks], vbh[nfd]);
            }
        }
        __syncthreads();   // all warps done with this buffer before restaging
    }

    // ---- finalize: O /= l, write single fp16 in [B,S,E] merged-head layout
    const float i0 = 1.f / lsum0, i1 = 1.f / lsum1;
    const int b = bh >> 4, h = bh & 15;
    uint32_t* Oh = (uint32_t*)g_Oh4;
    const long base0 = ((long)(b * SQ + qrow0)) * EMB + h * HD;
    const long base1 = base0 + 8L * EMB;
    #pragma unroll
    for (int nfd = 0; nfd < 8; nfd++) {
        const int col = nfd * 8 + tm4 * 2;
        Oh[(base0 + col) >> 1] = pack2h(O[nfd][0] * i0, O[nfd][1] * i0);
        Oh[(base1 + col) >> 1] = pack2h(O[nfd][2] * i1, O[nfd][3] * i1);
    }
}

// ---------------------------------------------------------------------------
extern "C" void kernel_launch(void* const* d_in, const int* in_sizes, int n_in,
                              void* d_out, int out_size)
{
    const float* x      = (const float*)d_in[0];
    const float* W_attn = (const float*)d_in[1];
    const float* b_attn = (const float*)d_in[2];
    const float* W_proj = (const float*)d_in[3];
    const float* b_proj = (const float*)d_in[4];
    float* out = (float*)d_out;

    const int DSM = 2 * STAGEB;          // 73728
    const int ASM_SZ = 2 * KVSTAGE;      // 36864
    cudaFuncSetAttribute(k_gemm_qkv,  cudaFuncAttributeMaxDynamicSharedMemorySize, DSM);
    cudaFuncSetAttribute(k_gemm_proj, cudaFuncAttributeMaxDynamicSharedMemorySize, DSM);
    cudaFuncSetAttribute(k_attn_mma,  cudaFuncAttributeMaxDynamicSharedMemorySize, ASM_SZ);

    uint4 *xh, *wah, *wph;
    cudaGetSymbolAddress((void**)&xh,  g_Xh4);
    cudaGetSymbolAddress((void**)&wah, g_WaTh4);
    cudaGetSymbolAddress((void**)&wph, g_WpTh4);

    k_cvt_h<<<4096, 256>>>((const float4*)x, (uint2*)xh, 4096 * 1024 / 4);
    k_wT<<<dim3(96, 32), dim3(32, 8)>>>(W_attn, 3072, (ushortx*)wah);
    k_wT<<<dim3(32, 32), dim3(32, 8)>>>(W_proj, 1024, (ushortx*)wph);
    k_gemm_qkv<<<dim3(24, 32), 128, DSM>>>(b_attn);
    k_attn_mma<<<dim3(8, 64), 256, ASM_SZ>>>();
    k_gemm_proj<<<dim3(8, 32), 128, DSM>>>(b_proj, out);
}